// round 1
// baseline (speedup 1.0000x reference)
#include <cuda_runtime.h>
#include <math.h>

namespace {

constexpr int C = 256, H = 4, HD = 64, L = 6, FC = 1024, OUT = 192;
constexpr int B = 8, T = 1024, BT = B * T, NREL = 9;

// ---------------- scratch (__device__ globals: allocation-free) ----------------
__device__ float g_x[BT * C];
__device__ float g_q[BT * C];
__device__ float g_k[BT * C];
__device__ float g_v[BT * C];
__device__ float g_attn[BT * C];
__device__ float g_tmp[BT * C];
__device__ float g_ffn[BT * FC];
__device__ float g_probs[(size_t)B * H * T * T];   // scores -> probs in place
__device__ float g_qrel[BT * H * NREL];

// ---------------- block reductions (blockDim.x == 256) ----------------
__device__ __forceinline__ float warpReduceSum(float v) {
#pragma unroll
    for (int o = 16; o; o >>= 1) v += __shfl_xor_sync(0xffffffffu, v, o);
    return v;
}
__device__ __forceinline__ float warpReduceMax(float v) {
#pragma unroll
    for (int o = 16; o; o >>= 1) v = fmaxf(v, __shfl_xor_sync(0xffffffffu, v, o));
    return v;
}
__device__ __forceinline__ float blockReduceSum256(float v) {
    __shared__ float s[8];
    int lane = threadIdx.x & 31, w = threadIdx.x >> 5;
    v = warpReduceSum(v);
    if (lane == 0) s[w] = v;
    __syncthreads();
    float tot = 0.f;
#pragma unroll
    for (int i = 0; i < 8; i++) tot += s[i];
    __syncthreads();
    return tot;
}
__device__ __forceinline__ float blockReduceMax256(float v) {
    __shared__ float s[8];
    int lane = threadIdx.x & 31, w = threadIdx.x >> 5;
    v = warpReduceMax(v);
    if (lane == 0) s[w] = v;
    __syncthreads();
    float tot = -1e30f;
#pragma unroll
    for (int i = 0; i < 8; i++) tot = fmaxf(tot, s[i]);
    __syncthreads();
    return tot;
}

// ---------------- embedding ----------------
__global__ void embed_kernel(const float* __restrict__ emb, const int* __restrict__ tokens,
                             float* __restrict__ x) {
    int bt = blockIdx.x;
    int c = threadIdx.x;
    x[(size_t)bt * C + c] = emb[(size_t)tokens[bt] * C + c] * 16.0f;  // sqrt(256)
}

// ---------------- generic GEMM: Y = act((X[M,K]@W[K,N] + bias)*alpha) ----------------
// 64x64 tile, BK=16, 256 threads, 4x4 per thread.
__global__ void gemm_bias_kernel(const float* __restrict__ X, const float* __restrict__ W,
                                 const float* __restrict__ bias, float* __restrict__ Y,
                                 int M, int N, int K, float alpha, int relu) {
    __shared__ float As[16][68];
    __shared__ float Bs[16][68];
    int tid = threadIdx.x;
    int tx = tid & 15, ty = tid >> 4;
    int m0 = blockIdx.y * 64, n0 = blockIdx.x * 64;
    int a_m = tid >> 2, a_k = (tid & 3) * 4;
    int b_k = tid >> 4, b_n = (tid & 15) * 4;
    float acc[4][4] = {};
    for (int k0 = 0; k0 < K; k0 += 16) {
        float4 av = *(const float4*)(X + (size_t)(m0 + a_m) * K + k0 + a_k);
        As[a_k + 0][a_m] = av.x;
        As[a_k + 1][a_m] = av.y;
        As[a_k + 2][a_m] = av.z;
        As[a_k + 3][a_m] = av.w;
        *(float4*)(&Bs[b_k][b_n]) = *(const float4*)(W + (size_t)(k0 + b_k) * N + n0 + b_n);
        __syncthreads();
#pragma unroll
        for (int kk = 0; kk < 16; kk++) {
            float4 a4 = *(const float4*)(&As[kk][ty * 4]);
            float4 b4 = *(const float4*)(&Bs[kk][tx * 4]);
            float ar[4] = {a4.x, a4.y, a4.z, a4.w};
            float br[4] = {b4.x, b4.y, b4.z, b4.w};
#pragma unroll
            for (int i = 0; i < 4; i++)
#pragma unroll
                for (int j = 0; j < 4; j++) acc[i][j] = fmaf(ar[i], br[j], acc[i][j]);
        }
        __syncthreads();
    }
#pragma unroll
    for (int i = 0; i < 4; i++) {
        int row = m0 + ty * 4 + i;
#pragma unroll
        for (int j = 0; j < 4; j++) {
            int col = n0 + tx * 4 + j;
            float v = (acc[i][j] + bias[col]) * alpha;
            if (relu) v = fmaxf(v, 0.0f);
            Y[(size_t)row * N + col] = v;
        }
    }
}

// ---------------- qrel[bt,h,j] = q_row(bt,h) . rel_k[j]  (q already scaled) ----------------
__global__ void qrel_kernel(const float* __restrict__ q, const float* __restrict__ relk) {
    int w = blockIdx.x * 8 + (threadIdx.x >> 5);  // exact: BT*H*NREL warps
    int lane = threadIdx.x & 31;
    int j = w % NREL;
    int bh = w / NREL;
    int h = bh % H;
    int bt = bh / H;
    const float* qp = q + (size_t)bt * C + h * HD;
    const float* rp = relk + j * HD;
    float s = qp[lane] * rp[lane] + qp[lane + 32] * rp[lane + 32];
#pragma unroll
    for (int o = 16; o; o >>= 1) s += __shfl_xor_sync(0xffffffffu, s, o);
    if (lane == 0) g_qrel[w] = s;
}

// ---------------- S[bh,q,k] = q.k + band bias ----------------
__global__ void scores_kernel(const float* __restrict__ q, const float* __restrict__ k) {
    __shared__ float Qs[16][68];
    __shared__ float Ks[16][68];
    int tid = threadIdx.x;
    int tx = tid & 15, ty = tid >> 4;
    int q0 = blockIdx.y * 64, k0 = blockIdx.x * 64;
    int bh = blockIdx.z;
    int b = bh >> 2, h = bh & 3;
    int r = tid >> 2, dq = (tid & 3) * 4;
    const float* qbase = q + (size_t)(b * T + q0 + r) * C + h * HD + dq;
    const float* kbase = k + (size_t)(b * T + k0 + r) * C + h * HD + dq;
    float acc[4][4] = {};
    for (int d0 = 0; d0 < HD; d0 += 16) {
        float4 qv = *(const float4*)(qbase + d0);
        Qs[dq + 0][r] = qv.x;
        Qs[dq + 1][r] = qv.y;
        Qs[dq + 2][r] = qv.z;
        Qs[dq + 3][r] = qv.w;
        float4 kv = *(const float4*)(kbase + d0);
        Ks[dq + 0][r] = kv.x;
        Ks[dq + 1][r] = kv.y;
        Ks[dq + 2][r] = kv.z;
        Ks[dq + 3][r] = kv.w;
        __syncthreads();
#pragma unroll
        for (int kk = 0; kk < 16; kk++) {
            float4 a4 = *(const float4*)(&Qs[kk][ty * 4]);
            float4 b4 = *(const float4*)(&Ks[kk][tx * 4]);
            float ar[4] = {a4.x, a4.y, a4.z, a4.w};
            float br[4] = {b4.x, b4.y, b4.z, b4.w};
#pragma unroll
            for (int i = 0; i < 4; i++)
#pragma unroll
                for (int j = 0; j < 4; j++) acc[i][j] = fmaf(ar[i], br[j], acc[i][j]);
        }
        __syncthreads();
    }
    float* S = g_probs + (size_t)bh * T * T;
#pragma unroll
    for (int i = 0; i < 4; i++) {
        int qg = q0 + ty * 4 + i;
#pragma unroll
        for (int j = 0; j < 4; j++) {
            int kg = k0 + tx * 4 + j;
            float s = acc[i][j];
            int d = kg - qg;
            if (d >= -4 && d <= 4)
                s += g_qrel[((size_t)(b * T + qg) * H + h) * NREL + (d + 4)];
            S[(size_t)qg * T + kg] = s;
        }
    }
}

// ---------------- softmax over k with length mask; masked q rows -> 0 ----------------
__global__ void softmax_kernel(const int* __restrict__ lens) {
    int row = blockIdx.x;         // bh*T + q
    int qpos = row & (T - 1);
    int bh = row >> 10;
    int b = bh >> 2;
    int len = lens[b];
    float* p = g_probs + (size_t)row * T;
    int tid = threadIdx.x;
    if (qpos >= len) {
        *(float4*)(p + tid * 4) = make_float4(0.f, 0.f, 0.f, 0.f);
        return;
    }
    float mx = -1e30f;
    for (int kk = tid; kk < len; kk += 256) mx = fmaxf(mx, p[kk]);
    mx = blockReduceMax256(mx);
    float sum = 0.f;
    for (int kk = tid; kk < len; kk += 256) sum += __expf(p[kk] - mx);
    sum = blockReduceSum256(sum);
    float inv = 1.0f / sum;
    for (int kk = tid; kk < T; kk += 256) p[kk] = (kk < len) ? __expf(p[kk] - mx) * inv : 0.f;
}

// ---------------- O = P@V + rel_v band ----------------
__global__ void pv_relv_kernel(const float* __restrict__ v, const float* __restrict__ relv,
                               float* __restrict__ o) {
    __shared__ float Ps[16][68];
    __shared__ float Vs[16][68];
    __shared__ float rvs[NREL * HD];
    int tid = threadIdx.x;
    int tx = tid & 15, ty = tid >> 4;
    int q0 = blockIdx.x * 64;
    int bh = blockIdx.y;
    int b = bh >> 2, h = bh & 3;
    for (int i = tid; i < NREL * HD; i += 256) rvs[i] = relv[i];
    const float* P = g_probs + (size_t)bh * T * T;
    int a_m = tid >> 2, a_k = (tid & 3) * 4;
    int b_k = tid >> 4, b_n = (tid & 15) * 4;
    float acc[4][4] = {};
    for (int k0 = 0; k0 < T; k0 += 16) {
        float4 pv4 = *(const float4*)(P + (size_t)(q0 + a_m) * T + k0 + a_k);
        Ps[a_k + 0][a_m] = pv4.x;
        Ps[a_k + 1][a_m] = pv4.y;
        Ps[a_k + 2][a_m] = pv4.z;
        Ps[a_k + 3][a_m] = pv4.w;
        *(float4*)(&Vs[b_k][b_n]) =
            *(const float4*)(v + (size_t)(b * T + k0 + b_k) * C + h * HD + b_n);
        __syncthreads();
#pragma unroll
        for (int kk = 0; kk < 16; kk++) {
            float4 a4 = *(const float4*)(&Ps[kk][ty * 4]);
            float4 b4 = *(const float4*)(&Vs[kk][tx * 4]);
            float ar[4] = {a4.x, a4.y, a4.z, a4.w};
            float br[4] = {b4.x, b4.y, b4.z, b4.w};
#pragma unroll
            for (int i = 0; i < 4; i++)
#pragma unroll
                for (int j = 0; j < 4; j++) acc[i][j] = fmaf(ar[i], br[j], acc[i][j]);
        }
        __syncthreads();
    }
    // relative-value band: o[q] += sum_{|d|<=4} p[q, q+d] * rel_v[d+4]
#pragma unroll
    for (int i = 0; i < 4; i++) {
        int qg = q0 + ty * 4 + i;
#pragma unroll
        for (int dlt = -4; dlt <= 4; dlt++) {
            int kidx = qg + dlt;
            if (kidx < 0 || kidx >= T) continue;
            float pval = P[(size_t)qg * T + kidx];
#pragma unroll
            for (int j = 0; j < 4; j++)
                acc[i][j] = fmaf(pval, rvs[(dlt + 4) * HD + tx * 4 + j], acc[i][j]);
        }
    }
#pragma unroll
    for (int i = 0; i < 4; i++) {
        int qg = q0 + ty * 4 + i;
#pragma unroll
        for (int j = 0; j < 4; j++)
            o[(size_t)(b * T + qg) * C + h * HD + tx * 4 + j] = acc[i][j];
    }
}

// ---------------- x = LN(x + r)*g + b  [optionally * mask] ----------------
__global__ void ln_res_kernel(float* __restrict__ x, const float* __restrict__ r,
                              const float* __restrict__ gg, const float* __restrict__ beta,
                              const int* __restrict__ lens, int apply_mask) {
    int row = blockIdx.x;
    int c = threadIdx.x;
    size_t idx = (size_t)row * C + c;
    float val = x[idx] + r[idx];
    float mean = blockReduceSum256(val) * (1.0f / C);
    float d = val - mean;
    float var = blockReduceSum256(d * d) * (1.0f / C);
    float y = d * rsqrtf(var + 1e-5f) * gg[c] + beta[c];
    if (apply_mask) {
        int b = row >> 10, t = row & (T - 1);
        if (t >= lens[b]) y = 0.0f;
    }
    x[idx] = y;
}

// ---------------- x (B,T,C) -> out (B,C,T) ----------------
__global__ void transpose_kernel(const float* __restrict__ x, float* __restrict__ out) {
    __shared__ float tile[32][33];
    int b = blockIdx.z;
    int t0 = blockIdx.x * 32, c0 = blockIdx.y * 32;
    int tx = threadIdx.x, ty = threadIdx.y;
#pragma unroll
    for (int i = 0; i < 32; i += 8)
        tile[ty + i][tx] = x[(size_t)(b * T + t0 + ty + i) * C + c0 + tx];
    __syncthreads();
#pragma unroll
    for (int i = 0; i < 32; i += 8)
        out[(size_t)(b * C + c0 + ty + i) * T + t0 + tx] = tile[tx][ty + i];
}

// ---------------- stats: (proj_w @ x^T + b) * mask -> split m / logs ----------------
__global__ void stats_kernel(const float* __restrict__ x, const float* __restrict__ pw,
                             const float* __restrict__ pb, const int* __restrict__ lens,
                             float* __restrict__ out_m, float* __restrict__ out_logs) {
    __shared__ float As[16][68];
    __shared__ float Bs[16][68];
    int tid = threadIdx.x;
    int tx = tid & 15, ty = tid >> 4;
    int m0 = blockIdx.y * 64, n0 = blockIdx.x * 64;
    int r = tid >> 2, kq = (tid & 3) * 4;
    float acc[4][4] = {};
    for (int k0 = 0; k0 < C; k0 += 16) {
        float4 av = *(const float4*)(x + (size_t)(m0 + r) * C + k0 + kq);
        As[kq + 0][r] = av.x;
        As[kq + 1][r] = av.y;
        As[kq + 2][r] = av.z;
        As[kq + 3][r] = av.w;
        float4 bv = *(const float4*)(pw + (size_t)(n0 + r) * C + k0 + kq);
        Bs[kq + 0][r] = bv.x;
        Bs[kq + 1][r] = bv.y;
        Bs[kq + 2][r] = bv.z;
        Bs[kq + 3][r] = bv.w;
        __syncthreads();
#pragma unroll
        for (int kk = 0; kk < 16; kk++) {
            float4 a4 = *(const float4*)(&As[kk][ty * 4]);
            float4 b4 = *(const float4*)(&Bs[kk][tx * 4]);
            float ar[4] = {a4.x, a4.y, a4.z, a4.w};
            float br[4] = {b4.x, b4.y, b4.z, b4.w};
#pragma unroll
            for (int i = 0; i < 4; i++)
#pragma unroll
                for (int j = 0; j < 4; j++) acc[i][j] = fmaf(ar[i], br[j], acc[i][j]);
        }
        __syncthreads();
    }
#pragma unroll
    for (int i = 0; i < 4; i++) {
        int row = m0 + ty * 4 + i;
        int b = row >> 10, t = row & (T - 1);
        float mk = (t < lens[b]) ? 1.0f : 0.0f;
#pragma unroll
        for (int j = 0; j < 4; j++) {
            int oc = n0 + tx * 4 + j;
            float vv = (acc[i][j] + pb[oc]) * mk;
            if (oc < OUT)
                out_m[((size_t)b * OUT + oc) * T + t] = vv;
            else
                out_logs[((size_t)b * OUT + (oc - OUT)) * T + t] = vv;
        }
    }
}

__global__ void mask_out_kernel(const int* __restrict__ lens, float* __restrict__ out_mask) {
    int b = blockIdx.x;
    int len = lens[b];
    for (int t = threadIdx.x; t < T; t += blockDim.x)
        out_mask[(size_t)b * T + t] = (t < len) ? 1.0f : 0.0f;
}

}  // namespace

extern "C" void kernel_launch(void* const* d_in, const int* in_sizes, int n_in,
                              void* d_out, int out_size) {
    (void)in_sizes; (void)n_in; (void)out_size;
    const float* emb   = (const float*)d_in[0];
    const float* Wq    = (const float*)d_in[1];
    const float* Wk    = (const float*)d_in[2];
    const float* Wv    = (const float*)d_in[3];
    const float* Wo    = (const float*)d_in[4];
    const float* bq    = (const float*)d_in[5];
    const float* bk    = (const float*)d_in[6];
    const float* bv    = (const float*)d_in[7];
    const float* bo    = (const float*)d_in[8];
    const float* rel_k = (const float*)d_in[9];
    const float* rel_v = (const float*)d_in[10];
    const float* ln1_g = (const float*)d_in[11];
    const float* ln1_b = (const float*)d_in[12];
    const float* ln2_g = (const float*)d_in[13];
    const float* ln2_b = (const float*)d_in[14];
    const float* fw1   = (const float*)d_in[15];
    const float* fb1   = (const float*)d_in[16];
    const float* fw2   = (const float*)d_in[17];
    const float* fb2   = (const float*)d_in[18];
    const float* pw    = (const float*)d_in[19];
    const float* pb    = (const float*)d_in[20];
    const int*   toks  = (const int*)d_in[21];
    const int*   lens  = (const int*)d_in[22];

    float *px, *pq, *pk, *pvb, *pattn, *ptmp, *pffn;
    cudaGetSymbolAddress((void**)&px,    g_x);
    cudaGetSymbolAddress((void**)&pq,    g_q);
    cudaGetSymbolAddress((void**)&pk,    g_k);
    cudaGetSymbolAddress((void**)&pvb,   g_v);
    cudaGetSymbolAddress((void**)&pattn, g_attn);
    cudaGetSymbolAddress((void**)&ptmp,  g_tmp);
    cudaGetSymbolAddress((void**)&pffn,  g_ffn);

    float* out      = (float*)d_out;
    float* out_x    = out;                                  // (B,C,T)
    float* out_m    = out + (size_t)B * C * T;              // (B,OUT,T)
    float* out_logs = out_m + (size_t)B * OUT * T;          // (B,OUT,T)
    float* out_mask = out_logs + (size_t)B * OUT * T;       // (B,1,T)

    embed_kernel<<<BT, C>>>(emb, toks, px);

    dim3 gC(C / 64, BT / 64);     // 4 x 128
    dim3 gFC(FC / 64, BT / 64);   // 16 x 128

    for (int l = 0; l < L; l++) {
        const float* wq = Wq + (size_t)l * C * C;
        const float* wk = Wk + (size_t)l * C * C;
        const float* wv = Wv + (size_t)l * C * C;
        const float* wo = Wo + (size_t)l * C * C;

        gemm_bias_kernel<<<gC, 256>>>(px, wq, bq + (size_t)l * C, pq, BT, C, C, 0.125f, 0);
        gemm_bias_kernel<<<gC, 256>>>(px, wk, bk + (size_t)l * C, pk, BT, C, C, 1.0f, 0);
        gemm_bias_kernel<<<gC, 256>>>(px, wv, bv + (size_t)l * C, pvb, BT, C, C, 1.0f, 0);

        qrel_kernel<<<BT * H * NREL / 8, 256>>>(pq, rel_k + (size_t)l * NREL * HD);
        scores_kernel<<<dim3(T / 64, T / 64, B * H), 256>>>(pq, pk);
        softmax_kernel<<<B * H * T, 256>>>(lens);
        pv_relv_kernel<<<dim3(T / 64, B * H), 256>>>(pvb, rel_v + (size_t)l * NREL * HD, pattn);

        gemm_bias_kernel<<<gC, 256>>>(pattn, wo, bo + (size_t)l * C, ptmp, BT, C, C, 1.0f, 0);
        ln_res_kernel<<<BT, C>>>(px, ptmp, ln1_g + (size_t)l * C, ln1_b + (size_t)l * C, lens, 0);

        gemm_bias_kernel<<<gFC, 256>>>(px, fw1 + (size_t)l * C * FC, fb1 + (size_t)l * FC,
                                       pffn, BT, FC, C, 1.0f, 1);
        gemm_bias_kernel<<<gC, 256>>>(pffn, fw2 + (size_t)l * FC * C, fb2 + (size_t)l * C,
                                      ptmp, BT, C, FC, 1.0f, 0);
        ln_res_kernel<<<BT, C>>>(px, ptmp, ln2_g + (size_t)l * C, ln2_b + (size_t)l * C, lens, 1);
    }

    transpose_kernel<<<dim3(T / 32, C / 32, B), dim3(32, 8)>>>(px, out_x);
    stats_kernel<<<dim3(2 * OUT / 64, BT / 64), 256>>>(px, pw, pb, lens, out_m, out_logs);
    mask_out_kernel<<<B, 256>>>(lens, out_mask);
}

// round 2
// speedup vs baseline: 1.3119x; 1.3119x over previous
#include <cuda_runtime.h>
#include <cuda_bf16.h>
#include <math.h>

namespace {

constexpr int C = 256, H = 4, HD = 64, L = 6, FC = 1024, OUT = 192;
constexpr int B = 8, T = 1024, BT = B * T, NREL = 9;

// ---------------- scratch (__device__ globals: allocation-free) ----------------
__device__ float g_x[BT * C];
__device__ float g_q[BT * C];
__device__ float g_k[BT * C];
__device__ float g_v[BT * C];
__device__ float g_attn[BT * C];
__device__ float g_tmp[BT * C];
__device__ float g_ffn[BT * FC];
__device__ float g_probs[(size_t)B * H * T * T];   // scores -> probs in place
__device__ float g_qrel[BT * H * NREL];

// ---------------- reductions ----------------
__device__ __forceinline__ float warpReduceSum(float v) {
#pragma unroll
    for (int o = 16; o; o >>= 1) v += __shfl_xor_sync(0xffffffffu, v, o);
    return v;
}
__device__ __forceinline__ float warpReduceMax(float v) {
#pragma unroll
    for (int o = 16; o; o >>= 1) v = fmaxf(v, __shfl_xor_sync(0xffffffffu, v, o));
    return v;
}
__device__ __forceinline__ float blockReduceSum256(float v) {
    __shared__ float s[8];
    int lane = threadIdx.x & 31, w = threadIdx.x >> 5;
    v = warpReduceSum(v);
    if (lane == 0) s[w] = v;
    __syncthreads();
    float tot = 0.f;
#pragma unroll
    for (int i = 0; i < 8; i++) tot += s[i];
    __syncthreads();
    return tot;
}
__device__ __forceinline__ float blockReduceMax256(float v) {
    __shared__ float s[8];
    int lane = threadIdx.x & 31, w = threadIdx.x >> 5;
    v = warpReduceMax(v);
    if (lane == 0) s[w] = v;
    __syncthreads();
    float tot = -1e30f;
#pragma unroll
    for (int i = 0; i < 8; i++) tot = fmaxf(tot, s[i]);
    __syncthreads();
    return tot;
}

// ---------------- bf16x3 helpers ----------------
__device__ __forceinline__ void cvt2(float a, float b, unsigned& ub, unsigned& us) {
    __nv_bfloat162 hb, hs;
    hb.x = __float2bfloat16_rn(a);
    hb.y = __float2bfloat16_rn(b);
    float ra = a - __bfloat162float(hb.x);
    float rb = b - __bfloat162float(hb.y);
    hs.x = __float2bfloat16_rn(ra);
    hs.y = __float2bfloat16_rn(rb);
    ub = *reinterpret_cast<unsigned*>(&hb);
    us = *reinterpret_cast<unsigned*>(&hs);
}

__device__ __forceinline__ void mma16816(float c[4], const unsigned a[4], const unsigned b2[2]) {
    asm volatile(
        "mma.sync.aligned.m16n8k16.row.col.f32.bf16.bf16.f32 "
        "{%0,%1,%2,%3}, {%4,%5,%6,%7}, {%8,%9}, {%0,%1,%2,%3};\n"
        : "+f"(c[0]), "+f"(c[1]), "+f"(c[2]), "+f"(c[3])
        : "r"(a[0]), "r"(a[1]), "r"(a[2]), "r"(a[3]), "r"(b2[0]), "r"(b2[1]));
}

#define LDU(ARR, R, Cc) (*reinterpret_cast<const unsigned*>(&ARR[R][Cc]))

// ---------------- embedding ----------------
__global__ void embed_kernel(const float* __restrict__ emb, const int* __restrict__ tokens,
                             float* __restrict__ x) {
    int bt = blockIdx.x;
    int c = threadIdx.x;
    x[(size_t)bt * C + c] = emb[(size_t)tokens[bt] * C + c] * 16.0f;  // sqrt(256)
}

// =====================================================================
//  bf16x3 tensor-core GEMM. Block tile 128(M) x 64(N), BK=32, 256 thr.
//  MODE 0: Y = act((A@B + bias)*alpha)          (B is [K,N] or [N,K] per BNK)
//  MODE 1: scores  S = Q@K^T + rel band -> g_probs     (BNK=true)
//  MODE 2: pv      O = P@V + rel_v band (strided out)  (BNK=false)
//  MODE 3: stats   split masked output                 (BNK=true)
// =====================================================================
template <int MODE, bool BNK>
__global__ __launch_bounds__(256) void mma_gemm(
    const float* __restrict__ Abase, const float* __restrict__ Bbase,
    const float* __restrict__ bias, float* __restrict__ out, float* __restrict__ out2,
    int M, int N, int K, int lda, int ldb, float alpha, int relu,
    const float* __restrict__ extra, const int* __restrict__ lens) {
    __shared__ __nv_bfloat16 As_b[128][40], As_s[128][40];
    __shared__ __nv_bfloat16 Bs_b[64][40], Bs_s[64][40];
    __shared__ float rvs[NREL * HD];

    const int tid = threadIdx.x;
    const int lane = tid & 31, wid = tid >> 5;
    const int wm = wid >> 1, wn = wid & 1;
    const int g = lane >> 2, tig = lane & 3;
    const int m0 = blockIdx.y * 128, n0 = blockIdx.x * 64;

    int b = 0, h = 0, bh = 0;
    const float* A = Abase;
    const float* Bm = Bbase;
    float* outp = out;
    if constexpr (MODE == 1) {
        bh = blockIdx.z; b = bh >> 2; h = bh & 3;
        A = Abase + (size_t)(b * T) * C + h * HD;
        Bm = Bbase + (size_t)(b * T) * C + h * HD;
    }
    if constexpr (MODE == 2) {
        bh = blockIdx.z; b = bh >> 2; h = bh & 3;
        A = g_probs + (size_t)bh * T * T;
        Bm = Bbase + (size_t)(b * T) * C + h * HD;
        outp = out + (size_t)(b * T) * C + h * HD;
        for (int i = tid; i < NREL * HD; i += 256) rvs[i] = extra[i];
    }

    float acc[2][4][4] = {};

    const int ar = tid >> 1, akh = (tid & 1) * 16;

    for (int k0 = 0; k0 < K; k0 += 32) {
        // ---- A tile: rows m0..m0+127, k0..k0+31, converted to big/small bf16 ----
        {
            const float* src = A + (size_t)(m0 + ar) * lda + k0 + akh;
#pragma unroll
            for (int i = 0; i < 4; i++) {
                float4 v = *reinterpret_cast<const float4*>(src + i * 4);
                unsigned ub0, us0, ub1, us1;
                cvt2(v.x, v.y, ub0, us0);
                cvt2(v.z, v.w, ub1, us1);
                *reinterpret_cast<uint2*>(&As_b[ar][akh + i * 4]) = make_uint2(ub0, ub1);
                *reinterpret_cast<uint2*>(&As_s[ar][akh + i * 4]) = make_uint2(us0, us1);
            }
        }
        // ---- B tile into Bs[n][k] (k-contiguous) ----
        if constexpr (BNK) {
            // B stored [N, K] row-major (ldb = row stride)
#pragma unroll
            for (int i = 0; i < 2; i++) {
                int idx = tid + i * 256;
                int n = idx >> 3, k4 = (idx & 7) * 4;
                float4 v = *reinterpret_cast<const float4*>(Bm + (size_t)(n0 + n) * ldb + k0 + k4);
                unsigned ub0, us0, ub1, us1;
                cvt2(v.x, v.y, ub0, us0);
                cvt2(v.z, v.w, ub1, us1);
                *reinterpret_cast<uint2*>(&Bs_b[n][k4]) = make_uint2(ub0, ub1);
                *reinterpret_cast<uint2*>(&Bs_s[n][k4]) = make_uint2(us0, us1);
            }
        } else {
            // B stored [K, N] row-major; transpose into Bs[n][k]
#pragma unroll
            for (int i = 0; i < 2; i++) {
                int idx = tid + i * 256;
                int k = idx >> 4, n4 = (idx & 15) * 4;
                float4 v = *reinterpret_cast<const float4*>(Bm + (size_t)(k0 + k) * ldb + n0 + n4);
                float vv[4] = {v.x, v.y, v.z, v.w};
#pragma unroll
                for (int j = 0; j < 4; j++) {
                    __nv_bfloat16 hb = __float2bfloat16_rn(vv[j]);
                    float s = vv[j] - __bfloat162float(hb);
                    Bs_b[n4 + j][k] = hb;
                    Bs_s[n4 + j][k] = __float2bfloat16_rn(s);
                }
            }
        }
        __syncthreads();

#pragma unroll
        for (int kk = 0; kk < 32; kk += 16) {
            unsigned ab[2][4], as_[2][4], bb[4][2], bs_[4][2];
#pragma unroll
            for (int am = 0; am < 2; am++) {
                int mr = wm * 32 + am * 16 + g;
                ab[am][0] = LDU(As_b, mr, kk + 2 * tig);
                ab[am][1] = LDU(As_b, mr + 8, kk + 2 * tig);
                ab[am][2] = LDU(As_b, mr, kk + 2 * tig + 8);
                ab[am][3] = LDU(As_b, mr + 8, kk + 2 * tig + 8);
                as_[am][0] = LDU(As_s, mr, kk + 2 * tig);
                as_[am][1] = LDU(As_s, mr + 8, kk + 2 * tig);
                as_[am][2] = LDU(As_s, mr, kk + 2 * tig + 8);
                as_[am][3] = LDU(As_s, mr + 8, kk + 2 * tig + 8);
            }
#pragma unroll
            for (int an = 0; an < 4; an++) {
                int nc = wn * 32 + an * 8 + g;
                bb[an][0] = LDU(Bs_b, nc, kk + 2 * tig);
                bb[an][1] = LDU(Bs_b, nc, kk + 2 * tig + 8);
                bs_[an][0] = LDU(Bs_s, nc, kk + 2 * tig);
                bs_[an][1] = LDU(Bs_s, nc, kk + 2 * tig + 8);
            }
#pragma unroll
            for (int am = 0; am < 2; am++)
#pragma unroll
                for (int an = 0; an < 4; an++) {
                    mma16816(acc[am][an], ab[am], bb[an]);
                    mma16816(acc[am][an], ab[am], bs_[an]);
                    mma16816(acc[am][an], as_[am], bb[an]);
                }
        }
        __syncthreads();
    }

    // ---------------- epilogue ----------------
#pragma unroll
    for (int am = 0; am < 2; am++) {
#pragma unroll
        for (int rr = 0; rr < 2; rr++) {
            int row = m0 + wm * 32 + am * 16 + g + rr * 8;
            float pband[9];
            if constexpr (MODE == 2) {
#pragma unroll
                for (int j = 0; j < 9; j++) {
                    int ki = row + j - 4;
                    pband[j] = (ki >= 0 && ki < T) ? A[(size_t)row * T + ki] : 0.0f;
                }
            }
#pragma unroll
            for (int an = 0; an < 4; an++) {
#pragma unroll
                for (int cc = 0; cc < 2; cc++) {
                    int col = n0 + wn * 32 + an * 8 + 2 * tig + cc;
                    float val = acc[am][an][rr * 2 + cc];
                    if constexpr (MODE == 0) {
                        val = (val + bias[col]) * alpha;
                        if (relu) val = fmaxf(val, 0.0f);
                        out[(size_t)row * N + col] = val;
                    } else if constexpr (MODE == 1) {
                        int d = col - row;
                        if (d >= -4 && d <= 4)
                            val += g_qrel[((size_t)(b * T + row) * H + h) * NREL + (d + 4)];
                        g_probs[(size_t)bh * T * T + (size_t)row * T + col] = val;
                    } else if constexpr (MODE == 2) {
#pragma unroll
                        for (int j = 0; j < 9; j++)
                            val = fmaf(pband[j], rvs[j * HD + col], val);
                        outp[(size_t)row * C + col] = val;
                    } else {  // MODE 3: stats
                        int bb2 = row >> 10, tt = row & (T - 1);
                        float mk = (tt < lens[bb2]) ? 1.0f : 0.0f;
                        float vv2 = (val + bias[col]) * mk;
                        if (col < OUT)
                            out[((size_t)bb2 * OUT + col) * T + tt] = vv2;
                        else
                            out2[((size_t)bb2 * OUT + (col - OUT)) * T + tt] = vv2;
                    }
                }
            }
        }
    }
}

// ---------------- qrel[bt,h,j] = q_row(bt,h) . rel_k[j]  (q already scaled) ----------------
__global__ void qrel_kernel(const float* __restrict__ q, const float* __restrict__ relk) {
    int w = blockIdx.x * 8 + (threadIdx.x >> 5);
    int lane = threadIdx.x & 31;
    int j = w % NREL;
    int bh = w / NREL;
    int h = bh % H;
    int bt = bh / H;
    const float* qp = q + (size_t)bt * C + h * HD;
    const float* rp = relk + j * HD;
    float s = qp[lane] * rp[lane] + qp[lane + 32] * rp[lane + 32];
#pragma unroll
    for (int o = 16; o; o >>= 1) s += __shfl_xor_sync(0xffffffffu, s, o);
    if (lane == 0) g_qrel[w] = s;
}

// ---------------- softmax over k with length mask; masked q rows -> 0 ----------------
__global__ void softmax_kernel(const int* __restrict__ lens) {
    int row = blockIdx.x;  // bh*T + q
    int qpos = row & (T - 1);
    int bh = row >> 10;
    int b = bh >> 2;
    int len = lens[b];
    float* p = g_probs + (size_t)row * T;
    int tid = threadIdx.x;
    if (qpos >= len) {
        *(float4*)(p + tid * 4) = make_float4(0.f, 0.f, 0.f, 0.f);
        return;
    }
    float mx = -1e30f;
    for (int kk = tid; kk < len; kk += 256) mx = fmaxf(mx, p[kk]);
    mx = blockReduceMax256(mx);
    float sum = 0.f;
    for (int kk = tid; kk < len; kk += 256) sum += __expf(p[kk] - mx);
    sum = blockReduceSum256(sum);
    float inv = 1.0f / sum;
    for (int kk = tid; kk < T; kk += 256) p[kk] = (kk < len) ? __expf(p[kk] - mx) * inv : 0.f;
}

// ---------------- x = LN(x + r)*g + b  [optionally * mask] ----------------
__global__ void ln_res_kernel(float* __restrict__ x, const float* __restrict__ r,
                              const float* __restrict__ gg, const float* __restrict__ beta,
                              const int* __restrict__ lens, int apply_mask) {
    int row = blockIdx.x;
    int c = threadIdx.x;
    size_t idx = (size_t)row * C + c;
    float val = x[idx] + r[idx];
    float mean = blockReduceSum256(val) * (1.0f / C);
    float d = val - mean;
    float var = blockReduceSum256(d * d) * (1.0f / C);
    float y = d * rsqrtf(var + 1e-5f) * gg[c] + beta[c];
    if (apply_mask) {
        int b = row >> 10, t = row & (T - 1);
        if (t >= lens[b]) y = 0.0f;
    }
    x[idx] = y;
}

// ---------------- x (B,T,C) -> out (B,C,T) ----------------
__global__ void transpose_kernel(const float* __restrict__ x, float* __restrict__ out) {
    __shared__ float tile[32][33];
    int b = blockIdx.z;
    int t0 = blockIdx.x * 32, c0 = blockIdx.y * 32;
    int tx = threadIdx.x, ty = threadIdx.y;
#pragma unroll
    for (int i = 0; i < 32; i += 8)
        tile[ty + i][tx] = x[(size_t)(b * T + t0 + ty + i) * C + c0 + tx];
    __syncthreads();
#pragma unroll
    for (int i = 0; i < 32; i += 8)
        out[(size_t)(b * C + c0 + ty + i) * T + t0 + tx] = tile[tx][ty + i];
}

__global__ void mask_out_kernel(const int* __restrict__ lens, float* __restrict__ out_mask) {
    int b = blockIdx.x;
    int len = lens[b];
    for (int t = threadIdx.x; t < T; t += blockDim.x)
        out_mask[(size_t)b * T + t] = (t < len) ? 1.0f : 0.0f;
}

}  // namespace

extern "C" void kernel_launch(void* const* d_in, const int* in_sizes, int n_in,
                              void* d_out, int out_size) {
    (void)in_sizes; (void)n_in; (void)out_size;
    const float* emb   = (const float*)d_in[0];
    const float* Wq    = (const float*)d_in[1];
    const float* Wk    = (const float*)d_in[2];
    const float* Wv    = (const float*)d_in[3];
    const float* Wo    = (const float*)d_in[4];
    const float* bq    = (const float*)d_in[5];
    const float* bk    = (const float*)d_in[6];
    const float* bv    = (const float*)d_in[7];
    const float* bo    = (const float*)d_in[8];
    const float* rel_k = (const float*)d_in[9];
    const float* rel_v = (const float*)d_in[10];
    const float* ln1_g = (const float*)d_in[11];
    const float* ln1_b = (const float*)d_in[12];
    const float* ln2_g = (const float*)d_in[13];
    const float* ln2_b = (const float*)d_in[14];
    const float* fw1   = (const float*)d_in[15];
    const float* fb1   = (const float*)d_in[16];
    const float* fw2   = (const float*)d_in[17];
    const float* fb2   = (const float*)d_in[18];
    const float* pw    = (const float*)d_in[19];
    const float* pb    = (const float*)d_in[20];
    const int*   toks  = (const int*)d_in[21];
    const int*   lens  = (const int*)d_in[22];

    float *px, *pq, *pk, *pvb, *pattn, *ptmp, *pffn;
    cudaGetSymbolAddress((void**)&px,    g_x);
    cudaGetSymbolAddress((void**)&pq,    g_q);
    cudaGetSymbolAddress((void**)&pk,    g_k);
    cudaGetSymbolAddress((void**)&pvb,   g_v);
    cudaGetSymbolAddress((void**)&pattn, g_attn);
    cudaGetSymbolAddress((void**)&ptmp,  g_tmp);
    cudaGetSymbolAddress((void**)&pffn,  g_ffn);

    float* out      = (float*)d_out;
    float* out_x    = out;                              // (B,C,T)
    float* out_m    = out + (size_t)B * C * T;          // (B,OUT,T)
    float* out_logs = out_m + (size_t)B * OUT * T;      // (B,OUT,T)
    float* out_mask = out_logs + (size_t)B * OUT * T;   // (B,1,T)

    embed_kernel<<<BT, C>>>(emb, toks, px);

    dim3 gC(C / 64, BT / 128);      // 4 x 64
    dim3 gFC(FC / 64, BT / 128);    // 16 x 64
    dim3 gSc(T / 64, T / 128, B * H);
    dim3 gPV(1, T / 128, B * H);

    for (int l = 0; l < L; l++) {
        const float* wq = Wq + (size_t)l * C * C;
        const float* wk = Wk + (size_t)l * C * C;
        const float* wv = Wv + (size_t)l * C * C;
        const float* wo = Wo + (size_t)l * C * C;

        mma_gemm<0, false><<<gC, 256>>>(px, wq, bq + (size_t)l * C, pq, nullptr,
                                        BT, C, C, C, C, 0.125f, 0, nullptr, nullptr);
        mma_gemm<0, false><<<gC, 256>>>(px, wk, bk + (size_t)l * C, pk, nullptr,
                                        BT, C, C, C, C, 1.0f, 0, nullptr, nullptr);
        mma_gemm<0, false><<<gC, 256>>>(px, wv, bv + (size_t)l * C, pvb, nullptr,
                                        BT, C, C, C, C, 1.0f, 0, nullptr, nullptr);

        qrel_kernel<<<BT * H * NREL / 8, 256>>>(pq, rel_k + (size_t)l * NREL * HD);
        mma_gemm<1, true><<<gSc, 256>>>(pq, pk, nullptr, nullptr, nullptr,
                                        T, T, HD, C, C, 1.0f, 0, nullptr, nullptr);
        softmax_kernel<<<B * H * T, 256>>>(lens);
        mma_gemm<2, false><<<gPV, 256>>>(nullptr, pvb, nullptr, pattn, nullptr,
                                         T, HD, T, T, C, 1.0f, 0,
                                         rel_v + (size_t)l * NREL * HD, nullptr);

        mma_gemm<0, false><<<gC, 256>>>(pattn, wo, bo + (size_t)l * C, ptmp, nullptr,
                                        BT, C, C, C, C, 1.0f, 0, nullptr, nullptr);
        ln_res_kernel<<<BT, C>>>(px, ptmp, ln1_g + (size_t)l * C, ln1_b + (size_t)l * C, lens, 0);

        mma_gemm<0, false><<<gFC, 256>>>(px, fw1 + (size_t)l * C * FC, fb1 + (size_t)l * FC,
                                         pffn, nullptr, BT, FC, C, C, FC, 1.0f, 1,
                                         nullptr, nullptr);
        mma_gemm<0, false><<<gC, 256>>>(pffn, fw2 + (size_t)l * FC * C, fb2 + (size_t)l * C,
                                        ptmp, nullptr, BT, C, FC, FC, C, 1.0f, 0,
                                        nullptr, nullptr);
        ln_res_kernel<<<BT, C>>>(px, ptmp, ln2_g + (size_t)l * C, ln2_b + (size_t)l * C, lens, 1);
    }

    transpose_kernel<<<dim3(T / 32, C / 32, B), dim3(32, 8)>>>(px, out_x);
    mma_gemm<3, true><<<dim3(2 * OUT / 64, BT / 128), 256>>>(px, pw, pb, out_m, out_logs,
                                                             BT, 2 * OUT, C, C, C, 1.0f, 0,
                                                             nullptr, lens);
    mask_out_kernel<<<B, 256>>>(lens, out_mask);
}

// round 3
// speedup vs baseline: 1.4018x; 1.0685x over previous
#include <cuda_runtime.h>
#include <cuda_bf16.h>
#include <math.h>

namespace {

constexpr int C = 256, H = 4, HD = 64, L = 6, FC = 1024, OUT = 192;
constexpr int B = 8, T = 1024, BT = B * T, NREL = 9;

// ---------------- scratch (__device__ globals: allocation-free) ----------------
__device__ float g_x[BT * C];
__device__ float g_q[BT * C];
__device__ float g_k[BT * C];
__device__ float g_v[BT * C];
__device__ float g_attn[BT * C];
__device__ float g_tmp[BT * C];
__device__ float g_ffn[BT * FC];
__device__ float g_probs[(size_t)B * H * T * T];
__device__ float g_qrel[BT * H * NREL];

// ---------------- reductions ----------------
__device__ __forceinline__ float warpReduceSum(float v) {
#pragma unroll
    for (int o = 16; o; o >>= 1) v += __shfl_xor_sync(0xffffffffu, v, o);
    return v;
}
__device__ __forceinline__ float warpReduceMax(float v) {
#pragma unroll
    for (int o = 16; o; o >>= 1) v = fmaxf(v, __shfl_xor_sync(0xffffffffu, v, o));
    return v;
}
__device__ __forceinline__ float blockReduceSum256(float v) {
    __shared__ float s[8];
    int lane = threadIdx.x & 31, w = threadIdx.x >> 5;
    v = warpReduceSum(v);
    if (lane == 0) s[w] = v;
    __syncthreads();
    float tot = 0.f;
#pragma unroll
    for (int i = 0; i < 8; i++) tot += s[i];
    __syncthreads();
    return tot;
}
__device__ __forceinline__ float blockReduceMax256(float v) {
    __shared__ float s[8];
    int lane = threadIdx.x & 31, w = threadIdx.x >> 5;
    v = warpReduceMax(v);
    if (lane == 0) s[w] = v;
    __syncthreads();
    float tot = -1e30f;
#pragma unroll
    for (int i = 0; i < 8; i++) tot = fmaxf(tot, s[i]);
    __syncthreads();
    return tot;
}

// ---------------- bf16x3 helpers ----------------
__device__ __forceinline__ void cvt2(float a, float b, unsigned& ub, unsigned& us) {
    __nv_bfloat162 hb, hs;
    hb.x = __float2bfloat16_rn(a);
    hb.y = __float2bfloat16_rn(b);
    float ra = a - __bfloat162float(hb.x);
    float rb = b - __bfloat162float(hb.y);
    hs.x = __float2bfloat16_rn(ra);
    hs.y = __float2bfloat16_rn(rb);
    ub = *reinterpret_cast<unsigned*>(&hb);
    us = *reinterpret_cast<unsigned*>(&hs);
}

__device__ __forceinline__ void mma16816(float c[4], const unsigned a[4], const unsigned b2[2]) {
    asm volatile(
        "mma.sync.aligned.m16n8k16.row.col.f32.bf16.bf16.f32 "
        "{%0,%1,%2,%3}, {%4,%5,%6,%7}, {%8,%9}, {%0,%1,%2,%3};\n"
        : "+f"(c[0]), "+f"(c[1]), "+f"(c[2]), "+f"(c[3])
        : "r"(a[0]), "r"(a[1]), "r"(a[2]), "r"(a[3]), "r"(b2[0]), "r"(b2[1]));
}

__device__ __forceinline__ void ldsm_x4(unsigned& r0, unsigned& r1, unsigned& r2, unsigned& r3,
                                        const void* p) {
    unsigned addr = (unsigned)__cvta_generic_to_shared(p);
    asm volatile("ldmatrix.sync.aligned.m8n8.x4.shared.b16 {%0,%1,%2,%3}, [%4];"
                 : "=r"(r0), "=r"(r1), "=r"(r2), "=r"(r3)
                 : "r"(addr));
}

// ---------------- embedding ----------------
__global__ void embed_kernel(const float* __restrict__ emb, const int* __restrict__ tokens,
                             float* __restrict__ x) {
    int bt = blockIdx.x;
    int c = threadIdx.x;
    x[(size_t)bt * C + c] = emb[(size_t)tokens[bt] * C + c] * 16.0f;  // sqrt(256)
}

// =====================================================================
//  bf16x3 tensor-core GEMM: 128(M) x 64(N) tile, BK=32, 256 threads.
//  Double-buffered smem (register-staged) + ldmatrix fragments.
// =====================================================================
constexpr int APITCH = 40;
constexpr int ASZ = 128 * APITCH;  // per buffer
constexpr int BSZ = 64 * APITCH;
constexpr int SMEM_BYTES = (4 * ASZ + 4 * BSZ) * (int)sizeof(__nv_bfloat16);  // 61440

template <int MODE, bool BNK>
__global__ __launch_bounds__(256, 2) void mma_gemm(
    const float* __restrict__ Abase, const float* __restrict__ Bbase,
    const float* __restrict__ bias, float* __restrict__ out, float* __restrict__ out2,
    int M, int N, int K, int lda, int ldb, float alpha, int relu,
    const float* __restrict__ extra, const int* __restrict__ lens) {
    extern __shared__ __nv_bfloat16 dsm[];
    __nv_bfloat16* As_b = dsm;                      // [2][128][40]
    __nv_bfloat16* As_s = dsm + 2 * ASZ;
    __nv_bfloat16* Bs_b = dsm + 4 * ASZ;            // [2][64][40]
    __nv_bfloat16* Bs_s = dsm + 4 * ASZ + 2 * BSZ;
    __shared__ float rvs[NREL * HD];

#define ASB(bf, r, c) As_b[(bf)*ASZ + (r)*APITCH + (c)]
#define ASS(bf, r, c) As_s[(bf)*ASZ + (r)*APITCH + (c)]
#define BSB(bf, r, c) Bs_b[(bf)*BSZ + (r)*APITCH + (c)]
#define BSS(bf, r, c) Bs_s[(bf)*BSZ + (r)*APITCH + (c)]

    const int tid = threadIdx.x;
    const int lane = tid & 31, wid = tid >> 5;
    const int wm = wid >> 1, wn = wid & 1;
    const int g = lane >> 2, tig = lane & 3;
    const int m0 = blockIdx.y * 128, n0 = blockIdx.x * 64;

    int b = 0, h = 0, bh = 0;
    const float* A = Abase;
    const float* Bm = Bbase;
    float* outp = out;
    if constexpr (MODE == 1) {
        bh = blockIdx.z; b = bh >> 2; h = bh & 3;
        A = Abase + (size_t)(b * T) * C + h * HD;
        Bm = Bbase + (size_t)(b * T) * C + h * HD;
    }
    if constexpr (MODE == 2) {
        bh = blockIdx.z; b = bh >> 2; h = bh & 3;
        A = g_probs + (size_t)bh * T * T;
        Bm = Bbase + (size_t)(b * T) * C + h * HD;
        outp = out + (size_t)(b * T) * C + h * HD;
        for (int i = tid; i < NREL * HD; i += 256) rvs[i] = extra[i];
    }

    const int ar = tid >> 1, akh = (tid & 1) * 16;

    // fragment lane addressing
    const int lane7 = lane & 7;
    const int arow = wm * 32 + lane7 + ((lane & 8) ? 8 : 0);
    const int acolsel = (lane & 16) ? 8 : 0;
    const int brow = wn * 32 + lane7 + ((lane & 16) ? 8 : 0);
    const int bcolsel = (lane & 8) ? 8 : 0;

    float acc[2][4][4] = {};
    float4 rA[4];
    float4 rB[2];

    auto load_tiles = [&](int k0) {
        const float* srcA = A + (size_t)(m0 + ar) * lda + k0 + akh;
#pragma unroll
        for (int i = 0; i < 4; i++) rA[i] = *reinterpret_cast<const float4*>(srcA + i * 4);
        if constexpr (BNK) {
#pragma unroll
            for (int i = 0; i < 2; i++) {
                int idx = tid + i * 256;
                int n = idx >> 3, k4 = (idx & 7) * 4;
                rB[i] = *reinterpret_cast<const float4*>(Bm + (size_t)(n0 + n) * ldb + k0 + k4);
            }
        } else {
#pragma unroll
            for (int i = 0; i < 2; i++) {
                int idx = tid + i * 256;
                int k = idx >> 4, n4 = (idx & 15) * 4;
                rB[i] = *reinterpret_cast<const float4*>(Bm + (size_t)(k0 + k) * ldb + n0 + n4);
            }
        }
    };

    auto store_tiles = [&](int buf) {
#pragma unroll
        for (int i = 0; i < 4; i++) {
            unsigned ub0, us0, ub1, us1;
            cvt2(rA[i].x, rA[i].y, ub0, us0);
            cvt2(rA[i].z, rA[i].w, ub1, us1);
            *reinterpret_cast<uint2*>(&ASB(buf, ar, akh + i * 4)) = make_uint2(ub0, ub1);
            *reinterpret_cast<uint2*>(&ASS(buf, ar, akh + i * 4)) = make_uint2(us0, us1);
        }
        if constexpr (BNK) {
#pragma unroll
            for (int i = 0; i < 2; i++) {
                int idx = tid + i * 256;
                int n = idx >> 3, k4 = (idx & 7) * 4;
                unsigned ub0, us0, ub1, us1;
                cvt2(rB[i].x, rB[i].y, ub0, us0);
                cvt2(rB[i].z, rB[i].w, ub1, us1);
                *reinterpret_cast<uint2*>(&BSB(buf, n, k4)) = make_uint2(ub0, ub1);
                *reinterpret_cast<uint2*>(&BSS(buf, n, k4)) = make_uint2(us0, us1);
            }
        } else {
#pragma unroll
            for (int i = 0; i < 2; i++) {
                int idx = tid + i * 256;
                int k = idx >> 4, n4 = (idx & 15) * 4;
                float vv[4] = {rB[i].x, rB[i].y, rB[i].z, rB[i].w};
#pragma unroll
                for (int j = 0; j < 4; j++) {
                    __nv_bfloat16 hb = __float2bfloat16_rn(vv[j]);
                    float s = vv[j] - __bfloat162float(hb);
                    BSB(buf, n4 + j, k) = hb;
                    BSS(buf, n4 + j, k) = __float2bfloat16_rn(s);
                }
            }
        }
    };

    load_tiles(0);
    int buf = 0;
    for (int k0 = 0; k0 < K; k0 += 32) {
        store_tiles(buf);
        __syncthreads();
        if (k0 + 32 < K) load_tiles(k0 + 32);
#pragma unroll
        for (int kk = 0; kk < 32; kk += 16) {
            unsigned ab[2][4], as_[2][4], bb[4][2], bs_[4][2];
#pragma unroll
            for (int am = 0; am < 2; am++) {
                ldsm_x4(ab[am][0], ab[am][1], ab[am][2], ab[am][3],
                        &ASB(buf, arow + am * 16, kk + acolsel));
                ldsm_x4(as_[am][0], as_[am][1], as_[am][2], as_[am][3],
                        &ASS(buf, arow + am * 16, kk + acolsel));
            }
#pragma unroll
            for (int p = 0; p < 2; p++) {
                ldsm_x4(bb[2 * p][0], bb[2 * p][1], bb[2 * p + 1][0], bb[2 * p + 1][1],
                        &BSB(buf, brow + p * 16, kk + bcolsel));
                ldsm_x4(bs_[2 * p][0], bs_[2 * p][1], bs_[2 * p + 1][0], bs_[2 * p + 1][1],
                        &BSS(buf, brow + p * 16, kk + bcolsel));
            }
#pragma unroll
            for (int am = 0; am < 2; am++)
#pragma unroll
                for (int an = 0; an < 4; an++) {
                    mma16816(acc[am][an], ab[am], bb[an]);
                    mma16816(acc[am][an], ab[am], bs_[an]);
                    mma16816(acc[am][an], as_[am], bb[an]);
                }
        }
        buf ^= 1;
        __syncthreads();
    }

    // ---------------- epilogue ----------------
#pragma unroll
    for (int am = 0; am < 2; am++) {
#pragma unroll
        for (int rr = 0; rr < 2; rr++) {
            int row = m0 + wm * 32 + am * 16 + g + rr * 8;
            float pband[9];
            if constexpr (MODE == 2) {
#pragma unroll
                for (int j = 0; j < 9; j++) {
                    int ki = row + j - 4;
                    pband[j] = (ki >= 0 && ki < T) ? A[(size_t)row * T + ki] : 0.0f;
                }
            }
#pragma unroll
            for (int an = 0; an < 4; an++) {
#pragma unroll
                for (int cc = 0; cc < 2; cc++) {
                    int col = n0 + wn * 32 + an * 8 + 2 * tig + cc;
                    float val = acc[am][an][rr * 2 + cc];
                    if constexpr (MODE == 0) {
                        val = (val + bias[col]) * alpha;
                        if (relu) val = fmaxf(val, 0.0f);
                        out[(size_t)row * N + col] = val;
                    } else if constexpr (MODE == 1) {
                        int d = col - row;
                        if (d >= -4 && d <= 4)
                            val += g_qrel[((size_t)(b * T + row) * H + h) * NREL + (d + 4)];
                        g_probs[(size_t)bh * T * T + (size_t)row * T + col] = val;
                    } else if constexpr (MODE == 2) {
#pragma unroll
                        for (int j = 0; j < 9; j++)
                            val = fmaf(pband[j], rvs[j * HD + col], val);
                        outp[(size_t)row * C + col] = val;
                    } else {  // MODE 3: stats
                        int bb2 = row >> 10, tt = row & (T - 1);
                        float mk = (tt < lens[bb2]) ? 1.0f : 0.0f;
                        float vv2 = (val + bias[col]) * mk;
                        if (col < OUT)
                            out[((size_t)bb2 * OUT + col) * T + tt] = vv2;
                        else
                            out2[((size_t)bb2 * OUT + (col - OUT)) * T + tt] = vv2;
                    }
                }
            }
        }
    }
#undef ASB
#undef ASS
#undef BSB
#undef BSS
}

// ---------------- qrel[bt,h,j] = q_row(bt,h) . rel_k[j]  (q pre-scaled) ----------------
__global__ void qrel_kernel(const float* __restrict__ q, const float* __restrict__ relk) {
    int w = blockIdx.x * 8 + (threadIdx.x >> 5);
    int lane = threadIdx.x & 31;
    int j = w % NREL;
    int bh = w / NREL;
    int h = bh % H;
    int bt = bh / H;
    const float* qp = q + (size_t)bt * C + h * HD;
    const float* rp = relk + j * HD;
    float s = qp[lane] * rp[lane] + qp[lane + 32] * rp[lane + 32];
#pragma unroll
    for (int o = 16; o; o >>= 1) s += __shfl_xor_sync(0xffffffffu, s, o);
    if (lane == 0) g_qrel[w] = s;
}

// ---------------- softmax over k (smem-cached row) ----------------
__global__ void softmax_kernel(const int* __restrict__ lens) {
    __shared__ float rowbuf[T];
    int row = blockIdx.x;  // bh*T + q
    int qpos = row & (T - 1);
    int bh = row >> 10;
    int b = bh >> 2;
    int len = lens[b];
    float* p = g_probs + (size_t)row * T;
    int tid = threadIdx.x;
    if (qpos >= len) {
        *(float4*)(p + tid * 4) = make_float4(0.f, 0.f, 0.f, 0.f);
        return;
    }
    float mx = -1e30f;
    for (int kk = tid; kk < len; kk += 256) {
        float v = p[kk];
        rowbuf[kk] = v;
        mx = fmaxf(mx, v);
    }
    mx = blockReduceMax256(mx);
    float sum = 0.f;
    for (int kk = tid; kk < len; kk += 256) {
        float e = __expf(rowbuf[kk] - mx);
        rowbuf[kk] = e;
        sum += e;
    }
    sum = blockReduceSum256(sum);
    float inv = 1.0f / sum;
    for (int kk = tid; kk < T; kk += 256) p[kk] = (kk < len) ? rowbuf[kk] * inv : 0.f;
}

// ---------------- x = LN(x + r)*g + b  [optionally * mask] ----------------
__global__ void ln_res_kernel(float* __restrict__ x, const float* __restrict__ r,
                              const float* __restrict__ gg, const float* __restrict__ beta,
                              const int* __restrict__ lens, int apply_mask) {
    int row = blockIdx.x;
    int c = threadIdx.x;
    size_t idx = (size_t)row * C + c;
    float val = x[idx] + r[idx];
    float mean = blockReduceSum256(val) * (1.0f / C);
    float d = val - mean;
    float var = blockReduceSum256(d * d) * (1.0f / C);
    float y = d * rsqrtf(var + 1e-5f) * gg[c] + beta[c];
    if (apply_mask) {
        int b = row >> 10, t = row & (T - 1);
        if (t >= lens[b]) y = 0.0f;
    }
    x[idx] = y;
}

// ---------------- x (B,T,C) -> out (B,C,T) ----------------
__global__ void transpose_kernel(const float* __restrict__ x, float* __restrict__ out) {
    __shared__ float tile[32][33];
    int b = blockIdx.z;
    int t0 = blockIdx.x * 32, c0 = blockIdx.y * 32;
    int tx = threadIdx.x, ty = threadIdx.y;
#pragma unroll
    for (int i = 0; i < 32; i += 8)
        tile[ty + i][tx] = x[(size_t)(b * T + t0 + ty + i) * C + c0 + tx];
    __syncthreads();
#pragma unroll
    for (int i = 0; i < 32; i += 8)
        out[(size_t)(b * C + c0 + ty + i) * T + t0 + tx] = tile[tx][ty + i];
}

__global__ void mask_out_kernel(const int* __restrict__ lens, float* __restrict__ out_mask) {
    int b = blockIdx.x;
    int len = lens[b];
    for (int t = threadIdx.x; t < T; t += blockDim.x)
        out_mask[(size_t)b * T + t] = (t < len) ? 1.0f : 0.0f;
}

}  // namespace

extern "C" void kernel_launch(void* const* d_in, const int* in_sizes, int n_in,
                              void* d_out, int out_size) {
    (void)in_sizes; (void)n_in; (void)out_size;
    const float* emb   = (const float*)d_in[0];
    const float* Wq    = (const float*)d_in[1];
    const float* Wk    = (const float*)d_in[2];
    const float* Wv    = (const float*)d_in[3];
    const float* Wo    = (const float*)d_in[4];
    const float* bq    = (const float*)d_in[5];
    const float* bk    = (const float*)d_in[6];
    const float* bv    = (const float*)d_in[7];
    const float* bo    = (const float*)d_in[8];
    const float* rel_k = (const float*)d_in[9];
    const float* rel_v = (const float*)d_in[10];
    const float* ln1_g = (const float*)d_in[11];
    const float* ln1_b = (const float*)d_in[12];
    const float* ln2_g = (const float*)d_in[13];
    const float* ln2_b = (const float*)d_in[14];
    const float* fw1   = (const float*)d_in[15];
    const float* fb1   = (const float*)d_in[16];
    const float* fw2   = (const float*)d_in[17];
    const float* fb2   = (const float*)d_in[18];
    const float* pw    = (const float*)d_in[19];
    const float* pb    = (const float*)d_in[20];
    const int*   toks  = (const int*)d_in[21];
    const int*   lens  = (const int*)d_in[22];

    static bool attr_done = false;
    if (!attr_done) {
        cudaFuncSetAttribute(mma_gemm<0, false>, cudaFuncAttributeMaxDynamicSharedMemorySize, SMEM_BYTES);
        cudaFuncSetAttribute(mma_gemm<1, true>,  cudaFuncAttributeMaxDynamicSharedMemorySize, SMEM_BYTES);
        cudaFuncSetAttribute(mma_gemm<2, false>, cudaFuncAttributeMaxDynamicSharedMemorySize, SMEM_BYTES);
        cudaFuncSetAttribute(mma_gemm<3, true>,  cudaFuncAttributeMaxDynamicSharedMemorySize, SMEM_BYTES);
        attr_done = true;
    }

    float *px, *pq, *pk, *pvb, *pattn, *ptmp, *pffn;
    cudaGetSymbolAddress((void**)&px,    g_x);
    cudaGetSymbolAddress((void**)&pq,    g_q);
    cudaGetSymbolAddress((void**)&pk,    g_k);
    cudaGetSymbolAddress((void**)&pvb,   g_v);
    cudaGetSymbolAddress((void**)&pattn, g_attn);
    cudaGetSymbolAddress((void**)&ptmp,  g_tmp);
    cudaGetSymbolAddress((void**)&pffn,  g_ffn);

    float* out      = (float*)d_out;
    float* out_x    = out;                              // (B,C,T)
    float* out_m    = out + (size_t)B * C * T;          // (B,OUT,T)
    float* out_logs = out_m + (size_t)B * OUT * T;      // (B,OUT,T)
    float* out_mask = out_logs + (size_t)B * OUT * T;   // (B,1,T)

    embed_kernel<<<BT, C>>>(emb, toks, px);

    dim3 gC(C / 64, BT / 128);      // 4 x 64
    dim3 gFC(FC / 64, BT / 128);    // 16 x 64
    dim3 gSc(T / 64, T / 128, B * H);
    dim3 gPV(1, T / 128, B * H);

    for (int l = 0; l < L; l++) {
        const float* wq = Wq + (size_t)l * C * C;
        const float* wk = Wk + (size_t)l * C * C;
        const float* wv = Wv + (size_t)l * C * C;
        const float* wo = Wo + (size_t)l * C * C;

        mma_gemm<0, false><<<gC, 256, SMEM_BYTES>>>(px, wq, bq + (size_t)l * C, pq, nullptr,
                                                    BT, C, C, C, C, 0.125f, 0, nullptr, nullptr);
        mma_gemm<0, false><<<gC, 256, SMEM_BYTES>>>(px, wk, bk + (size_t)l * C, pk, nullptr,
                                                    BT, C, C, C, C, 1.0f, 0, nullptr, nullptr);
        mma_gemm<0, false><<<gC, 256, SMEM_BYTES>>>(px, wv, bv + (size_t)l * C, pvb, nullptr,
                                                    BT, C, C, C, C, 1.0f, 0, nullptr, nullptr);

        qrel_kernel<<<BT * H * NREL / 8, 256>>>(pq, rel_k + (size_t)l * NREL * HD);
        mma_gemm<1, true><<<gSc, 256, SMEM_BYTES>>>(pq, pk, nullptr, nullptr, nullptr,
                                                    T, T, HD, C, C, 1.0f, 0, nullptr, nullptr);
        softmax_kernel<<<B * H * T, 256>>>(lens);
        mma_gemm<2, false><<<gPV, 256, SMEM_BYTES>>>(nullptr, pvb, nullptr, pattn, nullptr,
                                                     T, HD, T, T, C, 1.0f, 0,
                                                     rel_v + (size_t)l * NREL * HD, nullptr);

        mma_gemm<0, false><<<gC, 256, SMEM_BYTES>>>(pattn, wo, bo + (size_t)l * C, ptmp, nullptr,
                                                    BT, C, C, C, C, 1.0f, 0, nullptr, nullptr);
        ln_res_kernel<<<BT, C>>>(px, ptmp, ln1_g + (size_t)l * C, ln1_b + (size_t)l * C, lens, 0);

        mma_gemm<0, false><<<gFC, 256, SMEM_BYTES>>>(px, fw1 + (size_t)l * C * FC,
                                                     fb1 + (size_t)l * FC, pffn, nullptr,
                                                     BT, FC, C, C, FC, 1.0f, 1, nullptr, nullptr);
        mma_gemm<0, false><<<gC, 256, SMEM_BYTES>>>(pffn, fw2 + (size_t)l * FC * C,
                                                    fb2 + (size_t)l * C, ptmp, nullptr,
                                                    BT, C, FC, FC, C, 1.0f, 0, nullptr, nullptr);
        ln_res_kernel<<<BT, C>>>(px, ptmp, ln2_g + (size_t)l * C, ln2_b + (size_t)l * C, lens, 1);
    }

    transpose_kernel<<<dim3(T / 32, C / 32, B), dim3(32, 8)>>>(px, out_x);
    mma_gemm<3, true><<<dim3(2 * OUT / 64, BT / 128), 256, SMEM_BYTES>>>(
        px, pw, pb, out_m, out_logs, BT, 2 * OUT, C, C, C, 1.0f, 0, nullptr, lens);
    mask_out_kernel<<<B, 256>>>(lens, out_mask);
}

// round 4
// speedup vs baseline: 1.7437x; 1.2439x over previous
#include <cuda_runtime.h>
#include <cuda_bf16.h>
#include <math.h>

namespace {

constexpr int C = 256, H = 4, HD = 64, L = 6, FC = 1024, OUT = 192;
constexpr int B = 8, T = 1024, BT = B * T, NREL = 9;

typedef __nv_bfloat16 bf16;

// ---------------- weight pair storage ----------------
constexpr size_t WTENS = (size_t)L * C * C;             // 393216
constexpr size_t OFF_WQ = 0, OFF_WK = WTENS, OFF_WV = 2 * WTENS, OFF_WO = 3 * WTENS;
constexpr size_t OFF_F1 = 4 * WTENS;
constexpr size_t OFF_F2 = OFF_F1 + (size_t)L * C * FC;
constexpr size_t OFF_PJ = OFF_F2 + (size_t)L * FC * C;
constexpr size_t WTOT   = OFF_PJ + (size_t)2 * OUT * C;

__device__ bf16 g_wb[WTOT];
__device__ bf16 g_ws[WTOT];

// ---------------- activation scratch ----------------
__device__ float g_x[BT * C];
__device__ float g_tmp[BT * C];
__device__ bf16 g_xb[BT * C], g_xs[BT * C];
__device__ bf16 g_qb[BT * C], g_qs[BT * C];
__device__ bf16 g_kb[BT * C], g_ks[BT * C];
__device__ bf16 g_vb[BT * C], g_vs[BT * C];
__device__ bf16 g_ab[BT * C], g_as[BT * C];
__device__ bf16 g_fb[BT * FC], g_fs[BT * FC];

// ---------------- helpers ----------------
__device__ __forceinline__ float warpReduceSum(float v) {
#pragma unroll
    for (int o = 16; o; o >>= 1) v += __shfl_xor_sync(0xffffffffu, v, o);
    return v;
}
__device__ __forceinline__ float blockReduceSum256(float v) {
    __shared__ float s[8];
    int lane = threadIdx.x & 31, w = threadIdx.x >> 5;
    v = warpReduceSum(v);
    if (lane == 0) s[w] = v;
    __syncthreads();
    float tot = 0.f;
#pragma unroll
    for (int i = 0; i < 8; i++) tot += s[i];
    __syncthreads();
    return tot;
}

__device__ __forceinline__ void cvt2(float a, float b, unsigned& ub, unsigned& us) {
    __nv_bfloat162 hb, hs;
    hb.x = __float2bfloat16_rn(a);
    hb.y = __float2bfloat16_rn(b);
    float ra = a - __bfloat162float(hb.x);
    float rb = b - __bfloat162float(hb.y);
    hs.x = __float2bfloat16_rn(ra);
    hs.y = __float2bfloat16_rn(rb);
    ub = *reinterpret_cast<unsigned*>(&hb);
    us = *reinterpret_cast<unsigned*>(&hs);
}

__device__ __forceinline__ void mma16816(float c[4], const unsigned a[4], const unsigned b2[2]) {
    asm volatile(
        "mma.sync.aligned.m16n8k16.row.col.f32.bf16.bf16.f32 "
        "{%0,%1,%2,%3}, {%4,%5,%6,%7}, {%8,%9}, {%0,%1,%2,%3};\n"
        : "+f"(c[0]), "+f"(c[1]), "+f"(c[2]), "+f"(c[3])
        : "r"(a[0]), "r"(a[1]), "r"(a[2]), "r"(a[3]), "r"(b2[0]), "r"(b2[1]));
}

__device__ __forceinline__ void ldsm_x4(unsigned& r0, unsigned& r1, unsigned& r2, unsigned& r3,
                                        const void* p) {
    unsigned addr = (unsigned)__cvta_generic_to_shared(p);
    asm volatile("ldmatrix.sync.aligned.m8n8.x4.shared.b16 {%0,%1,%2,%3}, [%4];"
                 : "=r"(r0), "=r"(r1), "=r"(r2), "=r"(r3)
                 : "r"(addr));
}

// ---------------- weight conversion ----------------
// W [Lz][K][N] fp32 -> pair [Lz][N][K]
__global__ void wconv_t(const float* __restrict__ w, bf16* __restrict__ ob,
                        bf16* __restrict__ os, int K, int N) {
    __shared__ float tile[32][33];
    int l = blockIdx.z;
    const float* src = w + (size_t)l * K * N;
    int k0 = blockIdx.y * 32, n0 = blockIdx.x * 32;
    int tx = threadIdx.x, ty = threadIdx.y;
#pragma unroll
    for (int i = 0; i < 32; i += 8)
        tile[ty + i][tx] = src[(size_t)(k0 + ty + i) * N + n0 + tx];
    __syncthreads();
#pragma unroll
    for (int i = 0; i < 32; i += 8) {
        float v = tile[tx][ty + i];
        size_t o = (size_t)l * N * K + (size_t)(n0 + ty + i) * K + k0 + tx;
        bf16 hb = __float2bfloat16_rn(v);
        ob[o] = hb;
        os[o] = __float2bfloat16_rn(v - __bfloat162float(hb));
    }
}

__global__ void projconv(const float* __restrict__ pw) {
    int i = blockIdx.x * 256 + threadIdx.x;
    if (i >= 2 * OUT * C) return;
    float v = pw[i];
    bf16 hb = __float2bfloat16_rn(v);
    g_wb[OFF_PJ + i] = hb;
    g_ws[OFF_PJ + i] = __float2bfloat16_rn(v - __bfloat162float(hb));
}

// ---------------- embedding (fp32 + pair) ----------------
__global__ void embed_kernel(const float* __restrict__ emb, const int* __restrict__ tokens) {
    int bt = blockIdx.x;
    int c = threadIdx.x;
    float v = emb[(size_t)tokens[bt] * C + c] * 16.0f;
    size_t idx = (size_t)bt * C + c;
    g_x[idx] = v;
    bf16 hb = __float2bfloat16_rn(v);
    g_xb[idx] = hb;
    g_xs[idx] = __float2bfloat16_rn(v - __bfloat162float(hb));
}

// =====================================================================
//  Pair-input bf16x3 GEMM: 128x64 tile, BK=32, 256 threads, dbl-buffered.
//  MODE 0: linear (optional fp32 out / pair out, bias, alpha, relu)
//  MODE 3: stats split masked
// =====================================================================
constexpr int APITCH = 40;
constexpr int ASZ = 128 * APITCH;
constexpr int BSZ = 64 * APITCH;
constexpr int SMEM_BYTES = (4 * ASZ + 4 * BSZ) * (int)sizeof(bf16);  // 61440

template <int MODE>
__global__ __launch_bounds__(256, 2) void mma_gemm_p(
    const bf16* __restrict__ Ab, const bf16* __restrict__ As2,
    const bf16* __restrict__ Bb, const bf16* __restrict__ Bs2,
    const float* __restrict__ bias, float* __restrict__ outf,
    bf16* __restrict__ outb, bf16* __restrict__ outs, float* __restrict__ out2,
    int M, int N, int K, float alpha, int relu, const int* __restrict__ lens) {
    extern __shared__ bf16 dsm[];
    bf16* As_b = dsm;
    bf16* As_s = dsm + 2 * ASZ;
    bf16* Bs_b = dsm + 4 * ASZ;
    bf16* Bs_s = dsm + 4 * ASZ + 2 * BSZ;

#define ASB(bf_, r, c) As_b[(bf_)*ASZ + (r)*APITCH + (c)]
#define ASS(bf_, r, c) As_s[(bf_)*ASZ + (r)*APITCH + (c)]
#define BSB(bf_, r, c) Bs_b[(bf_)*BSZ + (r)*APITCH + (c)]
#define BSS(bf_, r, c) Bs_s[(bf_)*BSZ + (r)*APITCH + (c)]

    const int tid = threadIdx.x;
    const int lane = tid & 31, wid = tid >> 5;
    const int wm = wid >> 1, wn = wid & 1;
    const int g = lane >> 2, tig = lane & 3;
    const int m0 = blockIdx.y * 128, n0 = blockIdx.x * 64;

    const int ar = tid >> 1, akh = (tid & 1) * 16;
    const int bn = tid >> 2, bkq = (tid & 3) * 8;

    const int lane7 = lane & 7;
    const int arow = wm * 32 + lane7 + ((lane & 8) ? 8 : 0);
    const int acolsel = (lane & 16) ? 8 : 0;
    const int brow = wn * 32 + lane7 + ((lane & 16) ? 8 : 0);
    const int bcolsel = (lane & 8) ? 8 : 0;

    float acc[2][4][4] = {};
    uint2 rAb[4], rAs[4], rBb[2], rBs[2];

    auto load_tiles = [&](int k0) {
        const uint2* pa = (const uint2*)(Ab + (size_t)(m0 + ar) * K + k0 + akh);
        const uint2* ps = (const uint2*)(As2 + (size_t)(m0 + ar) * K + k0 + akh);
#pragma unroll
        for (int i = 0; i < 4; i++) { rAb[i] = pa[i]; rAs[i] = ps[i]; }
        const uint2* qb = (const uint2*)(Bb + (size_t)(n0 + bn) * K + k0 + bkq);
        const uint2* qs = (const uint2*)(Bs2 + (size_t)(n0 + bn) * K + k0 + bkq);
#pragma unroll
        for (int i = 0; i < 2; i++) { rBb[i] = qb[i]; rBs[i] = qs[i]; }
    };
    auto store_tiles = [&](int buf) {
#pragma unroll
        for (int i = 0; i < 4; i++) {
            *reinterpret_cast<uint2*>(&ASB(buf, ar, akh + i * 4)) = rAb[i];
            *reinterpret_cast<uint2*>(&ASS(buf, ar, akh + i * 4)) = rAs[i];
        }
#pragma unroll
        for (int i = 0; i < 2; i++) {
            *reinterpret_cast<uint2*>(&BSB(buf, bn, bkq + i * 4)) = rBb[i];
            *reinterpret_cast<uint2*>(&BSS(buf, bn, bkq + i * 4)) = rBs[i];
        }
    };

    load_tiles(0);
    int buf = 0;
    for (int k0 = 0; k0 < K; k0 += 32) {
        store_tiles(buf);
        __syncthreads();
        if (k0 + 32 < K) load_tiles(k0 + 32);
#pragma unroll
        for (int kk = 0; kk < 32; kk += 16) {
            unsigned ab[2][4], as_[2][4], bb[4][2], bs_[4][2];
#pragma unroll
            for (int am = 0; am < 2; am++) {
                ldsm_x4(ab[am][0], ab[am][1], ab[am][2], ab[am][3],
                        &ASB(buf, arow + am * 16, kk + acolsel));
                ldsm_x4(as_[am][0], as_[am][1], as_[am][2], as_[am][3],
                        &ASS(buf, arow + am * 16, kk + acolsel));
            }
#pragma unroll
            for (int p = 0; p < 2; p++) {
                ldsm_x4(bb[2 * p][0], bb[2 * p][1], bb[2 * p + 1][0], bb[2 * p + 1][1],
                        &BSB(buf, brow + p * 16, kk + bcolsel));
                ldsm_x4(bs_[2 * p][0], bs_[2 * p][1], bs_[2 * p + 1][0], bs_[2 * p + 1][1],
                        &BSS(buf, brow + p * 16, kk + bcolsel));
            }
#pragma unroll
            for (int am = 0; am < 2; am++)
#pragma unroll
                for (int an = 0; an < 4; an++) {
                    mma16816(acc[am][an], ab[am], bb[an]);
                    mma16816(acc[am][an], ab[am], bs_[an]);
                    mma16816(acc[am][an], as_[am], bb[an]);
                }
        }
        buf ^= 1;
        __syncthreads();
    }

#pragma unroll
    for (int am = 0; am < 2; am++) {
#pragma unroll
        for (int rr = 0; rr < 2; rr++) {
            int row = m0 + wm * 32 + am * 16 + g + rr * 8;
#pragma unroll
            for (int an = 0; an < 4; an++) {
                int col0 = n0 + wn * 32 + an * 8 + 2 * tig;
                if constexpr (MODE == 0) {
                    float v0 = (acc[am][an][rr * 2 + 0] + bias[col0]) * alpha;
                    float v1 = (acc[am][an][rr * 2 + 1] + bias[col0 + 1]) * alpha;
                    if (relu) { v0 = fmaxf(v0, 0.f); v1 = fmaxf(v1, 0.f); }
                    if (outf) {
                        outf[(size_t)row * N + col0] = v0;
                        outf[(size_t)row * N + col0 + 1] = v1;
                    }
                    if (outb) {
                        unsigned ub, us;
                        cvt2(v0, v1, ub, us);
                        *reinterpret_cast<unsigned*>(&outb[(size_t)row * N + col0]) = ub;
                        *reinterpret_cast<unsigned*>(&outs[(size_t)row * N + col0]) = us;
                    }
                } else {  // MODE 3
                    int bb2 = row >> 10, tt = row & (T - 1);
                    float mk = (tt < lens[bb2]) ? 1.0f : 0.0f;
#pragma unroll
                    for (int cc = 0; cc < 2; cc++) {
                        int col = col0 + cc;
                        float vv = (acc[am][an][rr * 2 + cc] + bias[col]) * mk;
                        if (col < OUT)
                            outf[((size_t)bb2 * OUT + col) * T + tt] = vv;
                        else
                            out2[((size_t)bb2 * OUT + (col - OUT)) * T + tt] = vv;
                    }
                }
            }
        }
    }
#undef ASB
#undef ASS
#undef BSB
#undef BSS
}

// =====================================================================
//  Flash attention: per (b,h,128-q-tile). QK^T + rel_k band + mask +
//  online softmax + P@V (bf16x3) + rel_v band. Writes attn out pair.
// =====================================================================
constexpr int QPITCH = 72;
constexpr int FLASH_SMEM = (2 * 128 * QPITCH + 4 * 64 * QPITCH) * (int)sizeof(bf16);  // 73728

__global__ __launch_bounds__(256, 1) void flash_attn(
    const int* __restrict__ lens, const float* __restrict__ relk,
    const float* __restrict__ relv) {
    extern __shared__ bf16 fsm[];
    bf16* Qb = fsm;                 // [128][72]
    bf16* Qs = fsm + 9216;
    bf16* Kb = fsm + 18432;         // [64][72]
    bf16* Ks = fsm + 23040;
    bf16* Vb = fsm + 27648;         // [64][72] transposed: [c][k]
    bf16* Vs = fsm + 32256;
    __shared__ float qrel_s[128 * NREL];
    __shared__ float relk_s[NREL * HD];
    __shared__ float relv_s[NREL * HD];

    const int tid = threadIdx.x, lane = tid & 31, w = tid >> 5;
    const int g = lane >> 2, tig = lane & 3;
    const unsigned qm = 0xFu << (lane & 28);
    const int m0 = blockIdx.x * 128;
    const int bh = blockIdx.y, b = bh >> 2, h = bh & 3;
    const int len = lens[b];

    // ---- load Q tile pair ----
    {
        int row = tid >> 1, half = (tid & 1) * 32;
        const uint2* sb = (const uint2*)(g_qb + ((size_t)(b * T + m0 + row)) * C + h * HD + half);
        const uint2* ss = (const uint2*)(g_qs + ((size_t)(b * T + m0 + row)) * C + h * HD + half);
        uint2* db = (uint2*)(Qb + row * QPITCH + half);
        uint2* ds = (uint2*)(Qs + row * QPITCH + half);
#pragma unroll
        for (int i = 0; i < 8; i++) { db[i] = sb[i]; ds[i] = ss[i]; }
    }
    for (int i = tid; i < NREL * HD; i += 256) { relk_s[i] = relk[i]; relv_s[i] = relv[i]; }
    __syncthreads();

    // ---- qrel[r][d] = q[r] . rel_k[d] ----
    for (int i = tid; i < 128 * NREL; i += 256) {
        int r = i / NREL, d = i % NREL;
        const bf16* qb = Qb + r * QPITCH;
        const bf16* qs = Qs + r * QPITCH;
        float s = 0.f;
#pragma unroll
        for (int c = 0; c < HD; c++)
            s += (__bfloat162float(qb[c]) + __bfloat162float(qs[c])) * relk_s[d * HD + c];
        qrel_s[i] = s;
    }

    // ---- preload Q fragments (warp w owns rows w*16..w*16+15) ----
    const int arow = w * 16 + (lane & 7) + ((lane & 8) ? 8 : 0);
    const int acolsel = (lane & 16) ? 8 : 0;
    const int brow = (lane & 7) + ((lane & 16) ? 8 : 0);
    const int bcolsel = (lane & 8) ? 8 : 0;
    unsigned qfb[4][4], qfs[4][4];
#pragma unroll
    for (int s2 = 0; s2 < 4; s2++) {
        ldsm_x4(qfb[s2][0], qfb[s2][1], qfb[s2][2], qfb[s2][3],
                Qb + arow * QPITCH + s2 * 16 + acolsel);
        ldsm_x4(qfs[s2][0], qfs[s2][1], qfs[s2][2], qfs[s2][3],
                Qs + arow * QPITCH + s2 * 16 + acolsel);
    }

    float oacc[8][4] = {};
    float mrow[2] = {-1e30f, -1e30f}, lrow[2] = {0.f, 0.f};

    for (int k0 = 0; k0 < len; k0 += 64) {
        // ---- load K tile ----
        {
            int kr = tid >> 2, cq = (tid & 3) * 16;
            const uint2* sb = (const uint2*)(g_kb + ((size_t)(b * T + k0 + kr)) * C + h * HD + cq);
            const uint2* ss = (const uint2*)(g_ks + ((size_t)(b * T + k0 + kr)) * C + h * HD + cq);
            uint2* db = (uint2*)(Kb + kr * QPITCH + cq);
            uint2* ds = (uint2*)(Ks + kr * QPITCH + cq);
#pragma unroll
            for (int i = 0; i < 4; i++) { db[i] = sb[i]; ds[i] = ss[i]; }
            // ---- V tile transposed ----
            int kv = tid & 63, c0 = (tid >> 6) * 16;
            const uint2* vb4 = (const uint2*)(g_vb + ((size_t)(b * T + k0 + kv)) * C + h * HD + c0);
            const uint2* vs4 = (const uint2*)(g_vs + ((size_t)(b * T + k0 + kv)) * C + h * HD + c0);
#pragma unroll
            for (int i = 0; i < 4; i++) {
                union U { uint2 u; bf16 hh[4]; } ub, us;
                ub.u = vb4[i];
                us.u = vs4[i];
#pragma unroll
                for (int j = 0; j < 4; j++) {
                    Vb[(c0 + i * 4 + j) * QPITCH + kv] = ub.hh[j];
                    Vs[(c0 + i * 4 + j) * QPITCH + kv] = us.hh[j];
                }
            }
        }
        __syncthreads();

        // ---- S = Q K^T (bf16x3) ----
        float sacc[8][4] = {};
#pragma unroll
        for (int s2 = 0; s2 < 4; s2++) {
            unsigned kb[8][2], km[8][2];
#pragma unroll
            for (int p = 0; p < 4; p++) {
                ldsm_x4(kb[2 * p][0], kb[2 * p][1], kb[2 * p + 1][0], kb[2 * p + 1][1],
                        Kb + (p * 16 + brow) * QPITCH + s2 * 16 + bcolsel);
                ldsm_x4(km[2 * p][0], km[2 * p][1], km[2 * p + 1][0], km[2 * p + 1][1],
                        Ks + (p * 16 + brow) * QPITCH + s2 * 16 + bcolsel);
            }
#pragma unroll
            for (int an = 0; an < 8; an++) {
                mma16816(sacc[an], qfb[s2], kb[an]);
                mma16816(sacc[an], qfb[s2], km[an]);
                mma16816(sacc[an], qfs[s2], kb[an]);
            }
        }

        // ---- bias + mask ----
#pragma unroll
        for (int rr = 0; rr < 2; rr++) {
            int lr = w * 16 + g + rr * 8;
            int qg = m0 + lr;
#pragma unroll
            for (int an = 0; an < 8; an++) {
#pragma unroll
                for (int cc = 0; cc < 2; cc++) {
                    int col = k0 + an * 8 + 2 * tig + cc;
                    float s = sacc[an][rr * 2 + cc];
                    int d = col - qg;
                    if (d >= -4 && d <= 4) s += qrel_s[lr * NREL + d + 4];
                    if (col >= len) s = -1e30f;
                    sacc[an][rr * 2 + cc] = s;
                }
            }
        }

        // ---- online softmax ----
#pragma unroll
        for (int rr = 0; rr < 2; rr++) {
            float mx = -1e30f;
#pragma unroll
            for (int an = 0; an < 8; an++) {
                mx = fmaxf(mx, sacc[an][rr * 2 + 0]);
                mx = fmaxf(mx, sacc[an][rr * 2 + 1]);
            }
            mx = fmaxf(mx, __shfl_xor_sync(qm, mx, 1));
            mx = fmaxf(mx, __shfl_xor_sync(qm, mx, 2));
            float mnew = fmaxf(mrow[rr], mx);
            float corr = __expf(mrow[rr] - mnew);
            mrow[rr] = mnew;
            float rs = 0.f;
#pragma unroll
            for (int an = 0; an < 8; an++) {
#pragma unroll
                for (int cc = 0; cc < 2; cc++) {
                    float p = __expf(sacc[an][rr * 2 + cc] - mnew);
                    sacc[an][rr * 2 + cc] = p;
                    rs += p;
                }
            }
            lrow[rr] = lrow[rr] * corr + rs;
#pragma unroll
            for (int an = 0; an < 8; an++) {
                oacc[an][rr * 2 + 0] *= corr;
                oacc[an][rr * 2 + 1] *= corr;
            }
        }

        // ---- P -> A fragments (big + small) ----
        unsigned pfb[4][4], pfs[4][4];
#pragma unroll
        for (int s2 = 0; s2 < 4; s2++) {
            cvt2(sacc[2 * s2][0], sacc[2 * s2][1], pfb[s2][0], pfs[s2][0]);
            cvt2(sacc[2 * s2][2], sacc[2 * s2][3], pfb[s2][1], pfs[s2][1]);
            cvt2(sacc[2 * s2 + 1][0], sacc[2 * s2 + 1][1], pfb[s2][2], pfs[s2][2]);
            cvt2(sacc[2 * s2 + 1][2], sacc[2 * s2 + 1][3], pfb[s2][3], pfs[s2][3]);
        }

        // ---- O += P V ----
#pragma unroll
        for (int s2 = 0; s2 < 4; s2++) {
            unsigned vb[8][2], vs2[8][2];
#pragma unroll
            for (int p = 0; p < 4; p++) {
                ldsm_x4(vb[2 * p][0], vb[2 * p][1], vb[2 * p + 1][0], vb[2 * p + 1][1],
                        Vb + (p * 16 + brow) * QPITCH + s2 * 16 + bcolsel);
                ldsm_x4(vs2[2 * p][0], vs2[2 * p][1], vs2[2 * p + 1][0], vs2[2 * p + 1][1],
                        Vs + (p * 16 + brow) * QPITCH + s2 * 16 + bcolsel);
            }
#pragma unroll
            for (int an = 0; an < 8; an++) {
                mma16816(oacc[an], pfb[s2], vb[an]);
                mma16816(oacc[an], pfb[s2], vs2[an]);
                mma16816(oacc[an], pfs[s2], vb[an]);
            }
        }
        __syncthreads();
    }

    // ---- finalize: 1/l, band, write ----
    float linv[2];
#pragma unroll
    for (int rr = 0; rr < 2; rr++) {
        float lv = lrow[rr];
        lv += __shfl_xor_sync(qm, lv, 1);
        lv += __shfl_xor_sync(qm, lv, 2);
        linv[rr] = 1.0f / lv;
#pragma unroll
        for (int an = 0; an < 8; an++) {
            oacc[an][rr * 2 + 0] *= linv[rr];
            oacc[an][rr * 2 + 1] *= linv[rr];
        }
    }

#pragma unroll
    for (int rr = 0; rr < 2; rr++) {
        int lr = w * 16 + g + rr * 8;
        int qg = m0 + lr;
#pragma unroll
        for (int j = 0; j < NREL; j++) {
            int k = qg + j - 4;
            if (k < 0 || k >= len) continue;  // uniform across quad
            const bf16* kbp = g_kb + ((size_t)(b * T + k)) * C + h * HD;
            const bf16* ksp = g_ks + ((size_t)(b * T + k)) * C + h * HD;
            float part = 0.f;
#pragma unroll
            for (int c = tig * 16; c < tig * 16 + 16; c++) {
                float qv = __bfloat162float(Qb[lr * QPITCH + c]) +
                           __bfloat162float(Qs[lr * QPITCH + c]);
                float kv = __bfloat162float(kbp[c]) + __bfloat162float(ksp[c]);
                part += qv * kv;
            }
            part += __shfl_xor_sync(qm, part, 1);
            part += __shfl_xor_sync(qm, part, 2);
            float p = __expf(part + qrel_s[lr * NREL + j] - mrow[rr]) * linv[rr];
#pragma unroll
            for (int an = 0; an < 8; an++) {
                int c0 = an * 8 + 2 * tig;
                oacc[an][rr * 2 + 0] += p * relv_s[j * HD + c0];
                oacc[an][rr * 2 + 1] += p * relv_s[j * HD + c0 + 1];
            }
        }
        // write pair
#pragma unroll
        for (int an = 0; an < 8; an++) {
            int c0 = an * 8 + 2 * tig;
            unsigned ub, us;
            cvt2(oacc[an][rr * 2 + 0], oacc[an][rr * 2 + 1], ub, us);
            size_t o = ((size_t)(b * T + qg)) * C + h * HD + c0;
            *reinterpret_cast<unsigned*>(&g_ab[o]) = ub;
            *reinterpret_cast<unsigned*>(&g_as[o]) = us;
        }
    }
}

// ---------------- x = LN(x + r)*g + b, write fp32 + pair ----------------
__global__ void ln_res_kernel(float* __restrict__ x, const float* __restrict__ r,
                              const float* __restrict__ gg, const float* __restrict__ beta,
                              const int* __restrict__ lens, int apply_mask) {
    int row = blockIdx.x;
    int c = threadIdx.x;
    size_t idx = (size_t)row * C + c;
    float val = x[idx] + r[idx];
    float mean = blockReduceSum256(val) * (1.0f / C);
    float d = val - mean;
    float var = blockReduceSum256(d * d) * (1.0f / C);
    float y = d * rsqrtf(var + 1e-5f) * gg[c] + beta[c];
    if (apply_mask) {
        int b = row >> 10, t = row & (T - 1);
        if (t >= lens[b]) y = 0.0f;
    }
    x[idx] = y;
    bf16 hb = __float2bfloat16_rn(y);
    g_xb[idx] = hb;
    g_xs[idx] = __float2bfloat16_rn(y - __bfloat162float(hb));
}

// ---------------- x (B,T,C) -> out (B,C,T) ----------------
__global__ void transpose_kernel(const float* __restrict__ x, float* __restrict__ out) {
    __shared__ float tile[32][33];
    int b = blockIdx.z;
    int t0 = blockIdx.x * 32, c0 = blockIdx.y * 32;
    int tx = threadIdx.x, ty = threadIdx.y;
#pragma unroll
    for (int i = 0; i < 32; i += 8)
        tile[ty + i][tx] = x[(size_t)(b * T + t0 + ty + i) * C + c0 + tx];
    __syncthreads();
#pragma unroll
    for (int i = 0; i < 32; i += 8)
        out[(size_t)(b * C + c0 + ty + i) * T + t0 + tx] = tile[tx][ty + i];
}

__global__ void mask_out_kernel(const int* __restrict__ lens, float* __restrict__ out_mask) {
    int b = blockIdx.x;
    int len = lens[b];
    for (int t = threadIdx.x; t < T; t += blockDim.x)
        out_mask[(size_t)b * T + t] = (t < len) ? 1.0f : 0.0f;
}

}  // namespace

extern "C" void kernel_launch(void* const* d_in, const int* in_sizes, int n_in,
                              void* d_out, int out_size) {
    (void)in_sizes; (void)n_in; (void)out_size;
    const float* emb   = (const float*)d_in[0];
    const float* Wq    = (const float*)d_in[1];
    const float* Wk    = (const float*)d_in[2];
    const float* Wv    = (const float*)d_in[3];
    const float* Wo    = (const float*)d_in[4];
    const float* bq    = (const float*)d_in[5];
    const float* bk    = (const float*)d_in[6];
    const float* bv    = (const float*)d_in[7];
    const float* bo    = (const float*)d_in[8];
    const float* rel_k = (const float*)d_in[9];
    const float* rel_v = (const float*)d_in[10];
    const float* ln1_g = (const float*)d_in[11];
    const float* ln1_b = (const float*)d_in[12];
    const float* ln2_g = (const float*)d_in[13];
    const float* ln2_b = (const float*)d_in[14];
    const float* fw1   = (const float*)d_in[15];
    const float* fb1   = (const float*)d_in[16];
    const float* fw2   = (const float*)d_in[17];
    const float* fb2   = (const float*)d_in[18];
    const float* pw    = (const float*)d_in[19];
    const float* pb    = (const float*)d_in[20];
    const int*   toks  = (const int*)d_in[21];
    const int*   lens  = (const int*)d_in[22];

    cudaFuncSetAttribute(mma_gemm_p<0>, cudaFuncAttributeMaxDynamicSharedMemorySize, SMEM_BYTES);
    cudaFuncSetAttribute(mma_gemm_p<3>, cudaFuncAttributeMaxDynamicSharedMemorySize, SMEM_BYTES);
    cudaFuncSetAttribute(flash_attn, cudaFuncAttributeMaxDynamicSharedMemorySize, FLASH_SMEM);

    float *px, *ptmp;
    bf16 *pwb, *pws;
    bf16 *pxb, *pxs, *pqb, *pqs, *pkb, *pks, *pvbb, *pvss, *pab, *pas, *pfb, *pfs;
    cudaGetSymbolAddress((void**)&px,   g_x);
    cudaGetSymbolAddress((void**)&ptmp, g_tmp);
    cudaGetSymbolAddress((void**)&pwb,  g_wb);
    cudaGetSymbolAddress((void**)&pws,  g_ws);
    cudaGetSymbolAddress((void**)&pxb,  g_xb);
    cudaGetSymbolAddress((void**)&pxs,  g_xs);
    cudaGetSymbolAddress((void**)&pqb,  g_qb);
    cudaGetSymbolAddress((void**)&pqs,  g_qs);
    cudaGetSymbolAddress((void**)&pkb,  g_kb);
    cudaGetSymbolAddress((void**)&pks,  g_ks);
    cudaGetSymbolAddress((void**)&pvbb, g_vb);
    cudaGetSymbolAddress((void**)&pvss, g_vs);
    cudaGetSymbolAddress((void**)&pab,  g_ab);
    cudaGetSymbolAddress((void**)&pas,  g_as);
    cudaGetSymbolAddress((void**)&pfb,  g_fb);
    cudaGetSymbolAddress((void**)&pfs,  g_fs);

    float* out      = (float*)d_out;
    float* out_x    = out;
    float* out_m    = out + (size_t)B * C * T;
    float* out_logs = out_m + (size_t)B * OUT * T;
    float* out_mask = out_logs + (size_t)B * OUT * T;

    // ---- weight conversion (pairs, [N][K] layout) ----
    dim3 wcb(32, 8);
    wconv_t<<<dim3(C / 32, C / 32, L), wcb>>>(Wq, pwb + OFF_WQ, pws + OFF_WQ, C, C);
    wconv_t<<<dim3(C / 32, C / 32, L), wcb>>>(Wk, pwb + OFF_WK, pws + OFF_WK, C, C);
    wconv_t<<<dim3(C / 32, C / 32, L), wcb>>>(Wv, pwb + OFF_WV, pws + OFF_WV, C, C);
    wconv_t<<<dim3(C / 32, C / 32, L), wcb>>>(Wo, pwb + OFF_WO, pws + OFF_WO, C, C);
    wconv_t<<<dim3(FC / 32, C / 32, L), wcb>>>(fw1, pwb + OFF_F1, pws + OFF_F1, C, FC);
    wconv_t<<<dim3(C / 32, FC / 32, L), wcb>>>(fw2, pwb + OFF_F2, pws + OFF_F2, FC, C);
    projconv<<<(2 * OUT * C + 255) / 256, 256>>>(pw);

    embed_kernel<<<BT, C>>>(emb, toks);

    dim3 gC(C / 64, BT / 128);    // 4 x 64
    dim3 gFC(FC / 64, BT / 128);  // 16 x 64

    for (int l = 0; l < L; l++) {
        size_t wq = OFF_WQ + (size_t)l * C * C;
        size_t wk = OFF_WK + (size_t)l * C * C;
        size_t wv = OFF_WV + (size_t)l * C * C;
        size_t wo = OFF_WO + (size_t)l * C * C;
        size_t f1 = OFF_F1 + (size_t)l * C * FC;
        size_t f2 = OFF_F2 + (size_t)l * FC * C;

        mma_gemm_p<0><<<gC, 256, SMEM_BYTES>>>(pxb, pxs, pwb + wq, pws + wq, bq + (size_t)l * C,
                                               nullptr, pqb, pqs, nullptr, BT, C, C, 0.125f, 0,
                                               nullptr);
        mma_gemm_p<0><<<gC, 256, SMEM_BYTES>>>(pxb, pxs, pwb + wk, pws + wk, bk + (size_t)l * C,
                                               nullptr, pkb, pks, nullptr, BT, C, C, 1.0f, 0,
                                               nullptr);
        mma_gemm_p<0><<<gC, 256, SMEM_BYTES>>>(pxb, pxs, pwb + wv, pws + wv, bv + (size_t)l * C,
                                               nullptr, pvbb, pvss, nullptr, BT, C, C, 1.0f, 0,
                                               nullptr);

        flash_attn<<<dim3(T / 128, B * H), 256, FLASH_SMEM>>>(
            lens, rel_k + (size_t)l * NREL * HD, rel_v + (size_t)l * NREL * HD);

        mma_gemm_p<0><<<gC, 256, SMEM_BYTES>>>(pab, pas, pwb + wo, pws + wo, bo + (size_t)l * C,
                                               ptmp, nullptr, nullptr, nullptr, BT, C, C, 1.0f,
                                               0, nullptr);
        ln_res_kernel<<<BT, C>>>(px, ptmp, ln1_g + (size_t)l * C, ln1_b + (size_t)l * C, lens, 0);

        mma_gemm_p<0><<<gFC, 256, SMEM_BYTES>>>(pxb, pxs, pwb + f1, pws + f1,
                                                fb1 + (size_t)l * FC, nullptr, pfb, pfs, nullptr,
                                                BT, FC, C, 1.0f, 1, nullptr);
        mma_gemm_p<0><<<gC, 256, SMEM_BYTES>>>(pfb, pfs, pwb + f2, pws + f2, fb2 + (size_t)l * C,
                                               ptmp, nullptr, nullptr, nullptr, BT, C, FC, 1.0f,
                                               0, nullptr);
        ln_res_kernel<<<BT, C>>>(px, ptmp, ln2_g + (size_t)l * C, ln2_b + (size_t)l * C, lens, 1);
    }

    transpose_kernel<<<dim3(T / 32, C / 32, B), dim3(32, 8)>>>(px, out_x);
    mma_gemm_p<3><<<dim3(2 * OUT / 64, BT / 128), 256, SMEM_BYTES>>>(
        pxb, pxs, pwb + OFF_PJ, pws + OFF_PJ, pb, out_m, nullptr, nullptr, out_logs, BT,
        2 * OUT, C, 1.0f, 0, lens);
    mask_out_kernel<<<B, 256>>>(lens, out_mask);
}

// round 6
// speedup vs baseline: 1.8992x; 1.0892x over previous
#include <cuda_runtime.h>
#include <cuda_bf16.h>
#include <math.h>

namespace {

constexpr int C = 256, H = 4, HD = 64, L = 6, FC = 1024, OUT = 192;
constexpr int B = 8, T = 1024, BT = B * T, NREL = 9;

typedef __nv_bfloat16 bf16;

// ---------------- weight pair storage (QKV concatenated per layer) ----------------
constexpr size_t OFF_QKV = 0;                                   // [L][3C][C]
constexpr size_t OFF_WO  = (size_t)L * 3 * C * C;               // [L][C][C]
constexpr size_t OFF_F1  = OFF_WO + (size_t)L * C * C;          // [L][FC][C]
constexpr size_t OFF_F2  = OFF_F1 + (size_t)L * C * FC;         // [L][C][FC]
constexpr size_t OFF_PJ  = OFF_F2 + (size_t)L * FC * C;         // [2*OUT][C]
constexpr size_t WTOT    = OFF_PJ + (size_t)2 * OUT * C;

__device__ bf16 g_wb[WTOT];
__device__ bf16 g_ws[WTOT];

// ---------------- activation scratch ----------------
__device__ float g_x[BT * C];
__device__ float g_tmp[BT * C];
__device__ bf16 g_xb[BT * C], g_xs[BT * C];
__device__ bf16 g_qb[BT * C], g_qs[BT * C];
__device__ bf16 g_kb[BT * C], g_ks[BT * C];
__device__ bf16 g_vb[BT * C], g_vs[BT * C];
__device__ bf16 g_ab[BT * C], g_as[BT * C];
__device__ bf16 g_fb[BT * FC], g_fs[BT * FC];

// ---------------- helpers ----------------
__device__ __forceinline__ float warpReduceSum(float v) {
#pragma unroll
    for (int o = 16; o; o >>= 1) v += __shfl_xor_sync(0xffffffffu, v, o);
    return v;
}
__device__ __forceinline__ float blockReduceSum256(float v) {
    __shared__ float s[8];
    int lane = threadIdx.x & 31, w = threadIdx.x >> 5;
    v = warpReduceSum(v);
    if (lane == 0) s[w] = v;
    __syncthreads();
    float tot = 0.f;
#pragma unroll
    for (int i = 0; i < 8; i++) tot += s[i];
    __syncthreads();
    return tot;
}

__device__ __forceinline__ void cvt2(float a, float b, unsigned& ub, unsigned& us) {
    __nv_bfloat162 hb, hs;
    hb.x = __float2bfloat16_rn(a);
    hb.y = __float2bfloat16_rn(b);
    float ra = a - __bfloat162float(hb.x);
    float rb = b - __bfloat162float(hb.y);
    hs.x = __float2bfloat16_rn(ra);
    hs.y = __float2bfloat16_rn(rb);
    ub = *reinterpret_cast<unsigned*>(&hb);
    us = *reinterpret_cast<unsigned*>(&hs);
}

__device__ __forceinline__ void mma16816(float c[4], const unsigned a[4], const unsigned b2[2]) {
    asm volatile(
        "mma.sync.aligned.m16n8k16.row.col.f32.bf16.bf16.f32 "
        "{%0,%1,%2,%3}, {%4,%5,%6,%7}, {%8,%9}, {%0,%1,%2,%3};\n"
        : "+f"(c[0]), "+f"(c[1]), "+f"(c[2]), "+f"(c[3])
        : "r"(a[0]), "r"(a[1]), "r"(a[2]), "r"(a[3]), "r"(b2[0]), "r"(b2[1]));
}

__device__ __forceinline__ void ldsm_x4(unsigned& r0, unsigned& r1, unsigned& r2, unsigned& r3,
                                        const void* p) {
    unsigned addr = (unsigned)__cvta_generic_to_shared(p);
    asm volatile("ldmatrix.sync.aligned.m8n8.x4.shared.b16 {%0,%1,%2,%3}, [%4];"
                 : "=r"(r0), "=r"(r1), "=r"(r2), "=r"(r3)
                 : "r"(addr));
}

// ---------------- weight conversion: W [Lz][K][N] fp32 -> pair [Lz(lstride)][N][K] ----------------
__global__ void wconv_t(const float* __restrict__ w, bf16* __restrict__ ob,
                        bf16* __restrict__ os, int K, int N, size_t lstride) {
    __shared__ float tile[32][33];
    int l = blockIdx.z;
    const float* src = w + (size_t)l * K * N;
    int k0 = blockIdx.y * 32, n0 = blockIdx.x * 32;
    int tx = threadIdx.x, ty = threadIdx.y;
#pragma unroll
    for (int i = 0; i < 32; i += 8)
        tile[ty + i][tx] = src[(size_t)(k0 + ty + i) * N + n0 + tx];
    __syncthreads();
#pragma unroll
    for (int i = 0; i < 32; i += 8) {
        float v = tile[tx][ty + i];
        size_t o = (size_t)l * lstride + (size_t)(n0 + ty + i) * K + k0 + tx;
        bf16 hb = __float2bfloat16_rn(v);
        ob[o] = hb;
        os[o] = __float2bfloat16_rn(v - __bfloat162float(hb));
    }
}

__global__ void projconv(const float* __restrict__ pw) {
    int i = blockIdx.x * 256 + threadIdx.x;
    if (i >= 2 * OUT * C) return;
    float v = pw[i];
    bf16 hb = __float2bfloat16_rn(v);
    g_wb[OFF_PJ + i] = hb;
    g_ws[OFF_PJ + i] = __float2bfloat16_rn(v - __bfloat162float(hb));
}

// ---------------- embedding (fp32 + pair) ----------------
__global__ void embed_kernel(const float* __restrict__ emb, const int* __restrict__ tokens) {
    int bt = blockIdx.x;
    int c = threadIdx.x;
    float v = emb[(size_t)tokens[bt] * C + c] * 16.0f;
    size_t idx = (size_t)bt * C + c;
    g_x[idx] = v;
    bf16 hb = __float2bfloat16_rn(v);
    g_xb[idx] = hb;
    g_xs[idx] = __float2bfloat16_rn(v - __bfloat162float(hb));
}

// =====================================================================
//  Pair-input bf16x3 GEMM: 128x128 tile, BK=32, 256 threads, dbl-buffered.
//  8 warps (4 M x 2 N), warp tile 32x64. 48 MMA per 12 LDSM.x4 per k16.
//  MODE 0: linear (fp32 out and/or pair out, bias, alpha, relu)
//  MODE 1: fused QKV (N=768, per-block target; writes q/k/v pairs)
//  MODE 3: stats split masked
// =====================================================================
constexpr int APITCH = 40;
constexpr int TSZ = 128 * APITCH;  // one tile buffer (A or B), per big/small, per stage
constexpr int SMEM_BYTES = 8 * TSZ * (int)sizeof(bf16);  // 81920

template <int MODE>
__global__ __launch_bounds__(256, 1) void mma_gemm_p(
    const bf16* __restrict__ Ab, const bf16* __restrict__ As2,
    const bf16* __restrict__ Bb, const bf16* __restrict__ Bs2,
    const float* __restrict__ bias, const float* __restrict__ bias2,
    const float* __restrict__ bias3, float* __restrict__ outf,
    bf16* __restrict__ outb, bf16* __restrict__ outs, float* __restrict__ out2,
    int M, int N, int K, float alpha, int relu, const int* __restrict__ lens) {
    extern __shared__ bf16 dsm[];
    bf16* As_b = dsm;
    bf16* As_s = dsm + 2 * TSZ;
    bf16* Bs_b = dsm + 4 * TSZ;
    bf16* Bs_s = dsm + 6 * TSZ;

#define ASB(bf_, r, c) As_b[(bf_)*TSZ + (r)*APITCH + (c)]
#define ASS(bf_, r, c) As_s[(bf_)*TSZ + (r)*APITCH + (c)]
#define BSB(bf_, r, c) Bs_b[(bf_)*TSZ + (r)*APITCH + (c)]
#define BSS(bf_, r, c) Bs_s[(bf_)*TSZ + (r)*APITCH + (c)]

    const int tid = threadIdx.x;
    const int lane = tid & 31, wid = tid >> 5;
    const int wm = wid >> 1, wn = wid & 1;
    const int g = lane >> 2, tig = lane & 3;
    const int m0 = blockIdx.y * 128, n0 = blockIdx.x * 128;

    const int ar = tid >> 1, akh = (tid & 1) * 16;

    const int lane7 = lane & 7;
    const int arow = wm * 32 + lane7 + ((lane & 8) ? 8 : 0);
    const int acolsel = (lane & 16) ? 8 : 0;
    const int brow = lane7 + ((lane & 16) ? 8 : 0);
    const int bcolsel = (lane & 8) ? 8 : 0;

    float acc[2][8][4] = {};
    uint2 rAb[4], rAs[4], rBb[4], rBs[4];

    auto load_tiles = [&](int k0) {
        const uint2* pa = (const uint2*)(Ab + (size_t)(m0 + ar) * K + k0 + akh);
        const uint2* ps = (const uint2*)(As2 + (size_t)(m0 + ar) * K + k0 + akh);
        const uint2* qb = (const uint2*)(Bb + (size_t)(n0 + ar) * K + k0 + akh);
        const uint2* qs = (const uint2*)(Bs2 + (size_t)(n0 + ar) * K + k0 + akh);
#pragma unroll
        for (int i = 0; i < 4; i++) {
            rAb[i] = pa[i];
            rAs[i] = ps[i];
            rBb[i] = qb[i];
            rBs[i] = qs[i];
        }
    };
    auto store_tiles = [&](int buf) {
#pragma unroll
        for (int i = 0; i < 4; i++) {
            *reinterpret_cast<uint2*>(&ASB(buf, ar, akh + i * 4)) = rAb[i];
            *reinterpret_cast<uint2*>(&ASS(buf, ar, akh + i * 4)) = rAs[i];
            *reinterpret_cast<uint2*>(&BSB(buf, ar, akh + i * 4)) = rBb[i];
            *reinterpret_cast<uint2*>(&BSS(buf, ar, akh + i * 4)) = rBs[i];
        }
    };

    load_tiles(0);
    int buf = 0;
    for (int k0 = 0; k0 < K; k0 += 32) {
        store_tiles(buf);
        __syncthreads();
        if (k0 + 32 < K) load_tiles(k0 + 32);
#pragma unroll
        for (int kk = 0; kk < 32; kk += 16) {
            unsigned ab[2][4], as_[2][4], bb[8][2], bs_[8][2];
#pragma unroll
            for (int am = 0; am < 2; am++) {
                ldsm_x4(ab[am][0], ab[am][1], ab[am][2], ab[am][3],
                        &ASB(buf, arow + am * 16, kk + acolsel));
                ldsm_x4(as_[am][0], as_[am][1], as_[am][2], as_[am][3],
                        &ASS(buf, arow + am * 16, kk + acolsel));
            }
#pragma unroll
            for (int p = 0; p < 4; p++) {
                ldsm_x4(bb[2 * p][0], bb[2 * p][1], bb[2 * p + 1][0], bb[2 * p + 1][1],
                        &BSB(buf, wn * 64 + p * 16 + brow, kk + bcolsel));
                ldsm_x4(bs_[2 * p][0], bs_[2 * p][1], bs_[2 * p + 1][0], bs_[2 * p + 1][1],
                        &BSS(buf, wn * 64 + p * 16 + brow, kk + bcolsel));
            }
#pragma unroll
            for (int am = 0; am < 2; am++)
#pragma unroll
                for (int an = 0; an < 8; an++) {
                    mma16816(acc[am][an], ab[am], bb[an]);
                    mma16816(acc[am][an], ab[am], bs_[an]);
                    mma16816(acc[am][an], as_[am], bb[an]);
                }
        }
        buf ^= 1;
        __syncthreads();
    }

    // ---------------- epilogue ----------------
    int tgt = 0;
    const float* biasp = bias;
    bf16* tob = outb;
    bf16* tos = outs;
    float al = alpha;
    if constexpr (MODE == 1) {
        tgt = n0 >> 8;  // 0:q 1:k 2:v (128-col tile never straddles)
        biasp = (tgt == 0) ? bias : (tgt == 1 ? bias2 : bias3);
        tob = (tgt == 0) ? g_qb : (tgt == 1 ? g_kb : g_vb);
        tos = (tgt == 0) ? g_qs : (tgt == 1 ? g_ks : g_vs);
        al = (tgt == 0) ? 0.125f : 1.0f;
    }

#pragma unroll
    for (int am = 0; am < 2; am++) {
#pragma unroll
        for (int rr = 0; rr < 2; rr++) {
            int row = m0 + wm * 32 + am * 16 + g + rr * 8;
#pragma unroll
            for (int an = 0; an < 8; an++) {
                int col0 = n0 + wn * 64 + an * 8 + 2 * tig;
                if constexpr (MODE == 0) {
                    float v0 = (acc[am][an][rr * 2 + 0] + bias[col0]) * alpha;
                    float v1 = (acc[am][an][rr * 2 + 1] + bias[col0 + 1]) * alpha;
                    if (relu) { v0 = fmaxf(v0, 0.f); v1 = fmaxf(v1, 0.f); }
                    if (outf) {
                        outf[(size_t)row * N + col0] = v0;
                        outf[(size_t)row * N + col0 + 1] = v1;
                    }
                    if (outb) {
                        unsigned ub, us;
                        cvt2(v0, v1, ub, us);
                        *reinterpret_cast<unsigned*>(&outb[(size_t)row * N + col0]) = ub;
                        *reinterpret_cast<unsigned*>(&outs[(size_t)row * N + col0]) = us;
                    }
                } else if constexpr (MODE == 1) {
                    int lc = col0 - tgt * 256;
                    float v0 = (acc[am][an][rr * 2 + 0] + biasp[lc]) * al;
                    float v1 = (acc[am][an][rr * 2 + 1] + biasp[lc + 1]) * al;
                    unsigned ub, us;
                    cvt2(v0, v1, ub, us);
                    *reinterpret_cast<unsigned*>(&tob[(size_t)row * C + lc]) = ub;
                    *reinterpret_cast<unsigned*>(&tos[(size_t)row * C + lc]) = us;
                } else {  // MODE 3
                    int bb2 = row >> 10, tt = row & (T - 1);
                    float mk = (tt < lens[bb2]) ? 1.0f : 0.0f;
#pragma unroll
                    for (int cc = 0; cc < 2; cc++) {
                        int col = col0 + cc;
                        float vv = (acc[am][an][rr * 2 + cc] + bias[col]) * mk;
                        if (col < OUT)
                            outf[((size_t)bb2 * OUT + col) * T + tt] = vv;
                        else
                            out2[((size_t)bb2 * OUT + (col - OUT)) * T + tt] = vv;
                    }
                }
            }
        }
    }
#undef ASB
#undef ASS
#undef BSB
#undef BSS
}

// =====================================================================
//  Flash attention (unchanged from R4)
// =====================================================================
constexpr int QPITCH = 72;
constexpr int FLASH_SMEM = (2 * 128 * QPITCH + 4 * 64 * QPITCH) * (int)sizeof(bf16);

__global__ __launch_bounds__(256, 1) void flash_attn(
    const int* __restrict__ lens, const float* __restrict__ relk,
    const float* __restrict__ relv) {
    extern __shared__ bf16 fsm[];
    bf16* Qb = fsm;
    bf16* Qs = fsm + 9216;
    bf16* Kb = fsm + 18432;
    bf16* Ks = fsm + 23040;
    bf16* Vb = fsm + 27648;
    bf16* Vs = fsm + 32256;
    __shared__ float qrel_s[128 * NREL];
    __shared__ float relk_s[NREL * HD];
    __shared__ float relv_s[NREL * HD];

    const int tid = threadIdx.x, lane = tid & 31, w = tid >> 5;
    const int g = lane >> 2, tig = lane & 3;
    const unsigned qm = 0xFu << (lane & 28);
    const int m0 = blockIdx.x * 128;
    const int bh = blockIdx.y, b = bh >> 2, h = bh & 3;
    const int len = lens[b];

    {
        int row = tid >> 1, half = (tid & 1) * 32;
        const uint2* sb = (const uint2*)(g_qb + ((size_t)(b * T + m0 + row)) * C + h * HD + half);
        const uint2* ss = (const uint2*)(g_qs + ((size_t)(b * T + m0 + row)) * C + h * HD + half);
        uint2* db = (uint2*)(Qb + row * QPITCH + half);
        uint2* ds = (uint2*)(Qs + row * QPITCH + half);
#pragma unroll
        for (int i = 0; i < 8; i++) { db[i] = sb[i]; ds[i] = ss[i]; }
    }
    for (int i = tid; i < NREL * HD; i += 256) { relk_s[i] = relk[i]; relv_s[i] = relv[i]; }
    __syncthreads();

    for (int i = tid; i < 128 * NREL; i += 256) {
        int r = i / NREL, d = i % NREL;
        const bf16* qb = Qb + r * QPITCH;
        const bf16* qs = Qs + r * QPITCH;
        float s = 0.f;
#pragma unroll
        for (int c = 0; c < HD; c++)
            s += (__bfloat162float(qb[c]) + __bfloat162float(qs[c])) * relk_s[d * HD + c];
        qrel_s[i] = s;
    }

    const int arow = w * 16 + (lane & 7) + ((lane & 8) ? 8 : 0);
    const int acolsel = (lane & 16) ? 8 : 0;
    const int brow = (lane & 7) + ((lane & 16) ? 8 : 0);
    const int bcolsel = (lane & 8) ? 8 : 0;
    unsigned qfb[4][4], qfs[4][4];
#pragma unroll
    for (int s2 = 0; s2 < 4; s2++) {
        ldsm_x4(qfb[s2][0], qfb[s2][1], qfb[s2][2], qfb[s2][3],
                Qb + arow * QPITCH + s2 * 16 + acolsel);
        ldsm_x4(qfs[s2][0], qfs[s2][1], qfs[s2][2], qfs[s2][3],
                Qs + arow * QPITCH + s2 * 16 + acolsel);
    }

    float oacc[8][4] = {};
    float mrow[2] = {-1e30f, -1e30f}, lrow[2] = {0.f, 0.f};

    for (int k0 = 0; k0 < len; k0 += 64) {
        {
            int kr = tid >> 2, cq = (tid & 3) * 16;
            const uint2* sb = (const uint2*)(g_kb + ((size_t)(b * T + k0 + kr)) * C + h * HD + cq);
            const uint2* ss = (const uint2*)(g_ks + ((size_t)(b * T + k0 + kr)) * C + h * HD + cq);
            uint2* db = (uint2*)(Kb + kr * QPITCH + cq);
            uint2* ds = (uint2*)(Ks + kr * QPITCH + cq);
#pragma unroll
            for (int i = 0; i < 4; i++) { db[i] = sb[i]; ds[i] = ss[i]; }
            int kv = tid & 63, c0 = (tid >> 6) * 16;
            const uint2* vb4 = (const uint2*)(g_vb + ((size_t)(b * T + k0 + kv)) * C + h * HD + c0);
            const uint2* vs4 = (const uint2*)(g_vs + ((size_t)(b * T + k0 + kv)) * C + h * HD + c0);
#pragma unroll
            for (int i = 0; i < 4; i++) {
                union U { uint2 u; bf16 hh[4]; } ub, us;
                ub.u = vb4[i];
                us.u = vs4[i];
#pragma unroll
                for (int j = 0; j < 4; j++) {
                    Vb[(c0 + i * 4 + j) * QPITCH + kv] = ub.hh[j];
                    Vs[(c0 + i * 4 + j) * QPITCH + kv] = us.hh[j];
                }
            }
        }
        __syncthreads();

        float sacc[8][4] = {};
#pragma unroll
        for (int s2 = 0; s2 < 4; s2++) {
            unsigned kb[8][2], km[8][2];
#pragma unroll
            for (int p = 0; p < 4; p++) {
                ldsm_x4(kb[2 * p][0], kb[2 * p][1], kb[2 * p + 1][0], kb[2 * p + 1][1],
                        Kb + (p * 16 + brow) * QPITCH + s2 * 16 + bcolsel);
                ldsm_x4(km[2 * p][0], km[2 * p][1], km[2 * p + 1][0], km[2 * p + 1][1],
                        Ks + (p * 16 + brow) * QPITCH + s2 * 16 + bcolsel);
            }
#pragma unroll
            for (int an = 0; an < 8; an++) {
                mma16816(sacc[an], qfb[s2], kb[an]);
                mma16816(sacc[an], qfb[s2], km[an]);
                mma16816(sacc[an], qfs[s2], kb[an]);
            }
        }

#pragma unroll
        for (int rr = 0; rr < 2; rr++) {
            int lr = w * 16 + g + rr * 8;
            int qg = m0 + lr;
#pragma unroll
            for (int an = 0; an < 8; an++) {
#pragma unroll
                for (int cc = 0; cc < 2; cc++) {
                    int col = k0 + an * 8 + 2 * tig + cc;
                    float s = sacc[an][rr * 2 + cc];
                    int d = col - qg;
                    if (d >= -4 && d <= 4) s += qrel_s[lr * NREL + d + 4];
                    if (col >= len) s = -1e30f;
                    sacc[an][rr * 2 + cc] = s;
                }
            }
        }

#pragma unroll
        for (int rr = 0; rr < 2; rr++) {
            float mx = -1e30f;
#pragma unroll
            for (int an = 0; an < 8; an++) {
                mx = fmaxf(mx, sacc[an][rr * 2 + 0]);
                mx = fmaxf(mx, sacc[an][rr * 2 + 1]);
            }
            mx = fmaxf(mx, __shfl_xor_sync(qm, mx, 1));
            mx = fmaxf(mx, __shfl_xor_sync(qm, mx, 2));
            float mnew = fmaxf(mrow[rr], mx);
            float corr = __expf(mrow[rr] - mnew);
            mrow[rr] = mnew;
            float rs = 0.f;
#pragma unroll
            for (int an = 0; an < 8; an++) {
#pragma unroll
                for (int cc = 0; cc < 2; cc++) {
                    float p = __expf(sacc[an][rr * 2 + cc] - mnew);
                    sacc[an][rr * 2 + cc] = p;
                    rs += p;
                }
            }
            lrow[rr] = lrow[rr] * corr + rs;
#pragma unroll
            for (int an = 0; an < 8; an++) {
                oacc[an][rr * 2 + 0] *= corr;
                oacc[an][rr * 2 + 1] *= corr;
            }
        }

        unsigned pfb[4][4], pfs[4][4];
#pragma unroll
        for (int s2 = 0; s2 < 4; s2++) {
            cvt2(sacc[2 * s2][0], sacc[2 * s2][1], pfb[s2][0], pfs[s2][0]);
            cvt2(sacc[2 * s2][2], sacc[2 * s2][3], pfb[s2][1], pfs[s2][1]);
            cvt2(sacc[2 * s2 + 1][0], sacc[2 * s2 + 1][1], pfb[s2][2], pfs[s2][2]);
            cvt2(sacc[2 * s2 + 1][2], sacc[2 * s2 + 1][3], pfb[s2][3], pfs[s2][3]);
        }

#pragma unroll
        for (int s2 = 0; s2 < 4; s2++) {
            unsigned vb[8][2], vs2[8][2];
#pragma unroll
            for (int p = 0; p < 4; p++) {
                ldsm_x4(vb[2 * p][0], vb[2 * p][1], vb[2 * p + 1][0], vb[2 * p + 1][1],
                        Vb + (p * 16 + brow) * QPITCH + s2 * 16 + bcolsel);
                ldsm_x4(vs2[2 * p][0], vs2[2 * p][1], vs2[2 * p + 1][0], vs2[2 * p + 1][1],
                        Vs + (p * 16 + brow) * QPITCH + s2 * 16 + bcolsel);
            }
#pragma unroll
            for (int an = 0; an < 8; an++) {
                mma16816(oacc[an], pfb[s2], vb[an]);
                mma16816(oacc[an], pfb[s2], vs2[an]);
                mma16816(oacc[an], pfs[s2], vb[an]);
            }
        }
        __syncthreads();
    }

    float linv[2];
#pragma unroll
    for (int rr = 0; rr < 2; rr++) {
        float lv = lrow[rr];
        lv += __shfl_xor_sync(qm, lv, 1);
        lv += __shfl_xor_sync(qm, lv, 2);
        linv[rr] = 1.0f / lv;
#pragma unroll
        for (int an = 0; an < 8; an++) {
            oacc[an][rr * 2 + 0] *= linv[rr];
            oacc[an][rr * 2 + 1] *= linv[rr];
        }
    }

#pragma unroll
    for (int rr = 0; rr < 2; rr++) {
        int lr = w * 16 + g + rr * 8;
        int qg = m0 + lr;
#pragma unroll
        for (int j = 0; j < NREL; j++) {
            int k = qg + j - 4;
            if (k < 0 || k >= len) continue;
            const bf16* kbp = g_kb + ((size_t)(b * T + k)) * C + h * HD;
            const bf16* ksp = g_ks + ((size_t)(b * T + k)) * C + h * HD;
            float part = 0.f;
#pragma unroll
            for (int c = tig * 16; c < tig * 16 + 16; c++) {
                float qv = __bfloat162float(Qb[lr * QPITCH + c]) +
                           __bfloat162float(Qs[lr * QPITCH + c]);
                float kv = __bfloat162float(kbp[c]) + __bfloat162float(ksp[c]);
                part += qv * kv;
            }
            part += __shfl_xor_sync(qm, part, 1);
            part += __shfl_xor_sync(qm, part, 2);
            float p = __expf(part + qrel_s[lr * NREL + j] - mrow[rr]) * linv[rr];
#pragma unroll
            for (int an = 0; an < 8; an++) {
                int c0 = an * 8 + 2 * tig;
                oacc[an][rr * 2 + 0] += p * relv_s[j * HD + c0];
                oacc[an][rr * 2 + 1] += p * relv_s[j * HD + c0 + 1];
            }
        }
#pragma unroll
        for (int an = 0; an < 8; an++) {
            int c0 = an * 8 + 2 * tig;
            unsigned ub, us;
            cvt2(oacc[an][rr * 2 + 0], oacc[an][rr * 2 + 1], ub, us);
            size_t o = ((size_t)(b * T + qg)) * C + h * HD + c0;
            *reinterpret_cast<unsigned*>(&g_ab[o]) = ub;
            *reinterpret_cast<unsigned*>(&g_as[o]) = us;
        }
    }
}

// ---------------- x = LN(x + r)*g + b, write fp32 + pair ----------------
__global__ void ln_res_kernel(float* __restrict__ x, const float* __restrict__ r,
                              const float* __restrict__ gg, const float* __restrict__ beta,
                              const int* __restrict__ lens, int apply_mask) {
    int row = blockIdx.x;
    int c = threadIdx.x;
    size_t idx = (size_t)row * C + c;
    float val = x[idx] + r[idx];
    float mean = blockReduceSum256(val) * (1.0f / C);
    float d = val - mean;
    float var = blockReduceSum256(d * d) * (1.0f / C);
    float y = d * rsqrtf(var + 1e-5f) * gg[c] + beta[c];
    if (apply_mask) {
        int b = row >> 10, t = row & (T - 1);
        if (t >= lens[b]) y = 0.0f;
    }
    x[idx] = y;
    bf16 hb = __float2bfloat16_rn(y);
    g_xb[idx] = hb;
    g_xs[idx] = __float2bfloat16_rn(y - __bfloat162float(hb));
}

// ---------------- x (B,T,C) -> out (B,C,T) ----------------
__global__ void transpose_kernel(const float* __restrict__ x, float* __restrict__ out) {
    __shared__ float tile[32][33];
    int b = blockIdx.z;
    int t0 = blockIdx.x * 32, c0 = blockIdx.y * 32;
    int tx = threadIdx.x, ty = threadIdx.y;
#pragma unroll
    for (int i = 0; i < 32; i += 8)
        tile[ty + i][tx] = x[(size_t)(b * T + t0 + ty + i) * C + c0 + tx];
    __syncthreads();
#pragma unroll
    for (int i = 0; i < 32; i += 8)
        out[(size_t)(b * C + c0 + ty + i) * T + t0 + tx] = tile[tx][ty + i];
}

__global__ void mask_out_kernel(const int* __restrict__ lens, float* __restrict__ out_mask) {
    int b = blockIdx.x;
    int len = lens[b];
    for (int t = threadIdx.x; t < T; t += blockDim.x)
        out_mask[(size_t)b * T + t] = (t < len) ? 1.0f : 0.0f;
}

}  // namespace

extern "C" void kernel_launch(void* const* d_in, const int* in_sizes, int n_in,
                              void* d_out, int out_size) {
    (void)in_sizes; (void)n_in; (void)out_size;
    const float* emb   = (const float*)d_in[0];
    const float* Wq    = (const float*)d_in[1];
    const float* Wk    = (const float*)d_in[2];
    const float* Wv    = (const float*)d_in[3];
    const float* Wo    = (const float*)d_in[4];
    const float* bq    = (const float*)d_in[5];
    const float* bk    = (const float*)d_in[6];
    const float* bv    = (const float*)d_in[7];
    const float* bo    = (const float*)d_in[8];
    const float* rel_k = (const float*)d_in[9];
    const float* rel_v = (const float*)d_in[10];
    const float* ln1_g = (const float*)d_in[11];
    const float* ln1_b = (const float*)d_in[12];
    const float* ln2_g = (const float*)d_in[13];
    const float* ln2_b = (const float*)d_in[14];
    const float* fw1   = (const float*)d_in[15];
    const float* fb1   = (const float*)d_in[16];
    const float* fw2   = (const float*)d_in[17];
    const float* fb2   = (const float*)d_in[18];
    const float* pw    = (const float*)d_in[19];
    const float* pb    = (const float*)d_in[20];
    const int*   toks  = (const int*)d_in[21];
    const int*   lens  = (const int*)d_in[22];

    cudaFuncSetAttribute(mma_gemm_p<0>, cudaFuncAttributeMaxDynamicSharedMemorySize, SMEM_BYTES);
    cudaFuncSetAttribute(mma_gemm_p<1>, cudaFuncAttributeMaxDynamicSharedMemorySize, SMEM_BYTES);
    cudaFuncSetAttribute(mma_gemm_p<3>, cudaFuncAttributeMaxDynamicSharedMemorySize, SMEM_BYTES);
    cudaFuncSetAttribute(flash_attn, cudaFuncAttributeMaxDynamicSharedMemorySize, FLASH_SMEM);

    float *px, *ptmp;
    bf16 *pwb, *pws, *pxb, *pxs, *pab, *pas, *pfb, *pfs;
    cudaGetSymbolAddress((void**)&px,   g_x);
    cudaGetSymbolAddress((void**)&ptmp, g_tmp);
    cudaGetSymbolAddress((void**)&pwb,  g_wb);
    cudaGetSymbolAddress((void**)&pws,  g_ws);
    cudaGetSymbolAddress((void**)&pxb,  g_xb);
    cudaGetSymbolAddress((void**)&pxs,  g_xs);
    cudaGetSymbolAddress((void**)&pab,  g_ab);
    cudaGetSymbolAddress((void**)&pas,  g_as);
    cudaGetSymbolAddress((void**)&pfb,  g_fb);
    cudaGetSymbolAddress((void**)&pfs,  g_fs);

    float* out      = (float*)d_out;
    float* out_x    = out;
    float* out_m    = out + (size_t)B * C * T;
    float* out_logs = out_m + (size_t)B * OUT * T;
    float* out_mask = out_logs + (size_t)B * OUT * T;

    // ---- weight conversion (pairs, [N][K] layout; QKV concatenated per layer) ----
    dim3 wcb(32, 8);
    wconv_t<<<dim3(C / 32, C / 32, L), wcb>>>(Wq, pwb + OFF_QKV, pws + OFF_QKV, C, C,
                                              (size_t)3 * C * C);
    wconv_t<<<dim3(C / 32, C / 32, L), wcb>>>(Wk, pwb + OFF_QKV + C * C, pws + OFF_QKV + C * C,
                                              C, C, (size_t)3 * C * C);
    wconv_t<<<dim3(C / 32, C / 32, L), wcb>>>(Wv, pwb + OFF_QKV + 2 * C * C,
                                              pws + OFF_QKV + 2 * C * C, C, C,
                                              (size_t)3 * C * C);
    wconv_t<<<dim3(C / 32, C / 32, L), wcb>>>(Wo, pwb + OFF_WO, pws + OFF_WO, C, C,
                                              (size_t)C * C);
    wconv_t<<<dim3(FC / 32, C / 32, L), wcb>>>(fw1, pwb + OFF_F1, pws + OFF_F1, C, FC,
                                               (size_t)C * FC);
    wconv_t<<<dim3(C / 32, FC / 32, L), wcb>>>(fw2, pwb + OFF_F2, pws + OFF_F2, FC, C,
                                               (size_t)FC * C);
    projconv<<<(2 * OUT * C + 255) / 256, 256>>>(pw);

    embed_kernel<<<BT, C>>>(emb, toks);

    dim3 gQKV(3 * C / 128, BT / 128);  // 6 x 64
    dim3 gC(C / 128, BT / 128);        // 2 x 64
    dim3 gFC(FC / 128, BT / 128);      // 8 x 64

    for (int l = 0; l < L; l++) {
        size_t qkv = OFF_QKV + (size_t)l * 3 * C * C;
        size_t wo = OFF_WO + (size_t)l * C * C;
        size_t f1 = OFF_F1 + (size_t)l * C * FC;
        size_t f2 = OFF_F2 + (size_t)l * FC * C;

        mma_gemm_p<1><<<gQKV, 256, SMEM_BYTES>>>(
            pxb, pxs, pwb + qkv, pws + qkv, bq + (size_t)l * C, bk + (size_t)l * C,
            bv + (size_t)l * C, nullptr, nullptr, nullptr, nullptr, BT, 3 * C, C, 1.0f, 0,
            nullptr);

        flash_attn<<<dim3(T / 128, B * H), 256, FLASH_SMEM>>>(
            lens, rel_k + (size_t)l * NREL * HD, rel_v + (size_t)l * NREL * HD);

        mma_gemm_p<0><<<gC, 256, SMEM_BYTES>>>(pab, pas, pwb + wo, pws + wo,
                                               bo + (size_t)l * C, nullptr, nullptr, ptmp,
                                               nullptr, nullptr, nullptr, BT, C, C, 1.0f, 0,
                                               nullptr);
        ln_res_kernel<<<BT, C>>>(px, ptmp, ln1_g + (size_t)l * C, ln1_b + (size_t)l * C, lens, 0);

        mma_gemm_p<0><<<gFC, 256, SMEM_BYTES>>>(pxb, pxs, pwb + f1, pws + f1,
                                                fb1 + (size_t)l * FC, nullptr, nullptr, nullptr,
                                                pfb, pfs, nullptr, BT, FC, C, 1.0f, 1, nullptr);
        mma_gemm_p<0><<<gC, 256, SMEM_BYTES>>>(pfb, pfs, pwb + f2, pws + f2,
                                               fb2 + (size_t)l * C, nullptr, nullptr, ptmp,
                                               nullptr, nullptr, nullptr, BT, C, FC, 1.0f, 0,
                                               nullptr);
        ln_res_kernel<<<BT, C>>>(px, ptmp, ln2_g + (size_t)l * C, ln2_b + (size_t)l * C, lens, 1);
    }

    transpose_kernel<<<dim3(T / 32, C / 32, B), dim3(32, 8)>>>(px, out_x);
    mma_gemm_p<3><<<dim3(2 * OUT / 128, BT / 128), 256, SMEM_BYTES>>>(
        pxb, pxs, pwb + OFF_PJ, pws + OFF_PJ, pb, nullptr, nullptr, out_m, nullptr, nullptr,
        out_logs, BT, 2 * OUT, C, 1.0f, 0, lens);
    mask_out_kernel<<<B, 256>>>(lens, out_mask);
}

// round 7
// speedup vs baseline: 2.1244x; 1.1186x over previous
#include <cuda_runtime.h>
#include <cuda_bf16.h>
#include <math.h>

namespace {

constexpr int C = 256, H = 4, HD = 64, L = 6, FC = 1024, OUT = 192;
constexpr int B = 8, T = 1024, BT = B * T, NREL = 9;

typedef __nv_bfloat16 bf16;

// ---------------- weight pair storage (QKV concatenated per layer) ----------------
constexpr size_t OFF_QKV = 0;                                   // [L][3C][C]
constexpr size_t OFF_WO  = (size_t)L * 3 * C * C;               // [L][C][C]
constexpr size_t OFF_F1  = OFF_WO + (size_t)L * C * C;          // [L][FC][C]
constexpr size_t OFF_F2  = OFF_F1 + (size_t)L * C * FC;         // [L][C][FC]
constexpr size_t OFF_PJ  = OFF_F2 + (size_t)L * FC * C;         // [2*OUT][C]
constexpr size_t WTOT    = OFF_PJ + (size_t)2 * OUT * C;

__device__ bf16 g_wb[WTOT];
__device__ bf16 g_ws[WTOT];

// ---------------- activation scratch ----------------
__device__ float g_x[BT * C];
__device__ float g_tmp[BT * C];
__device__ bf16 g_xb[BT * C], g_xs[BT * C];
__device__ bf16 g_qb[BT * C], g_qs[BT * C];
__device__ bf16 g_kb[BT * C], g_ks[BT * C];
__device__ bf16 g_vb[BT * C], g_vs[BT * C];
__device__ bf16 g_ab[BT * C], g_as[BT * C];
__device__ bf16 g_fb[BT * FC], g_fs[BT * FC];

// ---------------- helpers ----------------
__device__ __forceinline__ float warpReduceSum(float v) {
#pragma unroll
    for (int o = 16; o; o >>= 1) v += __shfl_xor_sync(0xffffffffu, v, o);
    return v;
}

__device__ __forceinline__ void cvt2(float a, float b, unsigned& ub, unsigned& us) {
    __nv_bfloat162 hb, hs;
    hb.x = __float2bfloat16_rn(a);
    hb.y = __float2bfloat16_rn(b);
    float ra = a - __bfloat162float(hb.x);
    float rb = b - __bfloat162float(hb.y);
    hs.x = __float2bfloat16_rn(ra);
    hs.y = __float2bfloat16_rn(rb);
    ub = *reinterpret_cast<unsigned*>(&hb);
    us = *reinterpret_cast<unsigned*>(&hs);
}

__device__ __forceinline__ void mma16816(float c[4], const unsigned a[4], const unsigned b2[2]) {
    asm volatile(
        "mma.sync.aligned.m16n8k16.row.col.f32.bf16.bf16.f32 "
        "{%0,%1,%2,%3}, {%4,%5,%6,%7}, {%8,%9}, {%0,%1,%2,%3};\n"
        : "+f"(c[0]), "+f"(c[1]), "+f"(c[2]), "+f"(c[3])
        : "r"(a[0]), "r"(a[1]), "r"(a[2]), "r"(a[3]), "r"(b2[0]), "r"(b2[1]));
}

__device__ __forceinline__ void ldsm_x4(unsigned& r0, unsigned& r1, unsigned& r2, unsigned& r3,
                                        const void* p) {
    unsigned addr = (unsigned)__cvta_generic_to_shared(p);
    asm volatile("ldmatrix.sync.aligned.m8n8.x4.shared.b16 {%0,%1,%2,%3}, [%4];"
                 : "=r"(r0), "=r"(r1), "=r"(r2), "=r"(r3)
                 : "r"(addr));
}
__device__ __forceinline__ void ldsm_x4_t(unsigned& r0, unsigned& r1, unsigned& r2, unsigned& r3,
                                          const void* p) {
    unsigned addr = (unsigned)__cvta_generic_to_shared(p);
    asm volatile("ldmatrix.sync.aligned.m8n8.x4.trans.shared.b16 {%0,%1,%2,%3}, [%4];"
                 : "=r"(r0), "=r"(r1), "=r"(r2), "=r"(r3)
                 : "r"(addr));
}
__device__ __forceinline__ void cp16(void* s, const void* g) {
    unsigned a = (unsigned)__cvta_generic_to_shared(s);
    asm volatile("cp.async.cg.shared.global [%0], [%1], 16;" :: "r"(a), "l"(g));
}
#define CP_COMMIT() asm volatile("cp.async.commit_group;")

// ---------------- weight conversion: W [Lz][K][N] fp32 -> pair [Lz(lstride)][N][K] ----------------
__global__ void wconv_t(const float* __restrict__ w, bf16* __restrict__ ob,
                        bf16* __restrict__ os, int K, int N, size_t lstride) {
    __shared__ float tile[32][33];
    int l = blockIdx.z;
    const float* src = w + (size_t)l * K * N;
    int k0 = blockIdx.y * 32, n0 = blockIdx.x * 32;
    int tx = threadIdx.x, ty = threadIdx.y;
#pragma unroll
    for (int i = 0; i < 32; i += 8)
        tile[ty + i][tx] = src[(size_t)(k0 + ty + i) * N + n0 + tx];
    __syncthreads();
#pragma unroll
    for (int i = 0; i < 32; i += 8) {
        float v = tile[tx][ty + i];
        size_t o = (size_t)l * lstride + (size_t)(n0 + ty + i) * K + k0 + tx;
        bf16 hb = __float2bfloat16_rn(v);
        ob[o] = hb;
        os[o] = __float2bfloat16_rn(v - __bfloat162float(hb));
    }
}

__global__ void projconv(const float* __restrict__ pw) {
    int i = blockIdx.x * 256 + threadIdx.x;
    if (i >= 2 * OUT * C) return;
    float v = pw[i];
    bf16 hb = __float2bfloat16_rn(v);
    g_wb[OFF_PJ + i] = hb;
    g_ws[OFF_PJ + i] = __float2bfloat16_rn(v - __bfloat162float(hb));
}

// ---------------- embedding (fp32 + pair) ----------------
__global__ void embed_kernel(const float* __restrict__ emb, const int* __restrict__ tokens) {
    int bt = blockIdx.x;
    int c = threadIdx.x;
    float v = emb[(size_t)tokens[bt] * C + c] * 16.0f;
    size_t idx = (size_t)bt * C + c;
    g_x[idx] = v;
    bf16 hb = __float2bfloat16_rn(v);
    g_xb[idx] = hb;
    g_xs[idx] = __float2bfloat16_rn(v - __bfloat162float(hb));
}

// =====================================================================
//  Pair-input bf16x3 GEMM: 128x128 tile, BK=32, 256 threads, dbl-buffered.
// =====================================================================
constexpr int APITCH = 40;
constexpr int TSZ = 128 * APITCH;
constexpr int SMEM_BYTES = 8 * TSZ * (int)sizeof(bf16);  // 81920

template <int MODE>
__global__ __launch_bounds__(256, 1) void mma_gemm_p(
    const bf16* __restrict__ Ab, const bf16* __restrict__ As2,
    const bf16* __restrict__ Bb, const bf16* __restrict__ Bs2,
    const float* __restrict__ bias, const float* __restrict__ bias2,
    const float* __restrict__ bias3, float* __restrict__ outf,
    bf16* __restrict__ outb, bf16* __restrict__ outs, float* __restrict__ out2,
    int M, int N, int K, float alpha, int relu, const int* __restrict__ lens) {
    extern __shared__ bf16 dsm[];
    bf16* As_b = dsm;
    bf16* As_s = dsm + 2 * TSZ;
    bf16* Bs_b = dsm + 4 * TSZ;
    bf16* Bs_s = dsm + 6 * TSZ;

#define ASB(bf_, r, c) As_b[(bf_)*TSZ + (r)*APITCH + (c)]
#define ASS(bf_, r, c) As_s[(bf_)*TSZ + (r)*APITCH + (c)]
#define BSB(bf_, r, c) Bs_b[(bf_)*TSZ + (r)*APITCH + (c)]
#define BSS(bf_, r, c) Bs_s[(bf_)*TSZ + (r)*APITCH + (c)]

    const int tid = threadIdx.x;
    const int lane = tid & 31, wid = tid >> 5;
    const int wm = wid >> 1, wn = wid & 1;
    const int g = lane >> 2, tig = lane & 3;
    const int m0 = blockIdx.y * 128, n0 = blockIdx.x * 128;

    const int ar = tid >> 1, akh = (tid & 1) * 16;

    const int lane7 = lane & 7;
    const int arow = wm * 32 + lane7 + ((lane & 8) ? 8 : 0);
    const int acolsel = (lane & 16) ? 8 : 0;
    const int brow = lane7 + ((lane & 16) ? 8 : 0);
    const int bcolsel = (lane & 8) ? 8 : 0;

    float acc[2][8][4] = {};
    uint2 rAb[4], rAs[4], rBb[4], rBs[4];

    auto load_tiles = [&](int k0) {
        const uint2* pa = (const uint2*)(Ab + (size_t)(m0 + ar) * K + k0 + akh);
        const uint2* ps = (const uint2*)(As2 + (size_t)(m0 + ar) * K + k0 + akh);
        const uint2* qb = (const uint2*)(Bb + (size_t)(n0 + ar) * K + k0 + akh);
        const uint2* qs = (const uint2*)(Bs2 + (size_t)(n0 + ar) * K + k0 + akh);
#pragma unroll
        for (int i = 0; i < 4; i++) {
            rAb[i] = pa[i];
            rAs[i] = ps[i];
            rBb[i] = qb[i];
            rBs[i] = qs[i];
        }
    };
    auto store_tiles = [&](int buf) {
#pragma unroll
        for (int i = 0; i < 4; i++) {
            *reinterpret_cast<uint2*>(&ASB(buf, ar, akh + i * 4)) = rAb[i];
            *reinterpret_cast<uint2*>(&ASS(buf, ar, akh + i * 4)) = rAs[i];
            *reinterpret_cast<uint2*>(&BSB(buf, ar, akh + i * 4)) = rBb[i];
            *reinterpret_cast<uint2*>(&BSS(buf, ar, akh + i * 4)) = rBs[i];
        }
    };

    load_tiles(0);
    int buf = 0;
    for (int k0 = 0; k0 < K; k0 += 32) {
        store_tiles(buf);
        __syncthreads();
        if (k0 + 32 < K) load_tiles(k0 + 32);
#pragma unroll
        for (int kk = 0; kk < 32; kk += 16) {
            unsigned ab[2][4], as_[2][4], bb[8][2], bs_[8][2];
#pragma unroll
            for (int am = 0; am < 2; am++) {
                ldsm_x4(ab[am][0], ab[am][1], ab[am][2], ab[am][3],
                        &ASB(buf, arow + am * 16, kk + acolsel));
                ldsm_x4(as_[am][0], as_[am][1], as_[am][2], as_[am][3],
                        &ASS(buf, arow + am * 16, kk + acolsel));
            }
#pragma unroll
            for (int p = 0; p < 4; p++) {
                ldsm_x4(bb[2 * p][0], bb[2 * p][1], bb[2 * p + 1][0], bb[2 * p + 1][1],
                        &BSB(buf, wn * 64 + p * 16 + brow, kk + bcolsel));
                ldsm_x4(bs_[2 * p][0], bs_[2 * p][1], bs_[2 * p + 1][0], bs_[2 * p + 1][1],
                        &BSS(buf, wn * 64 + p * 16 + brow, kk + bcolsel));
            }
#pragma unroll
            for (int am = 0; am < 2; am++)
#pragma unroll
                for (int an = 0; an < 8; an++) {
                    mma16816(acc[am][an], ab[am], bb[an]);
                    mma16816(acc[am][an], ab[am], bs_[an]);
                    mma16816(acc[am][an], as_[am], bb[an]);
                }
        }
        buf ^= 1;
        __syncthreads();
    }

    // ---------------- epilogue ----------------
    int tgt = 0;
    const float* biasp = bias;
    bf16* tob = outb;
    bf16* tos = outs;
    float al = alpha;
    if constexpr (MODE == 1) {
        tgt = n0 >> 8;
        biasp = (tgt == 0) ? bias : (tgt == 1 ? bias2 : bias3);
        tob = (tgt == 0) ? g_qb : (tgt == 1 ? g_kb : g_vb);
        tos = (tgt == 0) ? g_qs : (tgt == 1 ? g_ks : g_vs);
        al = (tgt == 0) ? 0.125f : 1.0f;
    }

#pragma unroll
    for (int am = 0; am < 2; am++) {
#pragma unroll
        for (int rr = 0; rr < 2; rr++) {
            int row = m0 + wm * 32 + am * 16 + g + rr * 8;
#pragma unroll
            for (int an = 0; an < 8; an++) {
                int col0 = n0 + wn * 64 + an * 8 + 2 * tig;
                if constexpr (MODE == 0) {
                    float v0 = (acc[am][an][rr * 2 + 0] + bias[col0]) * alpha;
                    float v1 = (acc[am][an][rr * 2 + 1] + bias[col0 + 1]) * alpha;
                    if (relu) { v0 = fmaxf(v0, 0.f); v1 = fmaxf(v1, 0.f); }
                    if (outf) {
                        outf[(size_t)row * N + col0] = v0;
                        outf[(size_t)row * N + col0 + 1] = v1;
                    }
                    if (outb) {
                        unsigned ub, us;
                        cvt2(v0, v1, ub, us);
                        *reinterpret_cast<unsigned*>(&outb[(size_t)row * N + col0]) = ub;
                        *reinterpret_cast<unsigned*>(&outs[(size_t)row * N + col0]) = us;
                    }
                } else if constexpr (MODE == 1) {
                    int lc = col0 - tgt * 256;
                    float v0 = (acc[am][an][rr * 2 + 0] + biasp[lc]) * al;
                    float v1 = (acc[am][an][rr * 2 + 1] + biasp[lc + 1]) * al;
                    unsigned ub, us;
                    cvt2(v0, v1, ub, us);
                    *reinterpret_cast<unsigned*>(&tob[(size_t)row * C + lc]) = ub;
                    *reinterpret_cast<unsigned*>(&tos[(size_t)row * C + lc]) = us;
                } else {  // MODE 3
                    int bb2 = row >> 10, tt = row & (T - 1);
                    float mk = (tt < lens[bb2]) ? 1.0f : 0.0f;
#pragma unroll
                    for (int cc = 0; cc < 2; cc++) {
                        int col = col0 + cc;
                        float vv = (acc[am][an][rr * 2 + cc] + bias[col]) * mk;
                        if (col < OUT)
                            outf[((size_t)bb2 * OUT + col) * T + tt] = vv;
                        else
                            out2[((size_t)bb2 * OUT + (col - OUT)) * T + tt] = vv;
                    }
                }
            }
        }
    }
#undef ASB
#undef ASS
#undef BSB
#undef BSS
}

// =====================================================================
//  Flash attention: cp.async double-buffered K/V, V row-major + ldsm.trans
// =====================================================================
constexpr int QPITCH = 72;
constexpr int KVT = 64 * QPITCH;  // 4608 elems per (tensor, stage)
constexpr int FLASH_SMEM = (2 * 128 * QPITCH + 8 * KVT) * (int)sizeof(bf16);  // 110592

__global__ __launch_bounds__(256, 1) void flash_attn(
    const int* __restrict__ lens, const float* __restrict__ relk,
    const float* __restrict__ relv) {
    extern __shared__ bf16 fsm[];
    bf16* Qb = fsm;                       // [128][72]
    bf16* Qs = fsm + 9216;
    bf16* Ktb = fsm + 18432;              // [2][64][72]
    bf16* Kts = fsm + 18432 + 2 * KVT;
    bf16* Vtb = fsm + 18432 + 4 * KVT;    // [2][64][72] row-major [k][c]
    bf16* Vts = fsm + 18432 + 6 * KVT;
    __shared__ float qrel_s[128 * NREL];
    __shared__ float relk_s[NREL * HD];
    __shared__ float relv_s[NREL * HD];

    const int tid = threadIdx.x, lane = tid & 31, w = tid >> 5;
    const int g = lane >> 2, tig = lane & 3;
    const unsigned qm = 0xFu << (lane & 28);
    const int m0 = blockIdx.x * 128;
    const int bh = blockIdx.y, b = bh >> 2, h = bh & 3;
    const int len = lens[b];

    const int kr = tid >> 2, cq = (tid & 3) * 16;
    auto load_kv = [&](int k0, int st) {
        size_t gi = ((size_t)(b * T + k0 + kr)) * C + h * HD + cq;
        bf16* kd = Ktb + st * KVT + kr * QPITCH + cq;
        bf16* ks = Kts + st * KVT + kr * QPITCH + cq;
        bf16* vd = Vtb + st * KVT + kr * QPITCH + cq;
        bf16* vs = Vts + st * KVT + kr * QPITCH + cq;
        cp16(kd, g_kb + gi);
        cp16(kd + 8, g_kb + gi + 8);
        cp16(ks, g_ks + gi);
        cp16(ks + 8, g_ks + gi + 8);
        cp16(vd, g_vb + gi);
        cp16(vd + 8, g_vb + gi + 8);
        cp16(vs, g_vs + gi);
        cp16(vs + 8, g_vs + gi + 8);
    };

    // prefetch tile 0
    load_kv(0, 0);
    CP_COMMIT();

    // ---- load Q tile pair ----
    {
        int row = tid >> 1, half = (tid & 1) * 32;
        const uint2* sb = (const uint2*)(g_qb + ((size_t)(b * T + m0 + row)) * C + h * HD + half);
        const uint2* ss = (const uint2*)(g_qs + ((size_t)(b * T + m0 + row)) * C + h * HD + half);
        uint2* db = (uint2*)(Qb + row * QPITCH + half);
        uint2* ds = (uint2*)(Qs + row * QPITCH + half);
#pragma unroll
        for (int i = 0; i < 8; i++) { db[i] = sb[i]; ds[i] = ss[i]; }
    }
    for (int i = tid; i < NREL * HD; i += 256) { relk_s[i] = relk[i]; relv_s[i] = relv[i]; }
    __syncthreads();

    // ---- qrel[r][d] = q[r] . rel_k[d] ----
    for (int i = tid; i < 128 * NREL; i += 256) {
        int r = i / NREL, d = i % NREL;
        const bf16* qb = Qb + r * QPITCH;
        const bf16* qs = Qs + r * QPITCH;
        float s = 0.f;
#pragma unroll
        for (int c = 0; c < HD; c++)
            s += (__bfloat162float(qb[c]) + __bfloat162float(qs[c])) * relk_s[d * HD + c];
        qrel_s[i] = s;
    }

    const int arow = w * 16 + (lane & 7) + ((lane & 8) ? 8 : 0);
    const int acolsel = (lane & 16) ? 8 : 0;
    const int brow = (lane & 7) + ((lane & 16) ? 8 : 0);
    const int bcolsel = (lane & 8) ? 8 : 0;
    const int vrow = (lane & 7) + ((lane & 8) ? 8 : 0);   // k offset within 16
    const int vcol = (lane & 16) ? 8 : 0;                 // n offset within 16
    unsigned qfb[4][4], qfs[4][4];
#pragma unroll
    for (int s2 = 0; s2 < 4; s2++) {
        ldsm_x4(qfb[s2][0], qfb[s2][1], qfb[s2][2], qfb[s2][3],
                Qb + arow * QPITCH + s2 * 16 + acolsel);
        ldsm_x4(qfs[s2][0], qfs[s2][1], qfs[s2][2], qfs[s2][3],
                Qs + arow * QPITCH + s2 * 16 + acolsel);
    }

    float oacc[8][4] = {};
    float mrow[2] = {-1e30f, -1e30f}, lrow[2] = {0.f, 0.f};

    const int nt = (len + 63) >> 6;
    int st = 0;
    for (int it = 0; it < nt; it++) {
        const int k0 = it * 64;
        if (it + 1 < nt) {
            load_kv(k0 + 64, st ^ 1);
            CP_COMMIT();
            asm volatile("cp.async.wait_group 1;");
        } else {
            asm volatile("cp.async.wait_group 0;");
        }
        __syncthreads();

        // ---- S = Q K^T (bf16x3) ----
        float sacc[8][4] = {};
#pragma unroll
        for (int s2 = 0; s2 < 4; s2++) {
            unsigned kb[8][2], km[8][2];
#pragma unroll
            for (int p = 0; p < 4; p++) {
                ldsm_x4(kb[2 * p][0], kb[2 * p][1], kb[2 * p + 1][0], kb[2 * p + 1][1],
                        Ktb + st * KVT + (p * 16 + brow) * QPITCH + s2 * 16 + bcolsel);
                ldsm_x4(km[2 * p][0], km[2 * p][1], km[2 * p + 1][0], km[2 * p + 1][1],
                        Kts + st * KVT + (p * 16 + brow) * QPITCH + s2 * 16 + bcolsel);
            }
#pragma unroll
            for (int an = 0; an < 8; an++) {
                mma16816(sacc[an], qfb[s2], kb[an]);
                mma16816(sacc[an], qfb[s2], km[an]);
                mma16816(sacc[an], qfs[s2], kb[an]);
            }
        }

        // ---- bias + mask ----
#pragma unroll
        for (int rr = 0; rr < 2; rr++) {
            int lr = w * 16 + g + rr * 8;
            int qg = m0 + lr;
#pragma unroll
            for (int an = 0; an < 8; an++) {
#pragma unroll
                for (int cc = 0; cc < 2; cc++) {
                    int col = k0 + an * 8 + 2 * tig + cc;
                    float s = sacc[an][rr * 2 + cc];
                    int d = col - qg;
                    if (d >= -4 && d <= 4) s += qrel_s[lr * NREL + d + 4];
                    if (col >= len) s = -1e30f;
                    sacc[an][rr * 2 + cc] = s;
                }
            }
        }

        // ---- online softmax ----
#pragma unroll
        for (int rr = 0; rr < 2; rr++) {
            float mx = -1e30f;
#pragma unroll
            for (int an = 0; an < 8; an++) {
                mx = fmaxf(mx, sacc[an][rr * 2 + 0]);
                mx = fmaxf(mx, sacc[an][rr * 2 + 1]);
            }
            mx = fmaxf(mx, __shfl_xor_sync(qm, mx, 1));
            mx = fmaxf(mx, __shfl_xor_sync(qm, mx, 2));
            float mnew = fmaxf(mrow[rr], mx);
            float corr = __expf(mrow[rr] - mnew);
            mrow[rr] = mnew;
            float rs = 0.f;
#pragma unroll
            for (int an = 0; an < 8; an++) {
#pragma unroll
                for (int cc = 0; cc < 2; cc++) {
                    float p = __expf(sacc[an][rr * 2 + cc] - mnew);
                    sacc[an][rr * 2 + cc] = p;
                    rs += p;
                }
            }
            lrow[rr] = lrow[rr] * corr + rs;
#pragma unroll
            for (int an = 0; an < 8; an++) {
                oacc[an][rr * 2 + 0] *= corr;
                oacc[an][rr * 2 + 1] *= corr;
            }
        }

        // ---- P -> A fragments ----
        unsigned pfb[4][4], pfs[4][4];
#pragma unroll
        for (int s2 = 0; s2 < 4; s2++) {
            cvt2(sacc[2 * s2][0], sacc[2 * s2][1], pfb[s2][0], pfs[s2][0]);
            cvt2(sacc[2 * s2][2], sacc[2 * s2][3], pfb[s2][1], pfs[s2][1]);
            cvt2(sacc[2 * s2 + 1][0], sacc[2 * s2 + 1][1], pfb[s2][2], pfs[s2][2]);
            cvt2(sacc[2 * s2 + 1][2], sacc[2 * s2 + 1][3], pfb[s2][3], pfs[s2][3]);
        }

        // ---- O += P V (V fragments via ldmatrix.trans from row-major [k][c]) ----
#pragma unroll
        for (int s2 = 0; s2 < 4; s2++) {
            unsigned vb[8][2], vs2[8][2];
#pragma unroll
            for (int p = 0; p < 4; p++) {
                ldsm_x4_t(vb[2 * p][0], vb[2 * p][1], vb[2 * p + 1][0], vb[2 * p + 1][1],
                          Vtb + st * KVT + (s2 * 16 + vrow) * QPITCH + p * 16 + vcol);
                ldsm_x4_t(vs2[2 * p][0], vs2[2 * p][1], vs2[2 * p + 1][0], vs2[2 * p + 1][1],
                          Vts + st * KVT + (s2 * 16 + vrow) * QPITCH + p * 16 + vcol);
            }
#pragma unroll
            for (int an = 0; an < 8; an++) {
                mma16816(oacc[an], pfb[s2], vb[an]);
                mma16816(oacc[an], pfb[s2], vs2[an]);
                mma16816(oacc[an], pfs[s2], vb[an]);
            }
        }
        __syncthreads();
        st ^= 1;
    }

    // ---- finalize ----
    float linv[2];
#pragma unroll
    for (int rr = 0; rr < 2; rr++) {
        float lv = lrow[rr];
        lv += __shfl_xor_sync(qm, lv, 1);
        lv += __shfl_xor_sync(qm, lv, 2);
        linv[rr] = 1.0f / lv;
#pragma unroll
        for (int an = 0; an < 8; an++) {
            oacc[an][rr * 2 + 0] *= linv[rr];
            oacc[an][rr * 2 + 1] *= linv[rr];
        }
    }

#pragma unroll
    for (int rr = 0; rr < 2; rr++) {
        int lr = w * 16 + g + rr * 8;
        int qg = m0 + lr;
#pragma unroll
        for (int j = 0; j < NREL; j++) {
            int k = qg + j - 4;
            if (k < 0 || k >= len) continue;
            const bf16* kbp = g_kb + ((size_t)(b * T + k)) * C + h * HD;
            const bf16* ksp = g_ks + ((size_t)(b * T + k)) * C + h * HD;
            float part = 0.f;
#pragma unroll
            for (int c = tig * 16; c < tig * 16 + 16; c++) {
                float qv = __bfloat162float(Qb[lr * QPITCH + c]) +
                           __bfloat162float(Qs[lr * QPITCH + c]);
                float kv = __bfloat162float(kbp[c]) + __bfloat162float(ksp[c]);
                part += qv * kv;
            }
            part += __shfl_xor_sync(qm, part, 1);
            part += __shfl_xor_sync(qm, part, 2);
            float p = __expf(part + qrel_s[lr * NREL + j] - mrow[rr]) * linv[rr];
#pragma unroll
            for (int an = 0; an < 8; an++) {
                int c0 = an * 8 + 2 * tig;
                oacc[an][rr * 2 + 0] += p * relv_s[j * HD + c0];
                oacc[an][rr * 2 + 1] += p * relv_s[j * HD + c0 + 1];
            }
        }
#pragma unroll
        for (int an = 0; an < 8; an++) {
            int c0 = an * 8 + 2 * tig;
            unsigned ub, us;
            cvt2(oacc[an][rr * 2 + 0], oacc[an][rr * 2 + 1], ub, us);
            size_t o = ((size_t)(b * T + qg)) * C + h * HD + c0;
            *reinterpret_cast<unsigned*>(&g_ab[o]) = ub;
            *reinterpret_cast<unsigned*>(&g_as[o]) = us;
        }
    }
}

// ---------------- LN warp-per-row: x = LN(x + r)*g + b, write fp32 + pair ----------------
__global__ void ln_res_kernel(float* __restrict__ x, const float* __restrict__ r,
                              const float* __restrict__ gg, const float* __restrict__ beta,
                              const int* __restrict__ lens, int apply_mask) {
    int row = blockIdx.x * 8 + (threadIdx.x >> 5);
    int lane = threadIdx.x & 31;
    const float4* xr = (const float4*)(x + (size_t)row * C);
    const float4* rr = (const float4*)(r + (size_t)row * C);
    float4 a0 = xr[lane], a1 = xr[lane + 32];
    float4 b0 = rr[lane], b1 = rr[lane + 32];
    float v[8] = {a0.x + b0.x, a0.y + b0.y, a0.z + b0.z, a0.w + b0.w,
                  a1.x + b1.x, a1.y + b1.y, a1.z + b1.z, a1.w + b1.w};
    float s = 0.f;
#pragma unroll
    for (int i = 0; i < 8; i++) s += v[i];
    float mean = warpReduceSum(s) * (1.0f / C);
    float sq = 0.f;
#pragma unroll
    for (int i = 0; i < 8; i++) {
        float d = v[i] - mean;
        sq += d * d;
    }
    float inv = rsqrtf(warpReduceSum(sq) * (1.0f / C) + 1e-5f);
    float zero = 1.0f;
    if (apply_mask) {
        int b = row >> 10, t = row & (T - 1);
        if (t >= lens[b]) zero = 0.0f;
    }
    const float4* gp = (const float4*)gg;
    const float4* bp = (const float4*)beta;
    float4 g0 = gp[lane], g1 = gp[lane + 32];
    float4 e0 = bp[lane], e1 = bp[lane + 32];
    float gv[8] = {g0.x, g0.y, g0.z, g0.w, g1.x, g1.y, g1.z, g1.w};
    float ev[8] = {e0.x, e0.y, e0.z, e0.w, e1.x, e1.y, e1.z, e1.w};
    float y[8];
#pragma unroll
    for (int i = 0; i < 8; i++) y[i] = ((v[i] - mean) * inv * gv[i] + ev[i]) * zero;

    float4* xo = (float4*)(x + (size_t)row * C);
    xo[lane] = make_float4(y[0], y[1], y[2], y[3]);
    xo[lane + 32] = make_float4(y[4], y[5], y[6], y[7]);
    unsigned* pb16 = (unsigned*)(g_xb + (size_t)row * C);
    unsigned* ps16 = (unsigned*)(g_xs + (size_t)row * C);
#pragma unroll
    for (int i = 0; i < 4; i += 2) {
        unsigned ub, us;
        cvt2(y[i], y[i + 1], ub, us);
        pb16[lane * 2 + i / 2] = ub;
        ps16[lane * 2 + i / 2] = us;
    }
#pragma unroll
    for (int i = 4; i < 8; i += 2) {
        unsigned ub, us;
        cvt2(y[i], y[i + 1], ub, us);
        pb16[64 + lane * 2 + (i - 4) / 2] = ub;
        ps16[64 + lane * 2 + (i - 4) / 2] = us;
    }
}

// ---------------- x (B,T,C) -> out (B,C,T) ----------------
__global__ void transpose_kernel(const float* __restrict__ x, float* __restrict__ out) {
    __shared__ float tile[32][33];
    int b = blockIdx.z;
    int t0 = blockIdx.x * 32, c0 = blockIdx.y * 32;
    int tx = threadIdx.x, ty = threadIdx.y;
#pragma unroll
    for (int i = 0; i < 32; i += 8)
        tile[ty + i][tx] = x[(size_t)(b * T + t0 + ty + i) * C + c0 + tx];
    __syncthreads();
#pragma unroll
    for (int i = 0; i < 32; i += 8)
        out[(size_t)(b * C + c0 + ty + i) * T + t0 + tx] = tile[tx][ty + i];
}

__global__ void mask_out_kernel(const int* __restrict__ lens, float* __restrict__ out_mask) {
    int b = blockIdx.x;
    int len = lens[b];
    for (int t = threadIdx.x; t < T; t += blockDim.x)
        out_mask[(size_t)b * T + t] = (t < len) ? 1.0f : 0.0f;
}

}  // namespace

extern "C" void kernel_launch(void* const* d_in, const int* in_sizes, int n_in,
                              void* d_out, int out_size) {
    (void)in_sizes; (void)n_in; (void)out_size;
    const float* emb   = (const float*)d_in[0];
    const float* Wq    = (const float*)d_in[1];
    const float* Wk    = (const float*)d_in[2];
    const float* Wv    = (const float*)d_in[3];
    const float* Wo    = (const float*)d_in[4];
    const float* bq    = (const float*)d_in[5];
    const float* bk    = (const float*)d_in[6];
    const float* bv    = (const float*)d_in[7];
    const float* bo    = (const float*)d_in[8];
    const float* rel_k = (const float*)d_in[9];
    const float* rel_v = (const float*)d_in[10];
    const float* ln1_g = (const float*)d_in[11];
    const float* ln1_b = (const float*)d_in[12];
    const float* ln2_g = (const float*)d_in[13];
    const float* ln2_b = (const float*)d_in[14];
    const float* fw1   = (const float*)d_in[15];
    const float* fb1   = (const float*)d_in[16];
    const float* fw2   = (const float*)d_in[17];
    const float* fb2   = (const float*)d_in[18];
    const float* pw    = (const float*)d_in[19];
    const float* pb    = (const float*)d_in[20];
    const int*   toks  = (const int*)d_in[21];
    const int*   lens  = (const int*)d_in[22];

    cudaFuncSetAttribute(mma_gemm_p<0>, cudaFuncAttributeMaxDynamicSharedMemorySize, SMEM_BYTES);
    cudaFuncSetAttribute(mma_gemm_p<1>, cudaFuncAttributeMaxDynamicSharedMemorySize, SMEM_BYTES);
    cudaFuncSetAttribute(mma_gemm_p<3>, cudaFuncAttributeMaxDynamicSharedMemorySize, SMEM_BYTES);
    cudaFuncSetAttribute(flash_attn, cudaFuncAttributeMaxDynamicSharedMemorySize, FLASH_SMEM);

    float *px, *ptmp;
    bf16 *pwb, *pws, *pxb, *pxs, *pab, *pas, *pfb, *pfs;
    cudaGetSymbolAddress((void**)&px,   g_x);
    cudaGetSymbolAddress((void**)&ptmp, g_tmp);
    cudaGetSymbolAddress((void**)&pwb,  g_wb);
    cudaGetSymbolAddress((void**)&pws,  g_ws);
    cudaGetSymbolAddress((void**)&pxb,  g_xb);
    cudaGetSymbolAddress((void**)&pxs,  g_xs);
    cudaGetSymbolAddress((void**)&pab,  g_ab);
    cudaGetSymbolAddress((void**)&pas,  g_as);
    cudaGetSymbolAddress((void**)&pfb,  g_fb);
    cudaGetSymbolAddress((void**)&pfs,  g_fs);

    float* out      = (float*)d_out;
    float* out_x    = out;
    float* out_m    = out + (size_t)B * C * T;
    float* out_logs = out_m + (size_t)B * OUT * T;
    float* out_mask = out_logs + (size_t)B * OUT * T;

    dim3 wcb(32, 8);
    wconv_t<<<dim3(C / 32, C / 32, L), wcb>>>(Wq, pwb + OFF_QKV, pws + OFF_QKV, C, C,
                                              (size_t)3 * C * C);
    wconv_t<<<dim3(C / 32, C / 32, L), wcb>>>(Wk, pwb + OFF_QKV + C * C, pws + OFF_QKV + C * C,
                                              C, C, (size_t)3 * C * C);
    wconv_t<<<dim3(C / 32, C / 32, L), wcb>>>(Wv, pwb + OFF_QKV + 2 * C * C,
                                              pws + OFF_QKV + 2 * C * C, C, C,
                                              (size_t)3 * C * C);
    wconv_t<<<dim3(C / 32, C / 32, L), wcb>>>(Wo, pwb + OFF_WO, pws + OFF_WO, C, C,
                                              (size_t)C * C);
    wconv_t<<<dim3(FC / 32, C / 32, L), wcb>>>(fw1, pwb + OFF_F1, pws + OFF_F1, C, FC,
                                               (size_t)C * FC);
    wconv_t<<<dim3(C / 32, FC / 32, L), wcb>>>(fw2, pwb + OFF_F2, pws + OFF_F2, FC, C,
                                               (size_t)FC * C);
    projconv<<<(2 * OUT * C + 255) / 256, 256>>>(pw);

    embed_kernel<<<BT, C>>>(emb, toks);

    dim3 gQKV(3 * C / 128, BT / 128);
    dim3 gC(C / 128, BT / 128);
    dim3 gFC(FC / 128, BT / 128);

    for (int l = 0; l < L; l++) {
        size_t qkv = OFF_QKV + (size_t)l * 3 * C * C;
        size_t wo = OFF_WO + (size_t)l * C * C;
        size_t f1 = OFF_F1 + (size_t)l * C * FC;
        size_t f2 = OFF_F2 + (size_t)l * FC * C;

        mma_gemm_p<1><<<gQKV, 256, SMEM_BYTES>>>(
            pxb, pxs, pwb + qkv, pws + qkv, bq + (size_t)l * C, bk + (size_t)l * C,
            bv + (size_t)l * C, nullptr, nullptr, nullptr, nullptr, BT, 3 * C, C, 1.0f, 0,
            nullptr);

        flash_attn<<<dim3(T / 128, B * H), 256, FLASH_SMEM>>>(
            lens, rel_k + (size_t)l * NREL * HD, rel_v + (size_t)l * NREL * HD);

        mma_gemm_p<0><<<gC, 256, SMEM_BYTES>>>(pab, pas, pwb + wo, pws + wo,
                                               bo + (size_t)l * C, nullptr, nullptr, ptmp,
                                               nullptr, nullptr, nullptr, BT, C, C, 1.0f, 0,
                                               nullptr);
        ln_res_kernel<<<BT / 8, 256>>>(px, ptmp, ln1_g + (size_t)l * C, ln1_b + (size_t)l * C,
                                       lens, 0);

        mma_gemm_p<0><<<gFC, 256, SMEM_BYTES>>>(pxb, pxs, pwb + f1, pws + f1,
                                                fb1 + (size_t)l * FC, nullptr, nullptr, nullptr,
                                                pfb, pfs, nullptr, BT, FC, C, 1.0f, 1, nullptr);
        mma_gemm_p<0><<<gC, 256, SMEM_BYTES>>>(pfb, pfs, pwb + f2, pws + f2,
                                               fb2 + (size_t)l * C, nullptr, nullptr, ptmp,
                                               nullptr, nullptr, nullptr, BT, C, FC, 1.0f, 0,
                                               nullptr);
        ln_res_kernel<<<BT / 8, 256>>>(px, ptmp, ln2_g + (size_t)l * C, ln2_b + (size_t)l * C,
                                       lens, 1);
    }

    transpose_kernel<<<dim3(T / 32, C / 32, B), dim3(32, 8)>>>(px, out_x);
    mma_gemm_p<3><<<dim3(2 * OUT / 128, BT / 128), 256, SMEM_BYTES>>>(
        pxb, pxs, pwb + OFF_PJ, pws + OFF_PJ, pb, nullptr, nullptr, out_m, nullptr, nullptr,
        out_logs, BT, 2 * OUT, C, 1.0f, 0, lens);
    mask_out_kernel<<<B, 256>>>(lens, out_mask);
}

// round 10
// speedup vs baseline: 2.3843x; 1.1223x over previous
#include <cuda_runtime.h>
#include <cuda_bf16.h>
#include <math.h>

namespace {

constexpr int C = 256, H = 4, HD = 64, L = 6, FC = 1024, OUT = 192;
constexpr int B = 8, T = 1024, BT = B * T, NREL = 9;

typedef __nv_bfloat16 bf16;

// ---------------- weight pair storage (QKV concatenated per layer) ----------------
constexpr size_t OFF_QKV = 0;
constexpr size_t OFF_WO  = (size_t)L * 3 * C * C;
constexpr size_t OFF_F1  = OFF_WO + (size_t)L * C * C;
constexpr size_t OFF_F2  = OFF_F1 + (size_t)L * C * FC;
constexpr size_t OFF_PJ  = OFF_F2 + (size_t)L * FC * C;
constexpr size_t WTOT    = OFF_PJ + (size_t)2 * OUT * C;

__device__ bf16 g_wb[WTOT];
__device__ bf16 g_ws[WTOT];

// ---------------- activation scratch ----------------
__device__ float g_x[BT * C];
__device__ float g_tmp[BT * C];
__device__ bf16 g_xb[BT * C], g_xs[BT * C];
__device__ bf16 g_qb[BT * C], g_qs[BT * C];
__device__ bf16 g_kb[BT * C], g_ks[BT * C];
__device__ bf16 g_vb[BT * C], g_vs[BT * C];
__device__ bf16 g_ab[BT * C], g_as[BT * C];
__device__ bf16 g_fb[BT * FC], g_fs[BT * FC];

// ---------------- helpers ----------------
__device__ __forceinline__ float warpReduceSum(float v) {
#pragma unroll
    for (int o = 16; o; o >>= 1) v += __shfl_xor_sync(0xffffffffu, v, o);
    return v;
}

__device__ __forceinline__ void cvt2(float a, float b, unsigned& ub, unsigned& us) {
    __nv_bfloat162 hb, hs;
    hb.x = __float2bfloat16_rn(a);
    hb.y = __float2bfloat16_rn(b);
    float ra = a - __bfloat162float(hb.x);
    float rb = b - __bfloat162float(hb.y);
    hs.x = __float2bfloat16_rn(ra);
    hs.y = __float2bfloat16_rn(rb);
    ub = *reinterpret_cast<unsigned*>(&hb);
    us = *reinterpret_cast<unsigned*>(&hs);
}

__device__ __forceinline__ void mma16816(float c[4], const unsigned a[4], const unsigned b2[2]) {
    asm volatile(
        "mma.sync.aligned.m16n8k16.row.col.f32.bf16.bf16.f32 "
        "{%0,%1,%2,%3}, {%4,%5,%6,%7}, {%8,%9}, {%0,%1,%2,%3};\n"
        : "+f"(c[0]), "+f"(c[1]), "+f"(c[2]), "+f"(c[3])
        : "r"(a[0]), "r"(a[1]), "r"(a[2]), "r"(a[3]), "r"(b2[0]), "r"(b2[1]));
}

__device__ __forceinline__ void ldsm_x4(unsigned& r0, unsigned& r1, unsigned& r2, unsigned& r3,
                                        const void* p) {
    unsigned addr = (unsigned)__cvta_generic_to_shared(p);
    asm volatile("ldmatrix.sync.aligned.m8n8.x4.shared.b16 {%0,%1,%2,%3}, [%4];"
                 : "=r"(r0), "=r"(r1), "=r"(r2), "=r"(r3)
                 : "r"(addr));
}
__device__ __forceinline__ void ldsm_x4_t(unsigned& r0, unsigned& r1, unsigned& r2, unsigned& r3,
                                          const void* p) {
    unsigned addr = (unsigned)__cvta_generic_to_shared(p);
    asm volatile("ldmatrix.sync.aligned.m8n8.x4.trans.shared.b16 {%0,%1,%2,%3}, [%4];"
                 : "=r"(r0), "=r"(r1), "=r"(r2), "=r"(r3)
                 : "r"(addr));
}
__device__ __forceinline__ void cp16(void* s, const void* g) {
    unsigned a = (unsigned)__cvta_generic_to_shared(s);
    asm volatile("cp.async.cg.shared.global [%0], [%1], 16;" :: "r"(a), "l"(g));
}
#define CP_COMMIT() asm volatile("cp.async.commit_group;")
#define CP_WAIT1() asm volatile("cp.async.wait_group 1;")

// ---------------- weight conversion ----------------
__global__ void wconv_t(const float* __restrict__ w, bf16* __restrict__ ob,
                        bf16* __restrict__ os, int K, int N, size_t lstride) {
    __shared__ float tile[32][33];
    int l = blockIdx.z;
    const float* src = w + (size_t)l * K * N;
    int k0 = blockIdx.y * 32, n0 = blockIdx.x * 32;
    int tx = threadIdx.x, ty = threadIdx.y;
#pragma unroll
    for (int i = 0; i < 32; i += 8)
        tile[ty + i][tx] = src[(size_t)(k0 + ty + i) * N + n0 + tx];
    __syncthreads();
#pragma unroll
    for (int i = 0; i < 32; i += 8) {
        float v = tile[tx][ty + i];
        size_t o = (size_t)l * lstride + (size_t)(n0 + ty + i) * K + k0 + tx;
        bf16 hb = __float2bfloat16_rn(v);
        ob[o] = hb;
        os[o] = __float2bfloat16_rn(v - __bfloat162float(hb));
    }
}

__global__ void projconv(const float* __restrict__ pw) {
    int i = blockIdx.x * 256 + threadIdx.x;
    if (i >= 2 * OUT * C) return;
    float v = pw[i];
    bf16 hb = __float2bfloat16_rn(v);
    g_wb[OFF_PJ + i] = hb;
    g_ws[OFF_PJ + i] = __float2bfloat16_rn(v - __bfloat162float(hb));
}

// ---------------- embedding ----------------
__global__ void embed_kernel(const float* __restrict__ emb, const int* __restrict__ tokens) {
    int bt = blockIdx.x;
    int c = threadIdx.x;
    float v = emb[(size_t)tokens[bt] * C + c] * 16.0f;
    size_t idx = (size_t)bt * C + c;
    g_x[idx] = v;
    bf16 hb = __float2bfloat16_rn(v);
    g_xb[idx] = hb;
    g_xs[idx] = __float2bfloat16_rn(v - __bfloat162float(hb));
}

// =====================================================================
//  Pair-input bf16x3 GEMM: 128x128 tile, BK=32, 256 threads,
//  3-stage cp.async pipeline, one __syncthreads per k-tile.
// =====================================================================
constexpr int APITCH = 40;
constexpr int TSZ = 128 * APITCH;                                 // per tensor per stage
constexpr int SMEM_BYTES = 12 * TSZ * (int)sizeof(bf16);          // 4 tensors * 3 stages

template <int MODE>
__global__ __launch_bounds__(256, 1) void mma_gemm_p(
    const bf16* __restrict__ Ab, const bf16* __restrict__ As2,
    const bf16* __restrict__ Bb, const bf16* __restrict__ Bs2,
    const float* __restrict__ bias, const float* __restrict__ bias2,
    const float* __restrict__ bias3, float* __restrict__ outf,
    bf16* __restrict__ outb, bf16* __restrict__ outs, float* __restrict__ out2,
    int M, int N, int K, float alpha, int relu, const int* __restrict__ lens) {
    extern __shared__ bf16 dsm[];
    bf16* As_b = dsm;                 // [3][128][40]
    bf16* As_s = dsm + 3 * TSZ;
    bf16* Bs_b = dsm + 6 * TSZ;
    bf16* Bs_s = dsm + 9 * TSZ;

    const int tid = threadIdx.x;
    const int lane = tid & 31, wid = tid >> 5;
    const int wm = wid >> 1, wn = wid & 1;
    const int g = lane >> 2, tig = lane & 3;
    const int m0 = blockIdx.y * 128, n0 = blockIdx.x * 128;

    const int ar = tid >> 1, akh = (tid & 1) * 16;

    const int lane7 = lane & 7;
    const int arow = wm * 32 + lane7 + ((lane & 8) ? 8 : 0);
    const int acolsel = (lane & 16) ? 8 : 0;
    const int brow = lane7 + ((lane & 16) ? 8 : 0);
    const int bcolsel = (lane & 8) ? 8 : 0;

    float acc[2][8][4] = {};

    auto load_st = [&](int k0, int st) {
        size_t ai = (size_t)(m0 + ar) * K + k0 + akh;
        size_t bi = (size_t)(n0 + ar) * K + k0 + akh;
        int so = st * TSZ + ar * APITCH + akh;
        cp16(As_b + so, Ab + ai);
        cp16(As_b + so + 8, Ab + ai + 8);
        cp16(As_s + so, As2 + ai);
        cp16(As_s + so + 8, As2 + ai + 8);
        cp16(Bs_b + so, Bb + bi);
        cp16(Bs_b + so + 8, Bb + bi + 8);
        cp16(Bs_s + so, Bs2 + bi);
        cp16(Bs_s + so + 8, Bs2 + bi + 8);
    };

    const int KT = K >> 5;
    load_st(0, 0);
    CP_COMMIT();
    load_st(32, 1);
    CP_COMMIT();

    for (int kt = 0; kt < KT; kt++) {
        CP_WAIT1();
        __syncthreads();
        if (kt + 2 < KT) load_st((kt + 2) * 32, (kt + 2) % 3);
        CP_COMMIT();
        const int buf = kt % 3;
        const bf16* ab_base = As_b + buf * TSZ;
        const bf16* as_base = As_s + buf * TSZ;
        const bf16* bb_base = Bs_b + buf * TSZ;
        const bf16* bs_base = Bs_s + buf * TSZ;
#pragma unroll
        for (int kk = 0; kk < 32; kk += 16) {
            unsigned ab[2][4], as_[2][4], bb[8][2], bs_[8][2];
#pragma unroll
            for (int am = 0; am < 2; am++) {
                ldsm_x4(ab[am][0], ab[am][1], ab[am][2], ab[am][3],
                        ab_base + (arow + am * 16) * APITCH + kk + acolsel);
                ldsm_x4(as_[am][0], as_[am][1], as_[am][2], as_[am][3],
                        as_base + (arow + am * 16) * APITCH + kk + acolsel);
            }
#pragma unroll
            for (int p = 0; p < 4; p++) {
                ldsm_x4(bb[2 * p][0], bb[2 * p][1], bb[2 * p + 1][0], bb[2 * p + 1][1],
                        bb_base + (wn * 64 + p * 16 + brow) * APITCH + kk + bcolsel);
                ldsm_x4(bs_[2 * p][0], bs_[2 * p][1], bs_[2 * p + 1][0], bs_[2 * p + 1][1],
                        bs_base + (wn * 64 + p * 16 + brow) * APITCH + kk + bcolsel);
            }
#pragma unroll
            for (int am = 0; am < 2; am++)
#pragma unroll
                for (int an = 0; an < 8; an++) {
                    mma16816(acc[am][an], ab[am], bb[an]);
                    mma16816(acc[am][an], ab[am], bs_[an]);
                    mma16816(acc[am][an], as_[am], bb[an]);
                }
        }
    }

    // ---------------- epilogue ----------------
    int tgt = 0;
    const float* biasp = bias;
    bf16* tob = outb;
    bf16* tos = outs;
    float al = alpha;
    if constexpr (MODE == 1) {
        tgt = n0 >> 8;
        biasp = (tgt == 0) ? bias : (tgt == 1 ? bias2 : bias3);
        tob = (tgt == 0) ? g_qb : (tgt == 1 ? g_kb : g_vb);
        tos = (tgt == 0) ? g_qs : (tgt == 1 ? g_ks : g_vs);
        al = (tgt == 0) ? 0.125f : 1.0f;
    }

#pragma unroll
    for (int am = 0; am < 2; am++) {
#pragma unroll
        for (int rr = 0; rr < 2; rr++) {
            int row = m0 + wm * 32 + am * 16 + g + rr * 8;
#pragma unroll
            for (int an = 0; an < 8; an++) {
                int col0 = n0 + wn * 64 + an * 8 + 2 * tig;
                if constexpr (MODE == 0) {
                    float v0 = (acc[am][an][rr * 2 + 0] + bias[col0]) * alpha;
                    float v1 = (acc[am][an][rr * 2 + 1] + bias[col0 + 1]) * alpha;
                    if (relu) { v0 = fmaxf(v0, 0.f); v1 = fmaxf(v1, 0.f); }
                    if (outf) {
                        outf[(size_t)row * N + col0] = v0;
                        outf[(size_t)row * N + col0 + 1] = v1;
                    }
                    if (outb) {
                        unsigned ub, us;
                        cvt2(v0, v1, ub, us);
                        *reinterpret_cast<unsigned*>(&outb[(size_t)row * N + col0]) = ub;
                        *reinterpret_cast<unsigned*>(&outs[(size_t)row * N + col0]) = us;
                    }
                } else if constexpr (MODE == 1) {
                    int lc = col0 - tgt * 256;
                    float v0 = (acc[am][an][rr * 2 + 0] + biasp[lc]) * al;
                    float v1 = (acc[am][an][rr * 2 + 1] + biasp[lc + 1]) * al;
                    unsigned ub, us;
                    cvt2(v0, v1, ub, us);
                    *reinterpret_cast<unsigned*>(&tob[(size_t)row * C + lc]) = ub;
                    *reinterpret_cast<unsigned*>(&tos[(size_t)row * C + lc]) = us;
                } else {  // MODE 3
                    int bb2 = row >> 10, tt = row & (T - 1);
                    float mk = (tt < lens[bb2]) ? 1.0f : 0.0f;
#pragma unroll
                    for (int cc = 0; cc < 2; cc++) {
                        int col = col0 + cc;
                        float vv = (acc[am][an][rr * 2 + cc] + bias[col]) * mk;
                        if (col < OUT)
                            outf[((size_t)bb2 * OUT + col) * T + tt] = vv;
                        else
                            out2[((size_t)bb2 * OUT + (col - OUT)) * T + tt] = vv;
                    }
                }
            }
        }
    }
}

// =====================================================================
//  Flash attention: 3-stage cp.async K/V, V row-major + ldsm.trans
// =====================================================================
constexpr int QPITCH = 72;
constexpr int KVT = 64 * QPITCH;  // 4608 elems per (tensor, stage)
constexpr int FLASH_SMEM = (2 * 128 * QPITCH + 12 * KVT) * (int)sizeof(bf16);  // 147456

__global__ __launch_bounds__(256, 1) void flash_attn(
    const int* __restrict__ lens, const float* __restrict__ relk,
    const float* __restrict__ relv) {
    extern __shared__ bf16 fsm[];
    bf16* Qb = fsm;                        // [128][72]
    bf16* Qs = fsm + 9216;
    bf16* Ktb = fsm + 18432;               // [3][64][72]
    bf16* Kts = fsm + 18432 + 3 * KVT;
    bf16* Vtb = fsm + 18432 + 6 * KVT;     // [3][64][72] row-major [k][c]
    bf16* Vts = fsm + 18432 + 9 * KVT;
    __shared__ float qrel_s[128 * NREL];
    __shared__ float relk_s[NREL * HD];
    __shared__ float relv_s[NREL * HD];

    const int tid = threadIdx.x, lane = tid & 31, w = tid >> 5;
    const int g = lane >> 2, tig = lane & 3;
    const unsigned qm = 0xFu << (lane & 28);
    const int m0 = blockIdx.x * 128;
    const int bh = blockIdx.y, b = bh >> 2, h = bh & 3;
    const int len = lens[b];
    const int nt = (len + 63) >> 6;

    const int kr = tid >> 2, cq = (tid & 3) * 16;
    auto load_kv = [&](int k0, int st) {
        size_t gi = ((size_t)(b * T + k0 + kr)) * C + h * HD + cq;
        int so = st * KVT + kr * QPITCH + cq;
        cp16(Ktb + so, g_kb + gi);
        cp16(Ktb + so + 8, g_kb + gi + 8);
        cp16(Kts + so, g_ks + gi);
        cp16(Kts + so + 8, g_ks + gi + 8);
        cp16(Vtb + so, g_vb + gi);
        cp16(Vtb + so + 8, g_vb + gi + 8);
        cp16(Vts + so, g_vs + gi);
        cp16(Vts + so + 8, g_vs + gi + 8);
    };

    load_kv(0, 0);
    CP_COMMIT();
    if (nt > 1) load_kv(64, 1);
    CP_COMMIT();

    // ---- load Q tile pair ----
    {
        int row = tid >> 1, half = (tid & 1) * 32;
        const uint2* sb = (const uint2*)(g_qb + ((size_t)(b * T + m0 + row)) * C + h * HD + half);
        const uint2* ss = (const uint2*)(g_qs + ((size_t)(b * T + m0 + row)) * C + h * HD + half);
        uint2* db = (uint2*)(Qb + row * QPITCH + half);
        uint2* ds = (uint2*)(Qs + row * QPITCH + half);
#pragma unroll
        for (int i = 0; i < 8; i++) { db[i] = sb[i]; ds[i] = ss[i]; }
    }
    for (int i = tid; i < NREL * HD; i += 256) { relk_s[i] = relk[i]; relv_s[i] = relv[i]; }
    __syncthreads();

    // ---- qrel[r][d] = q[r] . rel_k[d] ----
    for (int i = tid; i < 128 * NREL; i += 256) {
        int r = i / NREL, d = i % NREL;
        const bf16* qb = Qb + r * QPITCH;
        const bf16* qs = Qs + r * QPITCH;
        float s = 0.f;
#pragma unroll
        for (int c = 0; c < HD; c++)
            s += (__bfloat162float(qb[c]) + __bfloat162float(qs[c])) * relk_s[d * HD + c];
        qrel_s[i] = s;
    }

    const int arow = w * 16 + (lane & 7) + ((lane & 8) ? 8 : 0);
    const int acolsel = (lane & 16) ? 8 : 0;
    const int brow = (lane & 7) + ((lane & 16) ? 8 : 0);
    const int bcolsel = (lane & 8) ? 8 : 0;
    const int vrow = (lane & 7) + ((lane & 8) ? 8 : 0);
    const int vcol = (lane & 16) ? 8 : 0;
    unsigned qfb[4][4], qfs[4][4];
#pragma unroll
    for (int s2 = 0; s2 < 4; s2++) {
        ldsm_x4(qfb[s2][0], qfb[s2][1], qfb[s2][2], qfb[s2][3],
                Qb + arow * QPITCH + s2 * 16 + acolsel);
        ldsm_x4(qfs[s2][0], qfs[s2][1], qfs[s2][2], qfs[s2][3],
                Qs + arow * QPITCH + s2 * 16 + acolsel);
    }

    float oacc[8][4] = {};
    float mrow[2] = {-1e30f, -1e30f}, lrow[2] = {0.f, 0.f};

    for (int it = 0; it < nt; it++) {
        const int k0 = it * 64;
        CP_WAIT1();
        __syncthreads();
        if (it + 2 < nt) load_kv((it + 2) * 64, (it + 2) % 3);
        CP_COMMIT();
        const int st = it % 3;

        // ---- S = Q K^T (bf16x3) ----
        float sacc[8][4] = {};
#pragma unroll
        for (int s2 = 0; s2 < 4; s2++) {
            unsigned kb[8][2], km[8][2];
#pragma unroll
            for (int p = 0; p < 4; p++) {
                ldsm_x4(kb[2 * p][0], kb[2 * p][1], kb[2 * p + 1][0], kb[2 * p + 1][1],
                        Ktb + st * KVT + (p * 16 + brow) * QPITCH + s2 * 16 + bcolsel);
                ldsm_x4(km[2 * p][0], km[2 * p][1], km[2 * p + 1][0], km[2 * p + 1][1],
                        Kts + st * KVT + (p * 16 + brow) * QPITCH + s2 * 16 + bcolsel);
            }
#pragma unroll
            for (int an = 0; an < 8; an++) {
                mma16816(sacc[an], qfb[s2], kb[an]);
                mma16816(sacc[an], qfb[s2], km[an]);
                mma16816(sacc[an], qfs[s2], kb[an]);
            }
        }

        // ---- bias + mask ----
#pragma unroll
        for (int rr = 0; rr < 2; rr++) {
            int lr = w * 16 + g + rr * 8;
            int qg = m0 + lr;
#pragma unroll
            for (int an = 0; an < 8; an++) {
#pragma unroll
                for (int cc = 0; cc < 2; cc++) {
                    int col = k0 + an * 8 + 2 * tig + cc;
                    float s = sacc[an][rr * 2 + cc];
                    int d = col - qg;
                    if (d >= -4 && d <= 4) s += qrel_s[lr * NREL + d + 4];
                    if (col >= len) s = -1e30f;
                    sacc[an][rr * 2 + cc] = s;
                }
            }
        }

        // ---- online softmax ----
#pragma unroll
        for (int rr = 0; rr < 2; rr++) {
            float mx = -1e30f;
#pragma unroll
            for (int an = 0; an < 8; an++) {
                mx = fmaxf(mx, sacc[an][rr * 2 + 0]);
                mx = fmaxf(mx, sacc[an][rr * 2 + 1]);
            }
            mx = fmaxf(mx, __shfl_xor_sync(qm, mx, 1));
            mx = fmaxf(mx, __shfl_xor_sync(qm, mx, 2));
            float mnew = fmaxf(mrow[rr], mx);
            float corr = __expf(mrow[rr] - mnew);
            mrow[rr] = mnew;
            float rs = 0.f;
#pragma unroll
            for (int an = 0; an < 8; an++) {
#pragma unroll
                for (int cc = 0; cc < 2; cc++) {
                    float p = __expf(sacc[an][rr * 2 + cc] - mnew);
                    sacc[an][rr * 2 + cc] = p;
                    rs += p;
                }
            }
            lrow[rr] = lrow[rr] * corr + rs;
#pragma unroll
            for (int an = 0; an < 8; an++) {
                oacc[an][rr * 2 + 0] *= corr;
                oacc[an][rr * 2 + 1] *= corr;
            }
        }

        // ---- P -> A fragments ----
        unsigned pfb[4][4], pfs[4][4];
#pragma unroll
        for (int s2 = 0; s2 < 4; s2++) {
            cvt2(sacc[2 * s2][0], sacc[2 * s2][1], pfb[s2][0], pfs[s2][0]);
            cvt2(sacc[2 * s2][2], sacc[2 * s2][3], pfb[s2][1], pfs[s2][1]);
            cvt2(sacc[2 * s2 + 1][0], sacc[2 * s2 + 1][1], pfb[s2][2], pfs[s2][2]);
            cvt2(sacc[2 * s2 + 1][2], sacc[2 * s2 + 1][3], pfb[s2][3], pfs[s2][3]);
        }

        // ---- O += P V ----
#pragma unroll
        for (int s2 = 0; s2 < 4; s2++) {
            unsigned vb[8][2], vs2[8][2];
#pragma unroll
            for (int p = 0; p < 4; p++) {
                ldsm_x4_t(vb[2 * p][0], vb[2 * p][1], vb[2 * p + 1][0], vb[2 * p + 1][1],
                          Vtb + st * KVT + (s2 * 16 + vrow) * QPITCH + p * 16 + vcol);
                ldsm_x4_t(vs2[2 * p][0], vs2[2 * p][1], vs2[2 * p + 1][0], vs2[2 * p + 1][1],
                          Vts + st * KVT + (s2 * 16 + vrow) * QPITCH + p * 16 + vcol);
            }
#pragma unroll
            for (int an = 0; an < 8; an++) {
                mma16816(oacc[an], pfb[s2], vb[an]);
                mma16816(oacc[an], pfb[s2], vs2[an]);
                mma16816(oacc[an], pfs[s2], vb[an]);
            }
        }
    }

    // ---- finalize ----
    float linv[2];
#pragma unroll
    for (int rr = 0; rr < 2; rr++) {
        float lv = lrow[rr];
        lv += __shfl_xor_sync(qm, lv, 1);
        lv += __shfl_xor_sync(qm, lv, 2);
        linv[rr] = 1.0f / lv;
#pragma unroll
        for (int an = 0; an < 8; an++) {
            oacc[an][rr * 2 + 0] *= linv[rr];
            oacc[an][rr * 2 + 1] *= linv[rr];
        }
    }

#pragma unroll
    for (int rr = 0; rr < 2; rr++) {
        int lr = w * 16 + g + rr * 8;
        int qg = m0 + lr;
#pragma unroll
        for (int j = 0; j < NREL; j++) {
            int k = qg + j - 4;
            if (k < 0 || k >= len) continue;
            const bf16* kbp = g_kb + ((size_t)(b * T + k)) * C + h * HD;
            const bf16* ksp = g_ks + ((size_t)(b * T + k)) * C + h * HD;
            float part = 0.f;
#pragma unroll
            for (int c = tig * 16; c < tig * 16 + 16; c++) {
                float qv = __bfloat162float(Qb[lr * QPITCH + c]) +
                           __bfloat162float(Qs[lr * QPITCH + c]);
                float kv = __bfloat162float(kbp[c]) + __bfloat162float(ksp[c]);
                part += qv * kv;
            }
            part += __shfl_xor_sync(qm, part, 1);
            part += __shfl_xor_sync(qm, part, 2);
            float p = __expf(part + qrel_s[lr * NREL + j] - mrow[rr]) * linv[rr];
#pragma unroll
            for (int an = 0; an < 8; an++) {
                int c0 = an * 8 + 2 * tig;
                oacc[an][rr * 2 + 0] += p * relv_s[j * HD + c0];
                oacc[an][rr * 2 + 1] += p * relv_s[j * HD + c0 + 1];
            }
        }
#pragma unroll
        for (int an = 0; an < 8; an++) {
            int c0 = an * 8 + 2 * tig;
            unsigned ub, us;
            cvt2(oacc[an][rr * 2 + 0], oacc[an][rr * 2 + 1], ub, us);
            size_t o = ((size_t)(b * T + qg)) * C + h * HD + c0;
            *reinterpret_cast<unsigned*>(&g_ab[o]) = ub;
            *reinterpret_cast<unsigned*>(&g_as[o]) = us;
        }
    }
}

// ---------------- LN warp-per-row ----------------
__global__ void ln_res_kernel(float* __restrict__ x, const float* __restrict__ r,
                              const float* __restrict__ gg, const float* __restrict__ beta,
                              const int* __restrict__ lens, int apply_mask) {
    int row = blockIdx.x * 8 + (threadIdx.x >> 5);
    int lane = threadIdx.x & 31;
    const float4* xr = (const float4*)(x + (size_t)row * C);
    const float4* rr = (const float4*)(r + (size_t)row * C);
    float4 a0 = xr[lane], a1 = xr[lane + 32];
    float4 b0 = rr[lane], b1 = rr[lane + 32];
    float v[8] = {a0.x + b0.x, a0.y + b0.y, a0.z + b0.z, a0.w + b0.w,
                  a1.x + b1.x, a1.y + b1.y, a1.z + b1.z, a1.w + b1.w};
    float s = 0.f;
#pragma unroll
    for (int i = 0; i < 8; i++) s += v[i];
    float mean = warpReduceSum(s) * (1.0f / C);
    float sq = 0.f;
#pragma unroll
    for (int i = 0; i < 8; i++) {
        float d = v[i] - mean;
        sq += d * d;
    }
    float inv = rsqrtf(warpReduceSum(sq) * (1.0f / C) + 1e-5f);
    float zero = 1.0f;
    if (apply_mask) {
        int b = row >> 10, t = row & (T - 1);
        if (t >= lens[b]) zero = 0.0f;
    }
    const float4* gp = (const float4*)gg;
    const float4* bp = (const float4*)beta;
    float4 g0 = gp[lane], g1 = gp[lane + 32];
    float4 e0 = bp[lane], e1 = bp[lane + 32];
    float gv[8] = {g0.x, g0.y, g0.z, g0.w, g1.x, g1.y, g1.z, g1.w};
    float ev[8] = {e0.x, e0.y, e0.z, e0.w, e1.x, e1.y, e1.z, e1.w};
    float y[8];
#pragma unroll
    for (int i = 0; i < 8; i++) y[i] = ((v[i] - mean) * inv * gv[i] + ev[i]) * zero;

    float4* xo = (float4*)(x + (size_t)row * C);
    xo[lane] = make_float4(y[0], y[1], y[2], y[3]);
    xo[lane + 32] = make_float4(y[4], y[5], y[6], y[7]);
    unsigned* pb16 = (unsigned*)(g_xb + (size_t)row * C);
    unsigned* ps16 = (unsigned*)(g_xs + (size_t)row * C);
#pragma unroll
    for (int i = 0; i < 4; i += 2) {
        unsigned ub, us;
        cvt2(y[i], y[i + 1], ub, us);
        pb16[lane * 2 + i / 2] = ub;
        ps16[lane * 2 + i / 2] = us;
    }
#pragma unroll
    for (int i = 4; i < 8; i += 2) {
        unsigned ub, us;
        cvt2(y[i], y[i + 1], ub, us);
        pb16[64 + lane * 2 + (i - 4) / 2] = ub;
        ps16[64 + lane * 2 + (i - 4) / 2] = us;
    }
}

// ---------------- x (B,T,C) -> out (B,C,T) ----------------
__global__ void transpose_kernel(const float* __restrict__ x, float* __restrict__ out) {
    __shared__ float tile[32][33];
    int b = blockIdx.z;
    int t0 = blockIdx.x * 32, c0 = blockIdx.y * 32;
    int tx = threadIdx.x, ty = threadIdx.y;
#pragma unroll
    for (int i = 0; i < 32; i += 8)
        tile[ty + i][tx] = x[(size_t)(b * T + t0 + ty + i) * C + c0 + tx];
    __syncthreads();
#pragma unroll
    for (int i = 0; i < 32; i += 8)
        out[(size_t)(b * C + c0 + ty + i) * T + t0 + tx] = tile[tx][ty + i];
}

__global__ void mask_out_kernel(const int* __restrict__ lens, float* __restrict__ out_mask) {
    int b = blockIdx.x;
    int len = lens[b];
    for (int t = threadIdx.x; t < T; t += blockDim.x)
        out_mask[(size_t)b * T + t] = (t < len) ? 1.0f : 0.0f;
}

}  // namespace

extern "C" void kernel_launch(void* const* d_in, const int* in_sizes, int n_in,
                              void* d_out, int out_size) {
    (void)in_sizes; (void)n_in; (void)out_size;
    const float* emb   = (const float*)d_in[0];
    const float* Wq    = (const float*)d_in[1];
    const float* Wk    = (const float*)d_in[2];
    const float* Wv    = (const float*)d_in[3];
    const float* Wo    = (const float*)d_in[4];
    const float* bq    = (const float*)d_in[5];
    const float* bk    = (const float*)d_in[6];
    const float* bv    = (const float*)d_in[7];
    const float* bo    = (const float*)d_in[8];
    const float* rel_k = (const float*)d_in[9];
    const float* rel_v = (const float*)d_in[10];
    const float* ln1_g = (const float*)d_in[11];
    const float* ln1_b = (const float*)d_in[12];
    const float* ln2_g = (const float*)d_in[13];
    const float* ln2_b = (const float*)d_in[14];
    const float* fw1   = (const float*)d_in[15];
    const float* fb1   = (const float*)d_in[16];
    const float* fw2   = (const float*)d_in[17];
    const float* fb2   = (const float*)d_in[18];
    const float* pw    = (const float*)d_in[19];
    const float* pb    = (const float*)d_in[20];
    const int*   toks  = (const int*)d_in[21];
    const int*   lens  = (const int*)d_in[22];

    cudaFuncSetAttribute(mma_gemm_p<0>, cudaFuncAttributeMaxDynamicSharedMemorySize, SMEM_BYTES);
    cudaFuncSetAttribute(mma_gemm_p<1>, cudaFuncAttributeMaxDynamicSharedMemorySize, SMEM_BYTES);
    cudaFuncSetAttribute(mma_gemm_p<3>, cudaFuncAttributeMaxDynamicSharedMemorySize, SMEM_BYTES);
    cudaFuncSetAttribute(flash_attn, cudaFuncAttributeMaxDynamicSharedMemorySize, FLASH_SMEM);

    float *px, *ptmp;
    bf16 *pwb, *pws, *pxb, *pxs, *pab, *pas, *pfb, *pfs;
    cudaGetSymbolAddress((void**)&px,   g_x);
    cudaGetSymbolAddress((void**)&ptmp, g_tmp);
    cudaGetSymbolAddress((void**)&pwb,  g_wb);
    cudaGetSymbolAddress((void**)&pws,  g_ws);
    cudaGetSymbolAddress((void**)&pxb,  g_xb);
    cudaGetSymbolAddress((void**)&pxs,  g_xs);
    cudaGetSymbolAddress((void**)&pab,  g_ab);
    cudaGetSymbolAddress((void**)&pas,  g_as);
    cudaGetSymbolAddress((void**)&pfb,  g_fb);
    cudaGetSymbolAddress((void**)&pfs,  g_fs);

    float* out      = (float*)d_out;
    float* out_x    = out;
    float* out_m    = out + (size_t)B * C * T;
    float* out_logs = out_m + (size_t)B * OUT * T;
    float* out_mask = out_logs + (size_t)B * OUT * T;

    dim3 wcb(32, 8);
    wconv_t<<<dim3(C / 32, C / 32, L), wcb>>>(Wq, pwb + OFF_QKV, pws + OFF_QKV, C, C,
                                              (size_t)3 * C * C);
    wconv_t<<<dim3(C / 32, C / 32, L), wcb>>>(Wk, pwb + OFF_QKV + C * C, pws + OFF_QKV + C * C,
                                              C, C, (size_t)3 * C * C);
    wconv_t<<<dim3(C / 32, C / 32, L), wcb>>>(Wv, pwb + OFF_QKV + 2 * C * C,
                                              pws + OFF_QKV + 2 * C * C, C, C,
                                              (size_t)3 * C * C);
    wconv_t<<<dim3(C / 32, C / 32, L), wcb>>>(Wo, pwb + OFF_WO, pws + OFF_WO, C, C,
                                              (size_t)C * C);
    wconv_t<<<dim3(FC / 32, C / 32, L), wcb>>>(fw1, pwb + OFF_F1, pws + OFF_F1, C, FC,
                                               (size_t)C * FC);
    wconv_t<<<dim3(C / 32, FC / 32, L), wcb>>>(fw2, pwb + OFF_F2, pws + OFF_F2, FC, C,
                                               (size_t)FC * C);
    projconv<<<(2 * OUT * C + 255) / 256, 256>>>(pw);

    embed_kernel<<<BT, C>>>(emb, toks);

    dim3 gQKV(3 * C / 128, BT / 128);
    dim3 gC(C / 128, BT / 128);
    dim3 gFC(FC / 128, BT / 128);

    for (int l = 0; l < L; l++) {
        size_t qkv = OFF_QKV + (size_t)l * 3 * C * C;
        size_t wo = OFF_WO + (size_t)l * C * C;
        size_t f1 = OFF_F1 + (size_t)l * C * FC;
        size_t f2 = OFF_F2 + (size_t)l * FC * C;

        mma_gemm_p<1><<<gQKV, 256, SMEM_BYTES>>>(
            pxb, pxs, pwb + qkv, pws + qkv, bq + (size_t)l * C, bk + (size_t)l * C,
            bv + (size_t)l * C, nullptr, nullptr, nullptr, nullptr, BT, 3 * C, C, 1.0f, 0,
            nullptr);

        flash_attn<<<dim3(T / 128, B * H), 256, FLASH_SMEM>>>(
            lens, rel_k + (size_t)l * NREL * HD, rel_v + (size_t)l * NREL * HD);

        mma_gemm_p<0><<<gC, 256, SMEM_BYTES>>>(pab, pas, pwb + wo, pws + wo,
                                               bo + (size_t)l * C, nullptr, nullptr, ptmp,
                                               nullptr, nullptr, nullptr, BT, C, C, 1.0f, 0,
                                               nullptr);
        ln_res_kernel<<<BT / 8, 256>>>(px, ptmp, ln1_g + (size_t)l * C, ln1_b + (size_t)l * C,
                                       lens, 0);

        mma_gemm_p<0><<<gFC, 256, SMEM_BYTES>>>(pxb, pxs, pwb + f1, pws + f1,
                                                fb1 + (size_t)l * FC, nullptr, nullptr, nullptr,
                                                pfb, pfs, nullptr, BT, FC, C, 1.0f, 1, nullptr);
        mma_gemm_p<0><<<gC, 256, SMEM_BYTES>>>(pfb, pfs, pwb + f2, pws + f2,
                                               fb2 + (size_t)l * C, nullptr, nullptr, ptmp,
                                               nullptr, nullptr, nullptr, BT, C, FC, 1.0f, 0,
                                               nullptr);
        ln_res_kernel<<<BT / 8, 256>>>(px, ptmp, ln2_g + (size_t)l * C, ln2_b + (size_t)l * C,
                                       lens, 1);
    }

    transpose_kernel<<<dim3(T / 32, C / 32, B), dim3(32, 8)>>>(px, out_x);
    mma_gemm_p<3><<<dim3(2 * OUT / 128, BT / 128), 256, SMEM_BYTES>>>(
        pxb, pxs, pwb + OFF_PJ, pws + OFF_PJ, pb, nullptr, nullptr, out_m, nullptr, nullptr,
        out_logs, BT, 2 * OUT, C, 1.0f, 0, lens);
    mask_out_kernel<<<B, 256>>>(lens, out_mask);
}

// round 13
// speedup vs baseline: 2.4291x; 1.0188x over previous
#include <cuda_runtime.h>
#include <cuda_bf16.h>
#include <math.h>

namespace {

constexpr int C = 256, H = 4, HD = 64, L = 6, FC = 1024, OUT = 192;
constexpr int B = 8, T = 1024, BT = B * T, NREL = 9;

typedef __nv_bfloat16 bf16;

// ---------------- weight pair storage (QKV concatenated per layer) ----------------
constexpr size_t OFF_QKV = 0;
constexpr size_t OFF_WO  = (size_t)L * 3 * C * C;
constexpr size_t OFF_F1  = OFF_WO + (size_t)L * C * C;
constexpr size_t OFF_F2  = OFF_F1 + (size_t)L * C * FC;
constexpr size_t OFF_PJ  = OFF_F2 + (size_t)L * FC * C;
constexpr size_t WTOT    = OFF_PJ + (size_t)2 * OUT * C;

__device__ bf16 g_wb[WTOT];
__device__ bf16 g_ws[WTOT];

// ---------------- activation scratch ----------------
__device__ float g_x[BT * C];
__device__ float g_tmp[BT * C];
__device__ bf16 g_xb[BT * C], g_xs[BT * C];
__device__ bf16 g_qb[BT * C], g_qs[BT * C];
__device__ bf16 g_kb[BT * C], g_ks[BT * C];
__device__ bf16 g_vb[BT * C], g_vs[BT * C];
__device__ bf16 g_ab[BT * C], g_as[BT * C];
__device__ bf16 g_fb[BT * FC], g_fs[BT * FC];

// ---------------- helpers ----------------
__device__ __forceinline__ float warpReduceSum(float v) {
#pragma unroll
    for (int o = 16; o; o >>= 1) v += __shfl_xor_sync(0xffffffffu, v, o);
    return v;
}

__device__ __forceinline__ void cvt2(float a, float b, unsigned& ub, unsigned& us) {
    __nv_bfloat162 hb, hs;
    hb.x = __float2bfloat16_rn(a);
    hb.y = __float2bfloat16_rn(b);
    float ra = a - __bfloat162float(hb.x);
    float rb = b - __bfloat162float(hb.y);
    hs.x = __float2bfloat16_rn(ra);
    hs.y = __float2bfloat16_rn(rb);
    ub = *reinterpret_cast<unsigned*>(&hb);
    us = *reinterpret_cast<unsigned*>(&hs);
}

__device__ __forceinline__ void mma16816(float c[4], const unsigned a[4], const unsigned b2[2]) {
    asm volatile(
        "mma.sync.aligned.m16n8k16.row.col.f32.bf16.bf16.f32 "
        "{%0,%1,%2,%3}, {%4,%5,%6,%7}, {%8,%9}, {%0,%1,%2,%3};\n"
        : "+f"(c[0]), "+f"(c[1]), "+f"(c[2]), "+f"(c[3])
        : "r"(a[0]), "r"(a[1]), "r"(a[2]), "r"(a[3]), "r"(b2[0]), "r"(b2[1]));
}

__device__ __forceinline__ void ldsm_x4(unsigned& r0, unsigned& r1, unsigned& r2, unsigned& r3,
                                        const void* p) {
    unsigned addr = (unsigned)__cvta_generic_to_shared(p);
    asm volatile("ldmatrix.sync.aligned.m8n8.x4.shared.b16 {%0,%1,%2,%3}, [%4];"
                 : "=r"(r0), "=r"(r1), "=r"(r2), "=r"(r3)
                 : "r"(addr));
}
__device__ __forceinline__ void ldsm_x4_t(unsigned& r0, unsigned& r1, unsigned& r2, unsigned& r3,
                                          const void* p) {
    unsigned addr = (unsigned)__cvta_generic_to_shared(p);
    asm volatile("ldmatrix.sync.aligned.m8n8.x4.trans.shared.b16 {%0,%1,%2,%3}, [%4];"
                 : "=r"(r0), "=r"(r1), "=r"(r2), "=r"(r3)
                 : "r"(addr));
}
__device__ __forceinline__ void cp16(void* s, const void* g) {
    unsigned a = (unsigned)__cvta_generic_to_shared(s);
    asm volatile("cp.async.cg.shared.global [%0], [%1], 16;" :: "r"(a), "l"(g));
}
#define CP_COMMIT() asm volatile("cp.async.commit_group;")

// =====================================================================
//  prep kernel: all weight conversions + embedding in ONE launch.
//  Block ranges: Wq 384 | Wk 384 | Wv 384 | Wo 384 | fw1 1536 | fw2 1536
//                | proj 384 | embed 1024   (total 6016)
// =====================================================================
__device__ void wconv_blk(const float* __restrict__ w, bf16* __restrict__ ob,
                          bf16* __restrict__ os, int K, int N, size_t lstride, int bx) {
    __shared__ float tile[32][33];
    int nx = N / 32, ny = K / 32;
    int l = bx / (nx * ny);
    int rem = bx % (nx * ny);
    int y = rem / nx, x = rem % nx;
    const float* src = w + (size_t)l * K * N;
    int k0 = y * 32, n0 = x * 32;
    int tx = threadIdx.x & 31, ty = threadIdx.x >> 5;
#pragma unroll
    for (int i = 0; i < 32; i += 8)
        tile[ty + i][tx] = src[(size_t)(k0 + ty + i) * N + n0 + tx];
    __syncthreads();
#pragma unroll
    for (int i = 0; i < 32; i += 8) {
        float v = tile[tx][ty + i];
        size_t o = (size_t)l * lstride + (size_t)(n0 + ty + i) * K + k0 + tx;
        bf16 hb = __float2bfloat16_rn(v);
        ob[o] = hb;
        os[o] = __float2bfloat16_rn(v - __bfloat162float(hb));
    }
}

__global__ void prep_kernel(const float* __restrict__ Wq, const float* __restrict__ Wk,
                            const float* __restrict__ Wv, const float* __restrict__ Wo,
                            const float* __restrict__ fw1, const float* __restrict__ fw2,
                            const float* __restrict__ pw, const float* __restrict__ emb,
                            const int* __restrict__ toks) {
    int bx = blockIdx.x;
    if (bx < 384) { wconv_blk(Wq, g_wb + OFF_QKV, g_ws + OFF_QKV, C, C, (size_t)3 * C * C, bx); return; }
    bx -= 384;
    if (bx < 384) { wconv_blk(Wk, g_wb + OFF_QKV + C * C, g_ws + OFF_QKV + C * C, C, C, (size_t)3 * C * C, bx); return; }
    bx -= 384;
    if (bx < 384) { wconv_blk(Wv, g_wb + OFF_QKV + 2 * C * C, g_ws + OFF_QKV + 2 * C * C, C, C, (size_t)3 * C * C, bx); return; }
    bx -= 384;
    if (bx < 384) { wconv_blk(Wo, g_wb + OFF_WO, g_ws + OFF_WO, C, C, (size_t)C * C, bx); return; }
    bx -= 384;
    if (bx < 1536) { wconv_blk(fw1, g_wb + OFF_F1, g_ws + OFF_F1, C, FC, (size_t)C * FC, bx); return; }
    bx -= 1536;
    if (bx < 1536) { wconv_blk(fw2, g_wb + OFF_F2, g_ws + OFF_F2, FC, C, (size_t)FC * C, bx); return; }
    bx -= 1536;
    if (bx < 384) {  // proj conversion
        int i = bx * 256 + threadIdx.x;
        if (i < 2 * OUT * C) {
            float v = pw[i];
            bf16 hb = __float2bfloat16_rn(v);
            g_wb[OFF_PJ + i] = hb;
            g_ws[OFF_PJ + i] = __float2bfloat16_rn(v - __bfloat162float(hb));
        }
        return;
    }
    bx -= 384;
    // embed: 1024 blocks, 2048 elements each
#pragma unroll
    for (int j = 0; j < 8; j++) {
        int idx = bx * 2048 + j * 256 + threadIdx.x;
        int bt = idx >> 8, c = idx & 255;
        float v = emb[(size_t)toks[bt] * C + c] * 16.0f;
        g_x[idx] = v;
        bf16 hb = __float2bfloat16_rn(v);
        g_xb[idx] = hb;
        g_xs[idx] = __float2bfloat16_rn(v - __bfloat162float(hb));
    }
}

// =====================================================================
//  Pair-input bf16x3 GEMM: 128x128 tile, BK=32, 256 threads,
//  2-stage cp.async, __launch_bounds__(256,2) for 2 CTAs/SM.
// =====================================================================
constexpr int APITCH = 40;
constexpr int TSZ = 128 * APITCH;                                 // per tensor per stage
constexpr int SMEM_BYTES = 8 * TSZ * (int)sizeof(bf16);           // 4 tensors * 2 stages = 81920

template <int MODE>
__global__ __launch_bounds__(256, 2) void mma_gemm_p(
    const bf16* __restrict__ Ab, const bf16* __restrict__ As2,
    const bf16* __restrict__ Bb, const bf16* __restrict__ Bs2,
    const float* __restrict__ bias, const float* __restrict__ bias2,
    const float* __restrict__ bias3, float* __restrict__ outf,
    bf16* __restrict__ outb, bf16* __restrict__ outs, float* __restrict__ out2,
    int M, int N, int K, float alpha, int relu, const int* __restrict__ lens) {
    extern __shared__ bf16 dsm[];
    bf16* As_b = dsm;                 // [2][128][40]
    bf16* As_s = dsm + 2 * TSZ;
    bf16* Bs_b = dsm + 4 * TSZ;
    bf16* Bs_s = dsm + 6 * TSZ;

    const int tid = threadIdx.x;
    const int lane = tid & 31, wid = tid >> 5;
    const int wm = wid >> 1, wn = wid & 1;
    const int g = lane >> 2, tig = lane & 3;
    const int m0 = blockIdx.y * 128, n0 = blockIdx.x * 128;

    const int ar = tid >> 1, akh = (tid & 1) * 16;

    const int lane7 = lane & 7;
    const int arow = wm * 32 + lane7 + ((lane & 8) ? 8 : 0);
    const int acolsel = (lane & 16) ? 8 : 0;
    const int brow = lane7 + ((lane & 16) ? 8 : 0);
    const int bcolsel = (lane & 8) ? 8 : 0;

    float acc[2][8][4] = {};

    auto load_st = [&](int k0, int st) {
        size_t ai = (size_t)(m0 + ar) * K + k0 + akh;
        size_t bi = (size_t)(n0 + ar) * K + k0 + akh;
        int so = st * TSZ + ar * APITCH + akh;
        cp16(As_b + so, Ab + ai);
        cp16(As_b + so + 8, Ab + ai + 8);
        cp16(As_s + so, As2 + ai);
        cp16(As_s + so + 8, As2 + ai + 8);
        cp16(Bs_b + so, Bb + bi);
        cp16(Bs_b + so + 8, Bb + bi + 8);
        cp16(Bs_s + so, Bs2 + bi);
        cp16(Bs_s + so + 8, Bs2 + bi + 8);
    };

    const int KT = K >> 5;
    load_st(0, 0);
    CP_COMMIT();

    for (int kt = 0; kt < KT; kt++) {
        if (kt + 1 < KT) {
            load_st((kt + 1) * 32, (kt + 1) & 1);
            CP_COMMIT();
            asm volatile("cp.async.wait_group 1;");
        } else {
            CP_COMMIT();
            asm volatile("cp.async.wait_group 0;");
        }
        __syncthreads();
        const int buf = kt & 1;
        const bf16* ab_base = As_b + buf * TSZ;
        const bf16* as_base = As_s + buf * TSZ;
        const bf16* bb_base = Bs_b + buf * TSZ;
        const bf16* bs_base = Bs_s + buf * TSZ;
#pragma unroll
        for (int kk = 0; kk < 32; kk += 16) {
            unsigned ab[2][4], as_[2][4], bb[8][2], bs_[8][2];
#pragma unroll
            for (int am = 0; am < 2; am++) {
                ldsm_x4(ab[am][0], ab[am][1], ab[am][2], ab[am][3],
                        ab_base + (arow + am * 16) * APITCH + kk + acolsel);
                ldsm_x4(as_[am][0], as_[am][1], as_[am][2], as_[am][3],
                        as_base + (arow + am * 16) * APITCH + kk + acolsel);
            }
#pragma unroll
            for (int p = 0; p < 4; p++) {
                ldsm_x4(bb[2 * p][0], bb[2 * p][1], bb[2 * p + 1][0], bb[2 * p + 1][1],
                        bb_base + (wn * 64 + p * 16 + brow) * APITCH + kk + bcolsel);
                ldsm_x4(bs_[2 * p][0], bs_[2 * p][1], bs_[2 * p + 1][0], bs_[2 * p + 1][1],
                        bs_base + (wn * 64 + p * 16 + brow) * APITCH + kk + bcolsel);
            }
#pragma unroll
            for (int am = 0; am < 2; am++)
#pragma unroll
                for (int an = 0; an < 8; an++) {
                    mma16816(acc[am][an], ab[am], bb[an]);
                    mma16816(acc[am][an], ab[am], bs_[an]);
                    mma16816(acc[am][an], as_[am], bb[an]);
                }
        }
        __syncthreads();
    }

    // ---------------- epilogue ----------------
    int tgt = 0;
    const float* biasp = bias;
    bf16* tob = outb;
    bf16* tos = outs;
    float al = alpha;
    if constexpr (MODE == 1) {
        tgt = n0 >> 8;
        biasp = (tgt == 0) ? bias : (tgt == 1 ? bias2 : bias3);
        tob = (tgt == 0) ? g_qb : (tgt == 1 ? g_kb : g_vb);
        tos = (tgt == 0) ? g_qs : (tgt == 1 ? g_ks : g_vs);
        al = (tgt == 0) ? 0.125f : 1.0f;
    }

#pragma unroll
    for (int am = 0; am < 2; am++) {
#pragma unroll
        for (int rr = 0; rr < 2; rr++) {
            int row = m0 + wm * 32 + am * 16 + g + rr * 8;
#pragma unroll
            for (int an = 0; an < 8; an++) {
                int col0 = n0 + wn * 64 + an * 8 + 2 * tig;
                if constexpr (MODE == 0) {
                    float v0 = (acc[am][an][rr * 2 + 0] + bias[col0]) * alpha;
                    float v1 = (acc[am][an][rr * 2 + 1] + bias[col0 + 1]) * alpha;
                    if (relu) { v0 = fmaxf(v0, 0.f); v1 = fmaxf(v1, 0.f); }
                    if (outf) {
                        outf[(size_t)row * N + col0] = v0;
                        outf[(size_t)row * N + col0 + 1] = v1;
                    }
                    if (outb) {
                        unsigned ub, us;
                        cvt2(v0, v1, ub, us);
                        *reinterpret_cast<unsigned*>(&outb[(size_t)row * N + col0]) = ub;
                        *reinterpret_cast<unsigned*>(&outs[(size_t)row * N + col0]) = us;
                    }
                } else if constexpr (MODE == 1) {
                    int lc = col0 - tgt * 256;
                    float v0 = (acc[am][an][rr * 2 + 0] + biasp[lc]) * al;
                    float v1 = (acc[am][an][rr * 2 + 1] + biasp[lc + 1]) * al;
                    unsigned ub, us;
                    cvt2(v0, v1, ub, us);
                    *reinterpret_cast<unsigned*>(&tob[(size_t)row * C + lc]) = ub;
                    *reinterpret_cast<unsigned*>(&tos[(size_t)row * C + lc]) = us;
                } else {  // MODE 3
                    int bb2 = row >> 10, tt = row & (T - 1);
                    float mk = (tt < lens[bb2]) ? 1.0f : 0.0f;
#pragma unroll
                    for (int cc = 0; cc < 2; cc++) {
                        int col = col0 + cc;
                        float vv = (acc[am][an][rr * 2 + cc] + bias[col]) * mk;
                        if (col < OUT)
                            outf[((size_t)bb2 * OUT + col) * T + tt] = vv;
                        else
                            out2[((size_t)bb2 * OUT + (col - OUT)) * T + tt] = vv;
                    }
                }
            }
        }
    }
}

// =====================================================================
//  Flash attention: 3-stage cp.async K/V, V row-major + ldsm.trans
// =====================================================================
constexpr int QPITCH = 72;
constexpr int KVT = 64 * QPITCH;
constexpr int FLASH_SMEM = (2 * 128 * QPITCH + 12 * KVT) * (int)sizeof(bf16);  // 147456

__global__ __launch_bounds__(256, 1) void flash_attn(
    const int* __restrict__ lens, const float* __restrict__ relk,
    const float* __restrict__ relv) {
    extern __shared__ bf16 fsm[];
    bf16* Qb = fsm;
    bf16* Qs = fsm + 9216;
    bf16* Ktb = fsm + 18432;
    bf16* Kts = fsm + 18432 + 3 * KVT;
    bf16* Vtb = fsm + 18432 + 6 * KVT;
    bf16* Vts = fsm + 18432 + 9 * KVT;
    __shared__ float qrel_s[128 * NREL];
    __shared__ float relk_s[NREL * HD];
    __shared__ float relv_s[NREL * HD];

    const int tid = threadIdx.x, lane = tid & 31, w = tid >> 5;
    const int g = lane >> 2, tig = lane & 3;
    const unsigned qm = 0xFu << (lane & 28);
    const int m0 = blockIdx.x * 128;
    const int bh = blockIdx.y, b = bh >> 2, h = bh & 3;
    const int len = lens[b];
    const int nt = (len + 63) >> 6;

    const int kr = tid >> 2, cq = (tid & 3) * 16;
    auto load_kv = [&](int k0, int st) {
        size_t gi = ((size_t)(b * T + k0 + kr)) * C + h * HD + cq;
        int so = st * KVT + kr * QPITCH + cq;
        cp16(Ktb + so, g_kb + gi);
        cp16(Ktb + so + 8, g_kb + gi + 8);
        cp16(Kts + so, g_ks + gi);
        cp16(Kts + so + 8, g_ks + gi + 8);
        cp16(Vtb + so, g_vb + gi);
        cp16(Vtb + so + 8, g_vb + gi + 8);
        cp16(Vts + so, g_vs + gi);
        cp16(Vts + so + 8, g_vs + gi + 8);
    };

    load_kv(0, 0);
    CP_COMMIT();
    if (nt > 1) load_kv(64, 1);
    CP_COMMIT();

    {
        int row = tid >> 1, half = (tid & 1) * 32;
        const uint2* sb = (const uint2*)(g_qb + ((size_t)(b * T + m0 + row)) * C + h * HD + half);
        const uint2* ss = (const uint2*)(g_qs + ((size_t)(b * T + m0 + row)) * C + h * HD + half);
        uint2* db = (uint2*)(Qb + row * QPITCH + half);
        uint2* ds = (uint2*)(Qs + row * QPITCH + half);
#pragma unroll
        for (int i = 0; i < 8; i++) { db[i] = sb[i]; ds[i] = ss[i]; }
    }
    for (int i = tid; i < NREL * HD; i += 256) { relk_s[i] = relk[i]; relv_s[i] = relv[i]; }
    __syncthreads();

    for (int i = tid; i < 128 * NREL; i += 256) {
        int r = i / NREL, d = i % NREL;
        const bf16* qb = Qb + r * QPITCH;
        const bf16* qs = Qs + r * QPITCH;
        float s = 0.f;
#pragma unroll
        for (int c = 0; c < HD; c++)
            s += (__bfloat162float(qb[c]) + __bfloat162float(qs[c])) * relk_s[d * HD + c];
        qrel_s[i] = s;
    }

    const int arow = w * 16 + (lane & 7) + ((lane & 8) ? 8 : 0);
    const int acolsel = (lane & 16) ? 8 : 0;
    const int brow = (lane & 7) + ((lane & 16) ? 8 : 0);
    const int bcolsel = (lane & 8) ? 8 : 0;
    const int vrow = (lane & 7) + ((lane & 8) ? 8 : 0);
    const int vcol = (lane & 16) ? 8 : 0;
    unsigned qfb[4][4], qfs[4][4];
#pragma unroll
    for (int s2 = 0; s2 < 4; s2++) {
        ldsm_x4(qfb[s2][0], qfb[s2][1], qfb[s2][2], qfb[s2][3],
                Qb + arow * QPITCH + s2 * 16 + acolsel);
        ldsm_x4(qfs[s2][0], qfs[s2][1], qfs[s2][2], qfs[s2][3],
                Qs + arow * QPITCH + s2 * 16 + acolsel);
    }

    float oacc[8][4] = {};
    float mrow[2] = {-1e30f, -1e30f}, lrow[2] = {0.f, 0.f};

    for (int it = 0; it < nt; it++) {
        const int k0 = it * 64;
        asm volatile("cp.async.wait_group 1;");
        __syncthreads();
        if (it + 2 < nt) load_kv((it + 2) * 64, (it + 2) % 3);
        CP_COMMIT();
        const int st = it % 3;

        float sacc[8][4] = {};
#pragma unroll
        for (int s2 = 0; s2 < 4; s2++) {
            unsigned kb[8][2], km[8][2];
#pragma unroll
            for (int p = 0; p < 4; p++) {
                ldsm_x4(kb[2 * p][0], kb[2 * p][1], kb[2 * p + 1][0], kb[2 * p + 1][1],
                        Ktb + st * KVT + (p * 16 + brow) * QPITCH + s2 * 16 + bcolsel);
                ldsm_x4(km[2 * p][0], km[2 * p][1], km[2 * p + 1][0], km[2 * p + 1][1],
                        Kts + st * KVT + (p * 16 + brow) * QPITCH + s2 * 16 + bcolsel);
            }
#pragma unroll
            for (int an = 0; an < 8; an++) {
                mma16816(sacc[an], qfb[s2], kb[an]);
                mma16816(sacc[an], qfb[s2], km[an]);
                mma16816(sacc[an], qfs[s2], kb[an]);
            }
        }

#pragma unroll
        for (int rr = 0; rr < 2; rr++) {
            int lr = w * 16 + g + rr * 8;
            int qg = m0 + lr;
#pragma unroll
            for (int an = 0; an < 8; an++) {
#pragma unroll
                for (int cc = 0; cc < 2; cc++) {
                    int col = k0 + an * 8 + 2 * tig + cc;
                    float s = sacc[an][rr * 2 + cc];
                    int d = col - qg;
                    if (d >= -4 && d <= 4) s += qrel_s[lr * NREL + d + 4];
                    if (col >= len) s = -1e30f;
                    sacc[an][rr * 2 + cc] = s;
                }
            }
        }

#pragma unroll
        for (int rr = 0; rr < 2; rr++) {
            float mx = -1e30f;
#pragma unroll
            for (int an = 0; an < 8; an++) {
                mx = fmaxf(mx, sacc[an][rr * 2 + 0]);
                mx = fmaxf(mx, sacc[an][rr * 2 + 1]);
            }
            mx = fmaxf(mx, __shfl_xor_sync(qm, mx, 1));
            mx = fmaxf(mx, __shfl_xor_sync(qm, mx, 2));
            float mnew = fmaxf(mrow[rr], mx);
            float corr = __expf(mrow[rr] - mnew);
            mrow[rr] = mnew;
            float rs = 0.f;
#pragma unroll
            for (int an = 0; an < 8; an++) {
#pragma unroll
                for (int cc = 0; cc < 2; cc++) {
                    float p = __expf(sacc[an][rr * 2 + cc] - mnew);
                    sacc[an][rr * 2 + cc] = p;
                    rs += p;
                }
            }
            lrow[rr] = lrow[rr] * corr + rs;
#pragma unroll
            for (int an = 0; an < 8; an++) {
                oacc[an][rr * 2 + 0] *= corr;
                oacc[an][rr * 2 + 1] *= corr;
            }
        }

        unsigned pfb[4][4], pfs[4][4];
#pragma unroll
        for (int s2 = 0; s2 < 4; s2++) {
            cvt2(sacc[2 * s2][0], sacc[2 * s2][1], pfb[s2][0], pfs[s2][0]);
            cvt2(sacc[2 * s2][2], sacc[2 * s2][3], pfb[s2][1], pfs[s2][1]);
            cvt2(sacc[2 * s2 + 1][0], sacc[2 * s2 + 1][1], pfb[s2][2], pfs[s2][2]);
            cvt2(sacc[2 * s2 + 1][2], sacc[2 * s2 + 1][3], pfb[s2][3], pfs[s2][3]);
        }

#pragma unroll
        for (int s2 = 0; s2 < 4; s2++) {
            unsigned vb[8][2], vs2[8][2];
#pragma unroll
            for (int p = 0; p < 4; p++) {
                ldsm_x4_t(vb[2 * p][0], vb[2 * p][1], vb[2 * p + 1][0], vb[2 * p + 1][1],
                          Vtb + st * KVT + (s2 * 16 + vrow) * QPITCH + p * 16 + vcol);
                ldsm_x4_t(vs2[2 * p][0], vs2[2 * p][1], vs2[2 * p + 1][0], vs2[2 * p + 1][1],
                          Vts + st * KVT + (s2 * 16 + vrow) * QPITCH + p * 16 + vcol);
            }
#pragma unroll
            for (int an = 0; an < 8; an++) {
                mma16816(oacc[an], pfb[s2], vb[an]);
                mma16816(oacc[an], pfb[s2], vs2[an]);
                mma16816(oacc[an], pfs[s2], vb[an]);
            }
        }
    }

    float linv[2];
#pragma unroll
    for (int rr = 0; rr < 2; rr++) {
        float lv = lrow[rr];
        lv += __shfl_xor_sync(qm, lv, 1);
        lv += __shfl_xor_sync(qm, lv, 2);
        linv[rr] = 1.0f / lv;
#pragma unroll
        for (int an = 0; an < 8; an++) {
            oacc[an][rr * 2 + 0] *= linv[rr];
            oacc[an][rr * 2 + 1] *= linv[rr];
        }
    }

#pragma unroll
    for (int rr = 0; rr < 2; rr++) {
        int lr = w * 16 + g + rr * 8;
        int qg = m0 + lr;
#pragma unroll
        for (int j = 0; j < NREL; j++) {
            int k = qg + j - 4;
            if (k < 0 || k >= len) continue;
            const bf16* kbp = g_kb + ((size_t)(b * T + k)) * C + h * HD;
            const bf16* ksp = g_ks + ((size_t)(b * T + k)) * C + h * HD;
            float part = 0.f;
#pragma unroll
            for (int c = tig * 16; c < tig * 16 + 16; c++) {
                float qv = __bfloat162float(Qb[lr * QPITCH + c]) +
                           __bfloat162float(Qs[lr * QPITCH + c]);
                float kv = __bfloat162float(kbp[c]) + __bfloat162float(ksp[c]);
                part += qv * kv;
            }
            part += __shfl_xor_sync(qm, part, 1);
            part += __shfl_xor_sync(qm, part, 2);
            float p = __expf(part + qrel_s[lr * NREL + j] - mrow[rr]) * linv[rr];
#pragma unroll
            for (int an = 0; an < 8; an++) {
                int c0 = an * 8 + 2 * tig;
                oacc[an][rr * 2 + 0] += p * relv_s[j * HD + c0];
                oacc[an][rr * 2 + 1] += p * relv_s[j * HD + c0 + 1];
            }
        }
#pragma unroll
        for (int an = 0; an < 8; an++) {
            int c0 = an * 8 + 2 * tig;
            unsigned ub, us;
            cvt2(oacc[an][rr * 2 + 0], oacc[an][rr * 2 + 1], ub, us);
            size_t o = ((size_t)(b * T + qg)) * C + h * HD + c0;
            *reinterpret_cast<unsigned*>(&g_ab[o]) = ub;
            *reinterpret_cast<unsigned*>(&g_as[o]) = us;
        }
    }
}

// ---------------- LN warp-per-row ----------------
__global__ void ln_res_kernel(float* __restrict__ x, const float* __restrict__ r,
                              const float* __restrict__ gg, const float* __restrict__ beta,
                              const int* __restrict__ lens, int apply_mask) {
    int row = blockIdx.x * 8 + (threadIdx.x >> 5);
    int lane = threadIdx.x & 31;
    const float4* xr = (const float4*)(x + (size_t)row * C);
    const float4* rr = (const float4*)(r + (size_t)row * C);
    float4 a0 = xr[lane], a1 = xr[lane + 32];
    float4 b0 = rr[lane], b1 = rr[lane + 32];
    float v[8] = {a0.x + b0.x, a0.y + b0.y, a0.z + b0.z, a0.w + b0.w,
                  a1.x + b1.x, a1.y + b1.y, a1.z + b1.z, a1.w + b1.w};
    float s = 0.f;
#pragma unroll
    for (int i = 0; i < 8; i++) s += v[i];
    float mean = warpReduceSum(s) * (1.0f / C);
    float sq = 0.f;
#pragma unroll
    for (int i = 0; i < 8; i++) {
        float d = v[i] - mean;
        sq += d * d;
    }
    float inv = rsqrtf(warpReduceSum(sq) * (1.0f / C) + 1e-5f);
    float zero = 1.0f;
    if (apply_mask) {
        int b = row >> 10, t = row & (T - 1);
        if (t >= lens[b]) zero = 0.0f;
    }
    const float4* gp = (const float4*)gg;
    const float4* bp = (const float4*)beta;
    float4 g0 = gp[lane], g1 = gp[lane + 32];
    float4 e0 = bp[lane], e1 = bp[lane + 32];
    float gv[8] = {g0.x, g0.y, g0.z, g0.w, g1.x, g1.y, g1.z, g1.w};
    float ev[8] = {e0.x, e0.y, e0.z, e0.w, e1.x, e1.y, e1.z, e1.w};
    float y[8];
#pragma unroll
    for (int i = 0; i < 8; i++) y[i] = ((v[i] - mean) * inv * gv[i] + ev[i]) * zero;

    float4* xo = (float4*)(x + (size_t)row * C);
    xo[lane] = make_float4(y[0], y[1], y[2], y[3]);
    xo[lane + 32] = make_float4(y[4], y[5], y[6], y[7]);
    unsigned* pb16 = (unsigned*)(g_xb + (size_t)row * C);
    unsigned* ps16 = (unsigned*)(g_xs + (size_t)row * C);
#pragma unroll
    for (int i = 0; i < 4; i += 2) {
        unsigned ub, us;
        cvt2(y[i], y[i + 1], ub, us);
        pb16[lane * 2 + i / 2] = ub;
        ps16[lane * 2 + i / 2] = us;
    }
#pragma unroll
    for (int i = 4; i < 8; i += 2) {
        unsigned ub, us;
        cvt2(y[i], y[i + 1], ub, us);
        pb16[64 + lane * 2 + (i - 4) / 2] = ub;
        ps16[64 + lane * 2 + (i - 4) / 2] = us;
    }
}

// ---------------- x (B,T,C) -> out (B,C,T) ----------------
__global__ void transpose_kernel(const float* __restrict__ x, float* __restrict__ out) {
    __shared__ float tile[32][33];
    int b = blockIdx.z;
    int t0 = blockIdx.x * 32, c0 = blockIdx.y * 32;
    int tx = threadIdx.x, ty = threadIdx.y;
#pragma unroll
    for (int i = 0; i < 32; i += 8)
        tile[ty + i][tx] = x[(size_t)(b * T + t0 + ty + i) * C + c0 + tx];
    __syncthreads();
#pragma unroll
    for (int i = 0; i < 32; i += 8)
        out[(size_t)(b * C + c0 + ty + i) * T + t0 + tx] = tile[tx][ty + i];
}

__global__ void mask_out_kernel(const int* __restrict__ lens, float* __restrict__ out_mask) {
    int b = blockIdx.x;
    int len = lens[b];
    for (int t = threadIdx.x; t < T; t += blockDim.x)
        out_mask[(size_t)b * T + t] = (t < len) ? 1.0f : 0.0f;
}

}  // namespace

extern "C" void kernel_launch(void* const* d_in, const int* in_sizes, int n_in,
                              void* d_out, int out_size) {
    (void)in_sizes; (void)n_in; (void)out_size;
    const float* emb   = (const float*)d_in[0];
    const float* Wq    = (const float*)d_in[1];
    const float* Wk    = (const float*)d_in[2];
    const float* Wv    = (const float*)d_in[3];
    const float* Wo    = (const float*)d_in[4];
    const float* bq    = (const float*)d_in[5];
    const float* bk    = (const float*)d_in[6];
    const float* bv    = (const float*)d_in[7];
    const float* bo    = (const float*)d_in[8];
    const float* rel_k = (const float*)d_in[9];
    const float* rel_v = (const float*)d_in[10];
    const float* ln1_g = (const float*)d_in[11];
    const float* ln1_b = (const float*)d_in[12];
    const float* ln2_g = (const float*)d_in[13];
    const float* ln2_b = (const float*)d_in[14];
    const float* fw1   = (const float*)d_in[15];
    const float* fb1   = (const float*)d_in[16];
    const float* fw2   = (const float*)d_in[17];
    const float* fb2   = (const float*)d_in[18];
    const float* pw    = (const float*)d_in[19];
    const float* pb    = (const float*)d_in[20];
    const int*   toks  = (const int*)d_in[21];
    const int*   lens  = (const int*)d_in[22];

    cudaFuncSetAttribute(mma_gemm_p<0>, cudaFuncAttributeMaxDynamicSharedMemorySize, SMEM_BYTES);
    cudaFuncSetAttribute(mma_gemm_p<1>, cudaFuncAttributeMaxDynamicSharedMemorySize, SMEM_BYTES);
    cudaFuncSetAttribute(mma_gemm_p<3>, cudaFuncAttributeMaxDynamicSharedMemorySize, SMEM_BYTES);
    cudaFuncSetAttribute(flash_attn, cudaFuncAttributeMaxDynamicSharedMemorySize, FLASH_SMEM);

    float *px, *ptmp;
    bf16 *pwb, *pws, *pxb, *pxs, *pab, *pas, *pfb, *pfs;
    cudaGetSymbolAddress((void**)&px,   g_x);
    cudaGetSymbolAddress((void**)&ptmp, g_tmp);
    cudaGetSymbolAddress((void**)&pwb,  g_wb);
    cudaGetSymbolAddress((void**)&pws,  g_ws);
    cudaGetSymbolAddress((void**)&pxb,  g_xb);
    cudaGetSymbolAddress((void**)&pxs,  g_xs);
    cudaGetSymbolAddress((void**)&pab,  g_ab);
    cudaGetSymbolAddress((void**)&pas,  g_as);
    cudaGetSymbolAddress((void**)&pfb,  g_fb);
    cudaGetSymbolAddress((void**)&pfs,  g_fs);

    float* out      = (float*)d_out;
    float* out_x    = out;
    float* out_m    = out + (size_t)B * C * T;
    float* out_logs = out_m + (size_t)B * OUT * T;
    float* out_mask = out_logs + (size_t)B * OUT * T;

    // ---- single prep launch: all weight conversions + embedding ----
    prep_kernel<<<6016, 256>>>(Wq, Wk, Wv, Wo, fw1, fw2, pw, emb, toks);

    dim3 gQKV(3 * C / 128, BT / 128);
    dim3 gC(C / 128, BT / 128);
    dim3 gFC(FC / 128, BT / 128);

    for (int l = 0; l < L; l++) {
        size_t qkv = OFF_QKV + (size_t)l * 3 * C * C;
        size_t wo = OFF_WO + (size_t)l * C * C;
        size_t f1 = OFF_F1 + (size_t)l * C * FC;
        size_t f2 = OFF_F2 + (size_t)l * FC * C;

        mma_gemm_p<1><<<gQKV, 256, SMEM_BYTES>>>(
            pxb, pxs, pwb + qkv, pws + qkv, bq + (size_t)l * C, bk + (size_t)l * C,
            bv + (size_t)l * C, nullptr, nullptr, nullptr, nullptr, BT, 3 * C, C, 1.0f, 0,
            nullptr);

        flash_attn<<<dim3(T / 128, B * H), 256, FLASH_SMEM>>>(
            lens, rel_k + (size_t)l * NREL * HD, rel_v + (size_t)l * NREL * HD);

        mma_gemm_p<0><<<gC, 256, SMEM_BYTES>>>(pab, pas, pwb + wo, pws + wo,
                                               bo + (size_t)l * C, nullptr, nullptr, ptmp,
                                               nullptr, nullptr, nullptr, BT, C, C, 1.0f, 0,
                                               nullptr);
        ln_res_kernel<<<BT / 8, 256>>>(px, ptmp, ln1_g + (size_t)l * C, ln1_b + (size_t)l * C,
                                       lens, 0);

        mma_gemm_p<0><<<gFC, 256, SMEM_BYTES>>>(pxb, pxs, pwb + f1, pws + f1,
                                                fb1 + (size_t)l * FC, nullptr, nullptr, nullptr,
                                                pfb, pfs, nullptr, BT, FC, C, 1.0f, 1, nullptr);
        mma_gemm_p<0><<<gC, 256, SMEM_BYTES>>>(pfb, pfs, pwb + f2, pws + f2,
                                               fb2 + (size_t)l * C, nullptr, nullptr, ptmp,
                                               nullptr, nullptr, nullptr, BT, C, FC, 1.0f, 0,
                                               nullptr);
        ln_res_kernel<<<BT / 8, 256>>>(px, ptmp, ln2_g + (size_t)l * C, ln2_b + (size_t)l * C,
                                       lens, 1);
    }

    transpose_kernel<<<dim3(T / 32, C / 32, B), dim3(32, 8)>>>(px, out_x);
    mma_gemm_p<3><<<dim3(2 * OUT / 128, BT / 128), 256, SMEM_BYTES>>>(
        pxb, pxs, pwb + OFF_PJ, pws + OFF_PJ, pb, nullptr, nullptr, out_m, nullptr, nullptr,
        out_logs, BT, 2 * OUT, C, 1.0f, 0, lens);
    mask_out_kernel<<<B, 256>>>(lens, out_mask);
}